// round 2
// baseline (speedup 1.0000x reference)
#include <cuda_runtime.h>
#include <math.h>

#define B_  2
#define S_  2048
#define D_  2048
#define H_  16
#define HD_ 128
#define M_  (B_*S_)      // 4096
#define F_  (HD_/2)      // 64

// ---------------- scratch (alloc-free rule: __device__ globals) ----------------
__device__ float g_q [B_*H_*S_*HD_];   // [b,h,s,hd]
__device__ float g_k [B_*H_*S_*HD_];
__device__ float g_v [B_*H_*S_*HD_];
__device__ float g_ao[M_*D_];          // attention output, [b*s, d]
__device__ float g_cos[S_*F_];
__device__ float g_sin[S_*F_];

// ---------------- RoPE table ----------------
__global__ void rope_table_kernel() {
    int idx = blockIdx.x * blockDim.x + threadIdx.x;
    if (idx >= S_ * F_) return;
    int s = idx >> 6;
    int i = idx & 63;
    double invf = pow(10000.0, -(double)i / 64.0);
    double f = (double)s * invf;
    double sn, cs;
    sincos(f, &sn, &cs);
    g_cos[idx] = (float)cs;
    g_sin[idx] = (float)sn;
}

// ---------------- SGEMM: C[m,n] = sum_k A[m,k] * W[n,k] ----------------
// M=4096, N=2048, K=2048.  Tiles 128x128x16, 256 threads, 8x8 per thread.
// MODE 0: plain row-major out [M,N]
// MODE 1: RoPE epilogue, write [B,H,S,HD]
// MODE 2: no RoPE, write [B,H,S,HD]
template <int MODE>
__global__ __launch_bounds__(256, 2) void gemm_kernel(
    const float* __restrict__ A, const float* __restrict__ W, float* __restrict__ out)
{
    __shared__ float As[16][128];
    __shared__ float Ws[16][128];

    const int tid = threadIdx.x;
    const int tx = tid & 15;
    const int ty = tid >> 4;
    const int K = 2048;

    const float* Ablk = A + (size_t)(blockIdx.y * 128) * K;
    const float* Wblk = W + (size_t)(blockIdx.x * 128) * K;

    float acc[8][8];
    #pragma unroll
    for (int i = 0; i < 8; i++)
        #pragma unroll
        for (int j = 0; j < 8; j++) acc[i][j] = 0.f;

    for (int k0 = 0; k0 < K; k0 += 16) {
        #pragma unroll
        for (int t = 0; t < 2; t++) {
            int idx = tid + t * 256;          // 512 float4s cover a 128x16 tile
            int row = idx >> 2;
            int kc  = (idx & 3) << 2;
            float4 av = *(const float4*)(Ablk + (size_t)row * K + k0 + kc);
            float4 wv = *(const float4*)(Wblk + (size_t)row * K + k0 + kc);
            As[kc+0][row] = av.x; As[kc+1][row] = av.y; As[kc+2][row] = av.z; As[kc+3][row] = av.w;
            Ws[kc+0][row] = wv.x; Ws[kc+1][row] = wv.y; Ws[kc+2][row] = wv.z; Ws[kc+3][row] = wv.w;
        }
        __syncthreads();
        #pragma unroll
        for (int k = 0; k < 16; k++) {
            float a[8], b[8];
            *(float4*)(a)   = *(const float4*)&As[k][ty*8];
            *(float4*)(a+4) = *(const float4*)&As[k][ty*8+4];
            *(float4*)(b)   = *(const float4*)&Ws[k][tx*8];
            *(float4*)(b+4) = *(const float4*)&Ws[k][tx*8+4];
            #pragma unroll
            for (int i = 0; i < 8; i++)
                #pragma unroll
                for (int j = 0; j < 8; j++)
                    acc[i][j] += a[i] * b[j];
        }
        __syncthreads();
    }

    const int n0 = blockIdx.x * 128 + tx * 8;   // 8 cols, even-aligned, single head
    const int m0 = blockIdx.y * 128 + ty * 8;

    #pragma unroll
    for (int i = 0; i < 8; i++) {
        int m = m0 + i;
        int s = m & (S_ - 1);
        if (MODE == 1) {
            int fbase = s * F_ + ((n0 & (HD_ - 1)) >> 1);
            #pragma unroll
            for (int jp = 0; jp < 4; jp++) {
                float c  = g_cos[fbase + jp];
                float sn = g_sin[fbase + jp];
                float xe = acc[i][2*jp], xo = acc[i][2*jp+1];
                acc[i][2*jp]   = xe * c - xo * sn;
                acc[i][2*jp+1] = xo * c + xe * sn;
            }
        }
        if (MODE == 0) {
            float* p = out + (size_t)m * D_ + n0;
            *(float4*)(p)   = make_float4(acc[i][0], acc[i][1], acc[i][2], acc[i][3]);
            *(float4*)(p+4) = make_float4(acc[i][4], acc[i][5], acc[i][6], acc[i][7]);
        } else {
            int b  = m >> 11;            // m / S_
            int h  = n0 >> 7;            // head
            int hd = n0 & (HD_ - 1);
            float* p = out + (((size_t)(b * H_ + h)) * S_ + s) * HD_ + hd;
            *(float4*)(p)   = make_float4(acc[i][0], acc[i][1], acc[i][2], acc[i][3]);
            *(float4*)(p+4) = make_float4(acc[i][4], acc[i][5], acc[i][6], acc[i][7]);
        }
    }
}

// ---------------- flash attention (causal), fp32 ----------------
// grid: (S/64 q-tiles, B*H), block: 128 threads
// thread map: tx = tid&7 (cols k = tx+8j), ty = tid>>3 (q rows ty*4+i)
// O cols per thread: tx*4 + 32*g + c  (g=0..3, c=0..3)
__global__ __launch_bounds__(128, 1) void attn_kernel()
{
    extern __shared__ float sm[];
    float* Qs  = sm;                  // [64][132]
    float* KVs = sm + 64 * 132;       // [64][132]
    float* Ps  = sm + 2 * 64 * 132;   // [64][68]

    const int tid = threadIdx.x;
    const int tx = tid & 7;
    const int ty = tid >> 3;
    const int qt = blockIdx.x;
    const int bh = blockIdx.y;

    const float* Qg = g_q + (size_t)bh * S_ * HD_ + (size_t)qt * 64 * HD_;
    const float* Kg = g_k + (size_t)bh * S_ * HD_;
    const float* Vg = g_v + (size_t)bh * S_ * HD_;

    const float qscale = 0.08838834764831845f;  // 1/sqrt(128)

    #pragma unroll
    for (int it = 0; it < 16; it++) {
        int idx = it * 128 + tid;
        int r = idx >> 5;
        int c = (idx & 31) << 2;
        float4 v = *(const float4*)(Qg + (size_t)r * HD_ + c);
        Qs[r*132 + c + 0] = v.x * qscale;
        Qs[r*132 + c + 1] = v.y * qscale;
        Qs[r*132 + c + 2] = v.z * qscale;
        Qs[r*132 + c + 3] = v.w * qscale;
    }

    float acc_o[4][16];
    float m_run[4], l_run[4];
    #pragma unroll
    for (int i = 0; i < 4; i++) {
        m_run[i] = -INFINITY;
        l_run[i] = 0.f;
        #pragma unroll
        for (int c = 0; c < 16; c++) acc_o[i][c] = 0.f;
    }

    for (int kt = 0; kt <= qt; kt++) {
        #pragma unroll
        for (int it = 0; it < 16; it++) {
            int idx = it * 128 + tid;
            int r = idx >> 5;
            int c = (idx & 31) << 2;
            float4 v = *(const float4*)(Kg + (size_t)(kt*64 + r) * HD_ + c);
            KVs[r*132 + c + 0] = v.x;
            KVs[r*132 + c + 1] = v.y;
            KVs[r*132 + c + 2] = v.z;
            KVs[r*132 + c + 3] = v.w;
        }
        __syncthreads();

        float accs[4][8];
        #pragma unroll
        for (int i = 0; i < 4; i++)
            #pragma unroll
            for (int j = 0; j < 8; j++) accs[i][j] = 0.f;

        #pragma unroll 8
        for (int d4 = 0; d4 < 32; d4++) {
            float4 qf[4], kf[8];
            #pragma unroll
            for (int i = 0; i < 4; i++)
                qf[i] = *(const float4*)&Qs[(ty*4 + i) * 132 + d4*4];
            #pragma unroll
            for (int j = 0; j < 8; j++)
                kf[j] = *(const float4*)&KVs[(tx + 8*j) * 132 + d4*4];
            #pragma unroll
            for (int i = 0; i < 4; i++)
                #pragma unroll
                for (int j = 0; j < 8; j++)
                    accs[i][j] += qf[i].x*kf[j].x + qf[i].y*kf[j].y
                                + qf[i].z*kf[j].z + qf[i].w*kf[j].w;
        }

        if (kt == qt) {
            #pragma unroll
            for (int i = 0; i < 4; i++)
                #pragma unroll
                for (int j = 0; j < 8; j++)
                    if (tx + 8*j > ty*4 + i) accs[i][j] = -1e30f;
        }

        #pragma unroll
        for (int i = 0; i < 4; i++) {
            float mloc = accs[i][0];
            #pragma unroll
            for (int j = 1; j < 8; j++) mloc = fmaxf(mloc, accs[i][j]);
            mloc = fmaxf(mloc, __shfl_xor_sync(0xffffffffu, mloc, 1));
            mloc = fmaxf(mloc, __shfl_xor_sync(0xffffffffu, mloc, 2));
            mloc = fmaxf(mloc, __shfl_xor_sync(0xffffffffu, mloc, 4));
            float mnew = fmaxf(m_run[i], mloc);
            float corr = expf(m_run[i] - mnew);
            float rsum = 0.f;
            #pragma unroll
            for (int j = 0; j < 8; j++) {
                float p = expf(accs[i][j] - mnew);
                rsum += p;
                Ps[(ty*4 + i) * 68 + tx + 8*j] = p;
            }
            rsum += __shfl_xor_sync(0xffffffffu, rsum, 1);
            rsum += __shfl_xor_sync(0xffffffffu, rsum, 2);
            rsum += __shfl_xor_sync(0xffffffffu, rsum, 4);
            l_run[i] = l_run[i] * corr + rsum;
            m_run[i] = mnew;
            #pragma unroll
            for (int c = 0; c < 16; c++) acc_o[i][c] *= corr;
        }
        __syncthreads();   // K reads + P writes complete

        #pragma unroll
        for (int it = 0; it < 16; it++) {
            int idx = it * 128 + tid;
            int r = idx >> 5;
            int c = (idx & 31) << 2;
            float4 v = *(const float4*)(Vg + (size_t)(kt*64 + r) * HD_ + c);
            KVs[r*132 + c + 0] = v.x;
            KVs[r*132 + c + 1] = v.y;
            KVs[r*132 + c + 2] = v.z;
            KVs[r*132 + c + 3] = v.w;
        }
        __syncthreads();

        #pragma unroll 8
        for (int k = 0; k < 64; k++) {
            float pv[4];
            #pragma unroll
            for (int i = 0; i < 4; i++) pv[i] = Ps[(ty*4 + i) * 68 + k];
            float4 vv[4];
            #pragma unroll
            for (int g = 0; g < 4; g++)
                vv[g] = *(const float4*)&KVs[k*132 + tx*4 + 32*g];
            #pragma unroll
            for (int i = 0; i < 4; i++)
                #pragma unroll
                for (int g = 0; g < 4; g++) {
                    acc_o[i][g*4+0] += pv[i] * vv[g].x;
                    acc_o[i][g*4+1] += pv[i] * vv[g].y;
                    acc_o[i][g*4+2] += pv[i] * vv[g].z;
                    acc_o[i][g*4+3] += pv[i] * vv[g].w;
                }
        }
        __syncthreads();   // PV reads of KVs complete before next K load
    }

    const int b = bh >> 4;
    const int h = bh & 15;
    #pragma unroll
    for (int i = 0; i < 4; i++) {
        int sg = qt*64 + ty*4 + i;
        float inv = 1.0f / l_run[i];
        float* p = g_ao + ((size_t)(b * S_ + sg)) * D_ + h * HD_;
        #pragma unroll
        for (int g = 0; g < 4; g++) {
            float4 v = make_float4(acc_o[i][g*4+0]*inv, acc_o[i][g*4+1]*inv,
                                   acc_o[i][g*4+2]*inv, acc_o[i][g*4+3]*inv);
            *(float4*)(p + tx*4 + 32*g) = v;
        }
    }
}

extern "C" void kernel_launch(void* const* d_in, const int* in_sizes, int n_in,
                              void* d_out, int out_size) {
    (void)in_sizes; (void)n_in; (void)out_size;
    const float* x  = (const float*)d_in[0];
    const float* Wq = (const float*)d_in[1];
    const float* Wk = (const float*)d_in[2];
    const float* Wv = (const float*)d_in[3];
    const float* Wo = (const float*)d_in[4];
    float* out = (float*)d_out;

    float *q, *k, *v, *ao;
    cudaGetSymbolAddress((void**)&q,  g_q);
    cudaGetSymbolAddress((void**)&k,  g_k);
    cudaGetSymbolAddress((void**)&v,  g_v);
    cudaGetSymbolAddress((void**)&ao, g_ao);

    rope_table_kernel<<<(S_*F_ + 255)/256, 256>>>();

    dim3 ggrid(16, 32);
    gemm_kernel<1><<<ggrid, 256>>>(x, Wq, q);
    gemm_kernel<1><<<ggrid, 256>>>(x, Wk, k);
    gemm_kernel<2><<<ggrid, 256>>>(x, Wv, v);

    int attn_smem = (2*64*132 + 64*68) * 4;   // 84992 bytes
    cudaFuncSetAttribute(attn_kernel, cudaFuncAttributeMaxDynamicSharedMemorySize, attn_smem);
    attn_kernel<<<dim3(32, 32), 128, attn_smem>>>();

    gemm_kernel<0><<<ggrid, 256>>>(ao, Wo, out);
}

// round 5
// speedup vs baseline: 1.6545x; 1.6545x over previous
#include <cuda_runtime.h>
#include <cuda_bf16.h>
#include <math.h>
#include <stdint.h>

#define B_  2
#define S_  2048
#define D_  2048
#define H_  16
#define HD_ 128
#define M_  (B_*S_)      // 4096
#define F_  (HD_/2)      // 64

// ---------------- scratch (alloc-free rule: __device__ globals) ----------------
__device__ float g_q [B_*H_*S_*HD_];   // [b,h,s,hd]
__device__ float g_k [B_*H_*S_*HD_];
__device__ float g_v [B_*H_*S_*HD_];
__device__ float g_ao[M_*D_];          // attention output, [b*s, d]
__device__ float g_cos[S_*F_];
__device__ float g_sin[S_*F_];

__device__ __nv_bfloat16 g_xhi[M_*D_];
__device__ __nv_bfloat16 g_xlo[M_*D_];
__device__ __nv_bfloat16 g_whi[4*D_*D_];
__device__ __nv_bfloat16 g_wlo[4*D_*D_];

// ---------------- PTX helpers (plain sm_100 target: no tcgen05) ----------------
__device__ __forceinline__ uint32_t smem_u32(const void* p) {
    uint32_t a;
    asm("{ .reg .u64 t; cvta.to.shared.u64 t, %1; cvt.u32.u64 %0, t; }" : "=r"(a) : "l"(p));
    return a;
}
__device__ __forceinline__ void cp16(uint32_t s, const void* g) {
    asm volatile("cp.async.cg.shared.global [%0], [%1], 16;" :: "r"(s), "l"(g));
}
#define CP_COMMIT() asm volatile("cp.async.commit_group;")

__device__ __forceinline__ void ldsm4(uint32_t* r, uint32_t addr) {
    asm volatile("ldmatrix.sync.aligned.m8n8.x4.shared.b16 {%0,%1,%2,%3}, [%4];"
        : "=r"(r[0]), "=r"(r[1]), "=r"(r[2]), "=r"(r[3]) : "r"(addr));
}
__device__ __forceinline__ void mma16816(float* d, const uint32_t* a, uint32_t b0, uint32_t b1) {
    asm volatile(
        "mma.sync.aligned.m16n8k16.row.col.f32.bf16.bf16.f32 "
        "{%0,%1,%2,%3}, {%4,%5,%6,%7}, {%8,%9}, {%0,%1,%2,%3};"
        : "+f"(d[0]), "+f"(d[1]), "+f"(d[2]), "+f"(d[3])
        : "r"(a[0]), "r"(a[1]), "r"(a[2]), "r"(a[3]), "r"(b0), "r"(b1));
}

// ---------------- RoPE table ----------------
__global__ void rope_table_kernel() {
    int idx = blockIdx.x * blockDim.x + threadIdx.x;
    if (idx >= S_ * F_) return;
    int s = idx >> 6;
    int i = idx & 63;
    double invf = pow(10000.0, -(double)i / 64.0);
    double f = (double)s * invf;
    double sn, cs;
    sincos(f, &sn, &cs);
    g_cos[idx] = (float)cs;
    g_sin[idx] = (float)sn;
}

// ---------------- fp32 -> bf16 hi/lo split ----------------
__global__ void conv_kernel(const float* __restrict__ in,
                            __nv_bfloat16* __restrict__ hi,
                            __nv_bfloat16* __restrict__ lo, int n4) {
    int i = blockIdx.x * blockDim.x + threadIdx.x;
    if (i >= n4) return;
    float4 v = ((const float4*)in)[i];
    float xs[4] = {v.x, v.y, v.z, v.w};
    __nv_bfloat16 h[4], l[4];
    #pragma unroll
    for (int j = 0; j < 4; j++) {
        h[j] = __float2bfloat16(xs[j]);
        l[j] = __float2bfloat16(xs[j] - __bfloat162float(h[j]));
    }
    __nv_bfloat162* hp = (__nv_bfloat162*)hi;
    __nv_bfloat162* lp = (__nv_bfloat162*)lo;
    hp[2*i]   = __halves2bfloat162(h[0], h[1]);
    hp[2*i+1] = __halves2bfloat162(h[2], h[3]);
    lp[2*i]   = __halves2bfloat162(l[0], l[1]);
    lp[2*i+1] = __halves2bfloat162(l[2], l[3]);
}

// ---------------- mma.sync bf16 GEMM: C[m,n] = sum_k A[m,k]*B[n,k] ----------------
// 3-term hi/lo split. CTA 128x128, 8 warps (2m x 4n), warp tile 64x32.
// K-chunk 32, 3-stage cp.async pipeline. Smem rows padded to 80B (bank-clean ldmatrix).
// MODE 0: out row-major [M,2048]; MODE 1: RoPE + [B,H,S,HD]; MODE 2: [B,H,S,HD]
#define KC 32
#define STAGES 3
#define ROWB 80                      // bytes per 32-bf16 row (padded)
#define TILE_B (128*ROWB)            // 10240 bytes per (hi|lo) x (A|B) tile
#define STAGE_B (4*TILE_B)           // 40960
#define GT_SMEM (STAGES*STAGE_B)     // 122880

template <int MODE>
__global__ __launch_bounds__(256, 1) void gemm_tc(
    const __nv_bfloat16* __restrict__ Ahi, const __nv_bfloat16* __restrict__ Alo,
    const __nv_bfloat16* __restrict__ Bhi, const __nv_bfloat16* __restrict__ Blo,
    float* __restrict__ outp)
{
    extern __shared__ char smc[];
    const uint32_t sb = smem_u32(smc);
    const int tid = threadIdx.x;
    const int lane = tid & 31;
    const int wid = tid >> 5;
    const int wm = (wid >> 2) * 64;     // warp m offset in CTA tile
    const int wn = (wid & 3) * 32;      // warp n offset
    const int m0 = blockIdx.y * 128;
    const int n0 = blockIdx.x * 128;

    // per-thread load coords: 2 iterations x 4 tensors, 16B each
    // idx = t*256+tid ; row = idx>>2 (0..127) ; seg = idx&3 (16B segment)
    auto load_stage = [&](int stg, int k0) {
        uint32_t base = sb + stg * STAGE_B;
        #pragma unroll
        for (int t = 0; t < 2; t++) {
            int idx = t * 256 + tid;
            int row = idx >> 2, seg = idx & 3;
            uint32_t so = row * ROWB + seg * 16;
            size_t goA = (size_t)(m0 + row) * D_ + k0 + seg * 8;
            size_t goB = (size_t)(n0 + row) * D_ + k0 + seg * 8;
            cp16(base + 0*TILE_B + so, Ahi + goA);
            cp16(base + 1*TILE_B + so, Alo + goA);
            cp16(base + 2*TILE_B + so, Bhi + goB);
            cp16(base + 3*TILE_B + so, Blo + goB);
        }
        CP_COMMIT();
    };

    float acc[4][4][4];
    #pragma unroll
    for (int mi = 0; mi < 4; mi++)
        #pragma unroll
        for (int ni = 0; ni < 4; ni++)
            #pragma unroll
            for (int e = 0; e < 4; e++) acc[mi][ni][e] = 0.f;

    #pragma unroll
    for (int c = 0; c < STAGES - 1; c++) load_stage(c, c * KC);

    const int NCH = 2048 / KC;   // 64
    // ldmatrix address components (same formula for A x4 and B x4 pair-loads)
    const int lrow = lane & 15;            // row within 16
    const int lk   = (lane >> 4) * 8;      // 0 or 8 (k halves)

    for (int c = 0; c < NCH; c++) {
        asm volatile("cp.async.wait_group %0;" :: "n"(STAGES - 2) : "memory");
        __syncthreads();
        const uint32_t st = sb + (c % STAGES) * STAGE_B;
        const uint32_t aAh = st, aAl = st + TILE_B, aBh = st + 2*TILE_B, aBl = st + 3*TILE_B;

        #pragma unroll
        for (int kk = 0; kk < 2; kk++) {
            const int kb = (kk * 16 + lk) * 2;   // byte offset along k
            uint32_t ah[4][4], al[4][4];
            #pragma unroll
            for (int mi = 0; mi < 4; mi++) {
                uint32_t off = (wm + mi*16 + lrow) * ROWB + kb;
                ldsm4(ah[mi], aAh + off);
                ldsm4(al[mi], aAl + off);
            }
            uint32_t bh[2][4], bl[2][4];       // each x4 covers two n8 tiles
            #pragma unroll
            for (int nj = 0; nj < 2; nj++) {
                uint32_t off = (wn + nj*16 + lrow) * ROWB + kb;
                ldsm4(bh[nj], aBh + off);
                ldsm4(bl[nj], aBl + off);
            }
            #pragma unroll
            for (int mi = 0; mi < 4; mi++)
                #pragma unroll
                for (int ni = 0; ni < 4; ni++) {
                    const int nj = ni >> 1, ns = ni & 1;
                    // B n8k16 fragment = regs {ns, ns+2} of the x4 load
                    mma16816(acc[mi][ni], ah[mi], bh[nj][ns], bh[nj][ns+2]);
                    mma16816(acc[mi][ni], ah[mi], bl[nj][ns], bl[nj][ns+2]);
                    mma16816(acc[mi][ni], al[mi], bh[nj][ns], bh[nj][ns+2]);
                }
        }

        int nc = c + STAGES - 1;
        if (nc < NCH) load_stage(nc % STAGES, nc * KC);
    }

    // ---- epilogue: registers -> global; RoPE in registers (n-pair is even/odd) ----
    const int rr = lane >> 2;              // row within 8
    const int cp = (lane & 3) * 2;         // even col within 8
    #pragma unroll
    for (int mi = 0; mi < 4; mi++) {
        #pragma unroll
        for (int half = 0; half < 2; half++) {
            int m = m0 + wm + mi*16 + rr + half*8;
            int s = m & (S_ - 1);
            #pragma unroll
            for (int ni = 0; ni < 4; ni++) {
                float e = acc[mi][ni][half*2 + 0];
                float o = acc[mi][ni][half*2 + 1];
                int n = n0 + wn + ni*8 + cp;
                if (MODE == 1) {
                    int pair = (n & (HD_ - 1)) >> 1;
                    float cc = g_cos[s * F_ + pair], ss = g_sin[s * F_ + pair];
                    float xe = e, xo = o;
                    e = xe * cc - xo * ss;
                    o = xo * cc + xe * ss;
                }
                if (MODE == 0) {
                    *(float2*)(outp + (size_t)m * D_ + n) = make_float2(e, o);
                } else {
                    int br = m >> 11, h = n >> 7, hd = n & (HD_ - 1);
                    *(float2*)(outp + (((size_t)(br * H_ + h)) * S_ + s) * HD_ + hd) =
                        make_float2(e, o);
                }
            }
        }
    }
}

// ---------------- flash attention (causal), fp32 (unchanged, verified) ----------------
__global__ __launch_bounds__(128, 1) void attn_kernel()
{
    extern __shared__ float sm[];
    float* Qs  = sm;                  // [64][132]
    float* KVs = sm + 64 * 132;       // [64][132]
    float* Ps  = sm + 2 * 64 * 132;   // [64][68]

    const int tid = threadIdx.x;
    const int tx = tid & 7;
    const int ty = tid >> 3;
    const int qt = blockIdx.x;
    const int bh = blockIdx.y;

    const float* Qg = g_q + (size_t)bh * S_ * HD_ + (size_t)qt * 64 * HD_;
    const float* Kg = g_k + (size_t)bh * S_ * HD_;
    const float* Vg = g_v + (size_t)bh * S_ * HD_;

    const float qscale = 0.08838834764831845f;  // 1/sqrt(128)

    #pragma unroll
    for (int it = 0; it < 16; it++) {
        int idx = it * 128 + tid;
        int r = idx >> 5;
        int c = (idx & 31) << 2;
        float4 v = *(const float4*)(Qg + (size_t)r * HD_ + c);
        Qs[r*132 + c + 0] = v.x * qscale;
        Qs[r*132 + c + 1] = v.y * qscale;
        Qs[r*132 + c + 2] = v.z * qscale;
        Qs[r*132 + c + 3] = v.w * qscale;
    }

    float acc_o[4][16];
    float m_run[4], l_run[4];
    #pragma unroll
    for (int i = 0; i < 4; i++) {
        m_run[i] = -INFINITY;
        l_run[i] = 0.f;
        #pragma unroll
        for (int c = 0; c < 16; c++) acc_o[i][c] = 0.f;
    }

    for (int kt = 0; kt <= qt; kt++) {
        #pragma unroll
        for (int it = 0; it < 16; it++) {
            int idx = it * 128 + tid;
            int r = idx >> 5;
            int c = (idx & 31) << 2;
            float4 v = *(const float4*)(Kg + (size_t)(kt*64 + r) * HD_ + c);
            KVs[r*132 + c + 0] = v.x;
            KVs[r*132 + c + 1] = v.y;
            KVs[r*132 + c + 2] = v.z;
            KVs[r*132 + c + 3] = v.w;
        }
        __syncthreads();

        float accs[4][8];
        #pragma unroll
        for (int i = 0; i < 4; i++)
            #pragma unroll
            for (int j = 0; j < 8; j++) accs[i][j] = 0.f;

        #pragma unroll 8
        for (int d4 = 0; d4 < 32; d4++) {
            float4 qf[4], kf[8];
            #pragma unroll
            for (int i = 0; i < 4; i++)
                qf[i] = *(const float4*)&Qs[(ty*4 + i) * 132 + d4*4];
            #pragma unroll
            for (int j = 0; j < 8; j++)
                kf[j] = *(const float4*)&KVs[(tx + 8*j) * 132 + d4*4];
            #pragma unroll
            for (int i = 0; i < 4; i++)
                #pragma unroll
                for (int j = 0; j < 8; j++)
                    accs[i][j] += qf[i].x*kf[j].x + qf[i].y*kf[j].y
                                + qf[i].z*kf[j].z + qf[i].w*kf[j].w;
        }

        if (kt == qt) {
            #pragma unroll
            for (int i = 0; i < 4; i++)
                #pragma unroll
                for (int j = 0; j < 8; j++)
                    if (tx + 8*j > ty*4 + i) accs[i][j] = -1e30f;
        }

        #pragma unroll
        for (int i = 0; i < 4; i++) {
            float mloc = accs[i][0];
            #pragma unroll
            for (int j = 1; j < 8; j++) mloc = fmaxf(mloc, accs[i][j]);
            mloc = fmaxf(mloc, __shfl_xor_sync(0xffffffffu, mloc, 1));
            mloc = fmaxf(mloc, __shfl_xor_sync(0xffffffffu, mloc, 2));
            mloc = fmaxf(mloc, __shfl_xor_sync(0xffffffffu, mloc, 4));
            float mnew = fmaxf(m_run[i], mloc);
            float corr = expf(m_run[i] - mnew);
            float rsum = 0.f;
            #pragma unroll
            for (int j = 0; j < 8; j++) {
                float p = expf(accs[i][j] - mnew);
                rsum += p;
                Ps[(ty*4 + i) * 68 + tx + 8*j] = p;
            }
            rsum += __shfl_xor_sync(0xffffffffu, rsum, 1);
            rsum += __shfl_xor_sync(0xffffffffu, rsum, 2);
            rsum += __shfl_xor_sync(0xffffffffu, rsum, 4);
            l_run[i] = l_run[i] * corr + rsum;
            m_run[i] = mnew;
            #pragma unroll
            for (int c = 0; c < 16; c++) acc_o[i][c] *= corr;
        }
        __syncthreads();

        #pragma unroll
        for (int it = 0; it < 16; it++) {
            int idx = it * 128 + tid;
            int r = idx >> 5;
            int c = (idx & 31) << 2;
            float4 v = *(const float4*)(Vg + (size_t)(kt*64 + r) * HD_ + c);
            KVs[r*132 + c + 0] = v.x;
            KVs[r*132 + c + 1] = v.y;
            KVs[r*132 + c + 2] = v.z;
            KVs[r*132 + c + 3] = v.w;
        }
        __syncthreads();

        #pragma unroll 8
        for (int k = 0; k < 64; k++) {
            float pv[4];
            #pragma unroll
            for (int i = 0; i < 4; i++) pv[i] = Ps[(ty*4 + i) * 68 + k];
            float4 vv[4];
            #pragma unroll
            for (int g = 0; g < 4; g++)
                vv[g] = *(const float4*)&KVs[k*132 + tx*4 + 32*g];
            #pragma unroll
            for (int i = 0; i < 4; i++)
                #pragma unroll
                for (int g = 0; g < 4; g++) {
                    acc_o[i][g*4+0] += pv[i] * vv[g].x;
                    acc_o[i][g*4+1] += pv[i] * vv[g].y;
                    acc_o[i][g*4+2] += pv[i] * vv[g].z;
                    acc_o[i][g*4+3] += pv[i] * vv[g].w;
                }
        }
        __syncthreads();
    }

    const int b = bh >> 4;
    const int h = bh & 15;
    #pragma unroll
    for (int i = 0; i < 4; i++) {
        int sg = qt*64 + ty*4 + i;
        float inv = 1.0f / l_run[i];
        float* p = g_ao + ((size_t)(b * S_ + sg)) * D_ + h * HD_;
        #pragma unroll
        for (int g = 0; g < 4; g++) {
            float4 v = make_float4(acc_o[i][g*4+0]*inv, acc_o[i][g*4+1]*inv,
                                   acc_o[i][g*4+2]*inv, acc_o[i][g*4+3]*inv);
            *(float4*)(p + tx*4 + 32*g) = v;
        }
    }
}

extern "C" void kernel_launch(void* const* d_in, const int* in_sizes, int n_in,
                              void* d_out, int out_size) {
    (void)in_sizes; (void)n_in; (void)out_size;
    const float* x  = (const float*)d_in[0];
    const float* Wq = (const float*)d_in[1];
    const float* Wk = (const float*)d_in[2];
    const float* Wv = (const float*)d_in[3];
    const float* Wo = (const float*)d_in[4];
    float* out = (float*)d_out;

    float *q, *k, *v, *ao;
    __nv_bfloat16 *xhi, *xlo, *whi, *wlo;
    cudaGetSymbolAddress((void**)&q,   g_q);
    cudaGetSymbolAddress((void**)&k,   g_k);
    cudaGetSymbolAddress((void**)&v,   g_v);
    cudaGetSymbolAddress((void**)&ao,  g_ao);
    cudaGetSymbolAddress((void**)&xhi, g_xhi);
    cudaGetSymbolAddress((void**)&xlo, g_xlo);
    cudaGetSymbolAddress((void**)&whi, g_whi);
    cudaGetSymbolAddress((void**)&wlo, g_wlo);

    rope_table_kernel<<<(S_*F_ + 255)/256, 256>>>();

    const size_t DD = (size_t)D_ * D_;
    conv_kernel<<<(M_*D_/4 + 255)/256, 256>>>(x,  xhi, xlo, M_*D_/4);
    conv_kernel<<<(D_*D_/4 + 255)/256, 256>>>(Wq, whi + 0*DD, wlo + 0*DD, D_*D_/4);
    conv_kernel<<<(D_*D_/4 + 255)/256, 256>>>(Wk, whi + 1*DD, wlo + 1*DD, D_*D_/4);
    conv_kernel<<<(D_*D_/4 + 255)/256, 256>>>(Wv, whi + 2*DD, wlo + 2*DD, D_*D_/4);
    conv_kernel<<<(D_*D_/4 + 255)/256, 256>>>(Wo, whi + 3*DD, wlo + 3*DD, D_*D_/4);

    cudaFuncSetAttribute(gemm_tc<0>, cudaFuncAttributeMaxDynamicSharedMemorySize, GT_SMEM);
    cudaFuncSetAttribute(gemm_tc<1>, cudaFuncAttributeMaxDynamicSharedMemorySize, GT_SMEM);
    cudaFuncSetAttribute(gemm_tc<2>, cudaFuncAttributeMaxDynamicSharedMemorySize, GT_SMEM);

    dim3 tgrid(D_/128, M_/128);   // (16, 32)
    gemm_tc<1><<<tgrid, 256, GT_SMEM>>>(xhi, xlo, whi + 0*DD, wlo + 0*DD, q);
    gemm_tc<1><<<tgrid, 256, GT_SMEM>>>(xhi, xlo, whi + 1*DD, wlo + 1*DD, k);
    gemm_tc<2><<<tgrid, 256, GT_SMEM>>>(xhi, xlo, whi + 2*DD, wlo + 2*DD, v);

    int attn_smem = (2*64*132 + 64*68) * 4;   // 84992 bytes
    cudaFuncSetAttribute(attn_kernel, cudaFuncAttributeMaxDynamicSharedMemorySize, attn_smem);
    attn_kernel<<<dim3(32, 32), 128, attn_smem>>>();

    conv_kernel<<<(M_*D_/4 + 255)/256, 256>>>(ao, xhi, xlo, M_*D_/4);
    gemm_tc<0><<<tgrid, 256, GT_SMEM>>>(xhi, xlo, whi + 3*DD, wlo + 3*DD, out);
}

// round 6
// speedup vs baseline: 1.8755x; 1.1336x over previous
#include <cuda_runtime.h>
#include <cuda_bf16.h>
#include <math.h>
#include <stdint.h>

#define B_  2
#define S_  2048
#define D_  2048
#define H_  16
#define HD_ 128
#define M_  (B_*S_)      // 4096
#define F_  (HD_/2)      // 64

// ---------------- scratch (alloc-free rule: __device__ globals) ----------------
__device__ float g_v [B_*H_*S_*HD_];   // [b,h,s,hd] fp32
__device__ float g_ao[M_*D_];          // attention output, [b*s, d]
__device__ float g_cos[S_*F_];
__device__ float g_sin[S_*F_];

__device__ __nv_bfloat16 g_qhi[B_*H_*S_*HD_];
__device__ __nv_bfloat16 g_qlo[B_*H_*S_*HD_];
__device__ __nv_bfloat16 g_khi[B_*H_*S_*HD_];
__device__ __nv_bfloat16 g_klo[B_*H_*S_*HD_];

__device__ __nv_bfloat16 g_xhi[M_*D_];
__device__ __nv_bfloat16 g_xlo[M_*D_];
__device__ __nv_bfloat16 g_whi[4*D_*D_];
__device__ __nv_bfloat16 g_wlo[4*D_*D_];

// ---------------- PTX helpers (plain sm_100 target: no tcgen05) ----------------
__device__ __forceinline__ uint32_t smem_u32(const void* p) {
    uint32_t a;
    asm("{ .reg .u64 t; cvta.to.shared.u64 t, %1; cvt.u32.u64 %0, t; }" : "=r"(a) : "l"(p));
    return a;
}
__device__ __forceinline__ void cp16(uint32_t s, const void* g) {
    asm volatile("cp.async.cg.shared.global [%0], [%1], 16;" :: "r"(s), "l"(g));
}
#define CP_COMMIT() asm volatile("cp.async.commit_group;")

__device__ __forceinline__ void ldsm4(uint32_t* r, uint32_t addr) {
    asm volatile("ldmatrix.sync.aligned.m8n8.x4.shared.b16 {%0,%1,%2,%3}, [%4];"
        : "=r"(r[0]), "=r"(r[1]), "=r"(r[2]), "=r"(r[3]) : "r"(addr));
}
__device__ __forceinline__ void mma16816(float* d, const uint32_t* a, uint32_t b0, uint32_t b1) {
    asm volatile(
        "mma.sync.aligned.m16n8k16.row.col.f32.bf16.bf16.f32 "
        "{%0,%1,%2,%3}, {%4,%5,%6,%7}, {%8,%9}, {%0,%1,%2,%3};"
        : "+f"(d[0]), "+f"(d[1]), "+f"(d[2]), "+f"(d[3])
        : "r"(a[0]), "r"(a[1]), "r"(a[2]), "r"(a[3]), "r"(b0), "r"(b1));
}

// ---------------- RoPE table ----------------
__global__ void rope_table_kernel() {
    int idx = blockIdx.x * blockDim.x + threadIdx.x;
    if (idx >= S_ * F_) return;
    int s = idx >> 6;
    int i = idx & 63;
    double invf = pow(10000.0, -(double)i / 64.0);
    double f = (double)s * invf;
    double sn, cs;
    sincos(f, &sn, &cs);
    g_cos[idx] = (float)cs;
    g_sin[idx] = (float)sn;
}

// ---------------- fp32 -> bf16 hi/lo split ----------------
__global__ void conv_kernel(const float* __restrict__ in,
                            __nv_bfloat16* __restrict__ hi,
                            __nv_bfloat16* __restrict__ lo, int n4) {
    int i = blockIdx.x * blockDim.x + threadIdx.x;
    if (i >= n4) return;
    float4 v = ((const float4*)in)[i];
    float xs[4] = {v.x, v.y, v.z, v.w};
    __nv_bfloat16 h[4], l[4];
    #pragma unroll
    for (int j = 0; j < 4; j++) {
        h[j] = __float2bfloat16(xs[j]);
        l[j] = __float2bfloat16(xs[j] - __bfloat162float(h[j]));
    }
    __nv_bfloat162* hp = (__nv_bfloat162*)hi;
    __nv_bfloat162* lp = (__nv_bfloat162*)lo;
    hp[2*i]   = __halves2bfloat162(h[0], h[1]);
    hp[2*i+1] = __halves2bfloat162(h[2], h[3]);
    lp[2*i]   = __halves2bfloat162(l[0], l[1]);
    lp[2*i+1] = __halves2bfloat162(l[2], l[3]);
}

// ---------------- mma.sync bf16 GEMM: C[m,n] = sum_k A[m,k]*B[n,k] ----------------
// MODE 0: out fp32 row-major [M,2048]
// MODE 1: RoPE, out bf16 hi/lo [B,H,S,HD]  (outhi/outlo)
// MODE 2: out fp32 [B,H,S,HD]
#define KC 32
#define STAGES 3
#define ROWB 80
#define TILE_B (128*ROWB)
#define STAGE_B (4*TILE_B)
#define GT_SMEM (STAGES*STAGE_B)     // 122880

template <int MODE>
__global__ __launch_bounds__(256, 1) void gemm_tc(
    const __nv_bfloat16* __restrict__ Ahi, const __nv_bfloat16* __restrict__ Alo,
    const __nv_bfloat16* __restrict__ Bhi, const __nv_bfloat16* __restrict__ Blo,
    float* __restrict__ outp,
    __nv_bfloat16* __restrict__ outhi, __nv_bfloat16* __restrict__ outlo)
{
    extern __shared__ char smc[];
    const uint32_t sb = smem_u32(smc);
    const int tid = threadIdx.x;
    const int lane = tid & 31;
    const int wid = tid >> 5;
    const int wm = (wid >> 2) * 64;
    const int wn = (wid & 3) * 32;
    const int m0 = blockIdx.y * 128;
    const int n0 = blockIdx.x * 128;

    auto load_stage = [&](int stg, int k0) {
        uint32_t base = sb + stg * STAGE_B;
        #pragma unroll
        for (int t = 0; t < 2; t++) {
            int idx = t * 256 + tid;
            int row = idx >> 2, seg = idx & 3;
            uint32_t so = row * ROWB + seg * 16;
            size_t goA = (size_t)(m0 + row) * D_ + k0 + seg * 8;
            size_t goB = (size_t)(n0 + row) * D_ + k0 + seg * 8;
            cp16(base + 0*TILE_B + so, Ahi + goA);
            cp16(base + 1*TILE_B + so, Alo + goA);
            cp16(base + 2*TILE_B + so, Bhi + goB);
            cp16(base + 3*TILE_B + so, Blo + goB);
        }
        CP_COMMIT();
    };

    float acc[4][4][4];
    #pragma unroll
    for (int mi = 0; mi < 4; mi++)
        #pragma unroll
        for (int ni = 0; ni < 4; ni++)
            #pragma unroll
            for (int e = 0; e < 4; e++) acc[mi][ni][e] = 0.f;

    #pragma unroll
    for (int c = 0; c < STAGES - 1; c++) load_stage(c, c * KC);

    const int NCH = 2048 / KC;
    const int lrow = lane & 15;
    const int lk   = (lane >> 4) * 8;

    for (int c = 0; c < NCH; c++) {
        asm volatile("cp.async.wait_group %0;" :: "n"(STAGES - 2) : "memory");
        __syncthreads();
        const uint32_t st = sb + (c % STAGES) * STAGE_B;
        const uint32_t aAh = st, aAl = st + TILE_B, aBh = st + 2*TILE_B, aBl = st + 3*TILE_B;

        #pragma unroll
        for (int kk = 0; kk < 2; kk++) {
            const int kb = (kk * 16 + lk) * 2;
            uint32_t ah[4][4], al[4][4];
            #pragma unroll
            for (int mi = 0; mi < 4; mi++) {
                uint32_t off = (wm + mi*16 + lrow) * ROWB + kb;
                ldsm4(ah[mi], aAh + off);
                ldsm4(al[mi], aAl + off);
            }
            uint32_t bh[2][4], bl[2][4];
            #pragma unroll
            for (int nj = 0; nj < 2; nj++) {
                uint32_t off = (wn + nj*16 + lrow) * ROWB + kb;
                ldsm4(bh[nj], aBh + off);
                ldsm4(bl[nj], aBl + off);
            }
            #pragma unroll
            for (int mi = 0; mi < 4; mi++)
                #pragma unroll
                for (int ni = 0; ni < 4; ni++) {
                    const int nj = ni >> 1, ns = ni & 1;
                    mma16816(acc[mi][ni], ah[mi], bh[nj][ns], bh[nj][ns+2]);
                    mma16816(acc[mi][ni], ah[mi], bl[nj][ns], bl[nj][ns+2]);
                    mma16816(acc[mi][ni], al[mi], bh[nj][ns], bh[nj][ns+2]);
                }
        }

        int nc = c + STAGES - 1;
        if (nc < NCH) load_stage(nc % STAGES, nc * KC);
    }

    const int rr = lane >> 2;
    const int cp = (lane & 3) * 2;
    #pragma unroll
    for (int mi = 0; mi < 4; mi++) {
        #pragma unroll
        for (int half = 0; half < 2; half++) {
            int m = m0 + wm + mi*16 + rr + half*8;
            int s = m & (S_ - 1);
            #pragma unroll
            for (int ni = 0; ni < 4; ni++) {
                float e = acc[mi][ni][half*2 + 0];
                float o = acc[mi][ni][half*2 + 1];
                int n = n0 + wn + ni*8 + cp;
                if (MODE == 1) {
                    int pair = (n & (HD_ - 1)) >> 1;
                    float cc = g_cos[s * F_ + pair], ss = g_sin[s * F_ + pair];
                    float xe = e, xo = o;
                    e = xe * cc - xo * ss;
                    o = xo * cc + xe * ss;
                    int br = m >> 11, h = n >> 7, hd = n & (HD_ - 1);
                    size_t ei = (((size_t)(br * H_ + h)) * S_ + s) * HD_ + hd;
                    __nv_bfloat16 eh = __float2bfloat16(e);
                    __nv_bfloat16 oh = __float2bfloat16(o);
                    __nv_bfloat16 el = __float2bfloat16(e - __bfloat162float(eh));
                    __nv_bfloat16 ol = __float2bfloat16(o - __bfloat162float(oh));
                    ((__nv_bfloat162*)outhi)[ei >> 1] = __halves2bfloat162(eh, oh);
                    ((__nv_bfloat162*)outlo)[ei >> 1] = __halves2bfloat162(el, ol);
                } else if (MODE == 0) {
                    *(float2*)(outp + (size_t)m * D_ + n) = make_float2(e, o);
                } else {
                    int br = m >> 11, h = n >> 7, hd = n & (HD_ - 1);
                    *(float2*)(outp + (((size_t)(br * H_ + h)) * S_ + s) * HD_ + hd) =
                        make_float2(e, o);
                }
            }
        }
    }
}

// ---------------- flash attention: HMMA QK^T (3-term) + fp32 PV ----------------
// CTA: 128 q-rows (8 warps x m16), K-tile 64, 256 threads.
#define A_SQH 0          // Q hi: 128 x 272B
#define A_SQL 34816
#define A_SKH 69632      // K hi: 64 x 272B
#define A_SKL 87040
#define A_SV  104448     // V fp32: 64 x 528B
#define A_SP  138240     // P fp32: 128 x 69 floats
#define A_SC  173568     // corr: 128 floats
#define A_SL  174080     // l:    128 floats
#define A_SMEM 174592

__global__ __launch_bounds__(256, 1) void attn_mma()
{
    extern __shared__ char smc[];
    const uint32_t sb = smem_u32(smc);
    float* Ps   = (float*)(smc + A_SP);
    float* CorS = (float*)(smc + A_SC);
    float* LSm  = (float*)(smc + A_SL);

    const int tid = threadIdx.x;
    const int lane = tid & 31;
    const int wq = tid >> 5;              // warp: q rows [wq*16, wq*16+16)
    const int qt = (int)gridDim.x - 1 - (int)blockIdx.x;   // heavy CTAs first
    const int bh = blockIdx.y;
    const size_t base = (size_t)bh * S_ * HD_;
    const float qscale = 0.08838834764831845f;  // 1/sqrt(128)

    // PV-phase thread map
    const int txp = tid & 7;              // hd cols: txp*4 + 32g
    const int typ = tid >> 3;             // q rows: typ*4 + i

    // ---- Q tiles (hi/lo) ----
    #pragma unroll
    for (int t = 0; t < 8; t++) {
        int idx = t * 256 + tid;
        int row = idx >> 4, ch = idx & 15;
        size_t go = base + (size_t)(qt * 128 + row) * HD_ + ch * 8;
        cp16(sb + A_SQH + row * 272 + ch * 16, g_qhi + go);
        cp16(sb + A_SQL + row * 272 + ch * 16, g_qlo + go);
    }
    CP_COMMIT();

    float acc_o[4][16];
    #pragma unroll
    for (int i = 0; i < 4; i++)
        #pragma unroll
        for (int c = 0; c < 16; c++) acc_o[i][c] = 0.f;
    float m_run[2] = {-1e30f, -1e30f};
    float l_run[2] = {0.f, 0.f};

    const int r0 = wq * 16 + (lane >> 2);
    const int nkt = 2 * qt + 2;

    for (int kt = 0; kt < nkt; kt++) {
        // ---- load K hi/lo + V ----
        #pragma unroll
        for (int t = 0; t < 4; t++) {
            int idx = t * 256 + tid;
            int row = idx >> 4, ch = idx & 15;
            size_t go = base + (size_t)(kt * 64 + row) * HD_ + ch * 8;
            cp16(sb + A_SKH + row * 272 + ch * 16, g_khi + go);
            cp16(sb + A_SKL + row * 272 + ch * 16, g_klo + go);
        }
        #pragma unroll
        for (int t = 0; t < 8; t++) {
            int idx = t * 256 + tid;
            int row = idx >> 5, ch = idx & 31;
            cp16(sb + A_SV + row * 528 + ch * 16,
                 g_v + base + (size_t)(kt * 64 + row) * HD_ + ch * 4);
        }
        CP_COMMIT();
        asm volatile("cp.async.wait_group 0;" ::: "memory");
        __syncthreads();

        // ---- scores: S = Q K^T (3-term hi/lo) ----
        float sacc[8][4];
        #pragma unroll
        for (int ni = 0; ni < 8; ni++)
            #pragma unroll
            for (int e = 0; e < 4; e++) sacc[ni][e] = 0.f;

        const int lrow = lane & 15;
        const int lk = (lane >> 4) * 8;
        #pragma unroll
        for (int kk = 0; kk < 8; kk++) {
            const int kb = (kk * 16 + lk) * 2;
            uint32_t ah[4], al[4];
            ldsm4(ah, sb + A_SQH + (wq * 16 + lrow) * 272 + kb);
            ldsm4(al, sb + A_SQL + (wq * 16 + lrow) * 272 + kb);
            uint32_t bh4[4][4], bl4[4][4];
            #pragma unroll
            for (int nj = 0; nj < 4; nj++) {
                ldsm4(bh4[nj], sb + A_SKH + (nj * 16 + lrow) * 272 + kb);
                ldsm4(bl4[nj], sb + A_SKL + (nj * 16 + lrow) * 272 + kb);
            }
            #pragma unroll
            for (int ni = 0; ni < 8; ni++) {
                const int nj = ni >> 1, ns = ni & 1;
                mma16816(sacc[ni], ah, bh4[nj][ns], bh4[nj][ns+2]);
                mma16816(sacc[ni], ah, bl4[nj][ns], bl4[nj][ns+2]);
                mma16816(sacc[ni], al, bh4[nj][ns], bh4[nj][ns+2]);
            }
        }

        // ---- online softmax (rows r0, r0+8) ----
        #pragma unroll
        for (int h2 = 0; h2 < 2; h2++) {
            const int qg = qt * 128 + r0 + h2 * 8;
            float v[16];
            float mloc = -1e30f;
            #pragma unroll
            for (int ni = 0; ni < 8; ni++)
                #pragma unroll
                for (int e = 0; e < 2; e++) {
                    float s = sacc[ni][h2*2 + e] * qscale;
                    int kg = kt * 64 + ni * 8 + (lane & 3) * 2 + e;
                    if (kg > qg) s = -1e30f;
                    v[ni*2 + e] = s;
                    mloc = fmaxf(mloc, s);
                }
            mloc = fmaxf(mloc, __shfl_xor_sync(0xffffffffu, mloc, 1));
            mloc = fmaxf(mloc, __shfl_xor_sync(0xffffffffu, mloc, 2));
            float mnew = fmaxf(m_run[h2], mloc);
            float corr = __expf(m_run[h2] - mnew);
            float rsum = 0.f;
            float* prow = Ps + (r0 + h2 * 8) * 69 + (lane & 3) * 2;
            #pragma unroll
            for (int ni = 0; ni < 8; ni++) {
                float p0 = __expf(v[ni*2 + 0] - mnew);
                float p1 = __expf(v[ni*2 + 1] - mnew);
                rsum += p0 + p1;
                prow[ni*8 + 0] = p0;
                prow[ni*8 + 1] = p1;
            }
            rsum += __shfl_xor_sync(0xffffffffu, rsum, 1);
            rsum += __shfl_xor_sync(0xffffffffu, rsum, 2);
            l_run[h2] = l_run[h2] * corr + rsum;
            m_run[h2] = mnew;
            if ((lane & 3) == 0) CorS[r0 + h2 * 8] = corr;
        }
        __syncthreads();

        // ---- PV (fp32): acc_o = acc_o*corr + P V ----
        #pragma unroll
        for (int i = 0; i < 4; i++) {
            float c = CorS[typ * 4 + i];
            #pragma unroll
            for (int g = 0; g < 16; g++) acc_o[i][g] *= c;
        }
        #pragma unroll 4
        for (int k = 0; k < 64; k++) {
            float pv[4];
            #pragma unroll
            for (int i = 0; i < 4; i++) pv[i] = Ps[(typ*4 + i) * 69 + k];
            float4 vv[4];
            #pragma unroll
            for (int g = 0; g < 4; g++)
                vv[g] = *(const float4*)(smc + A_SV + k * 528 + (txp*4 + 32*g) * 4);
            #pragma unroll
            for (int i = 0; i < 4; i++)
                #pragma unroll
                for (int g = 0; g < 4; g++) {
                    acc_o[i][g*4+0] += pv[i] * vv[g].x;
                    acc_o[i][g*4+1] += pv[i] * vv[g].y;
                    acc_o[i][g*4+2] += pv[i] * vv[g].z;
                    acc_o[i][g*4+3] += pv[i] * vv[g].w;
                }
        }
        __syncthreads();
    }

    // ---- finalize ----
    if ((lane & 3) == 0) {
        LSm[r0]     = l_run[0];
        LSm[r0 + 8] = l_run[1];
    }
    __syncthreads();

    const int b = bh >> 4;
    const int h = bh & 15;
    #pragma unroll
    for (int i = 0; i < 4; i++) {
        int sg = qt * 128 + typ * 4 + i;
        float inv = 1.0f / LSm[typ * 4 + i];
        float* p = g_ao + ((size_t)(b * S_ + sg)) * D_ + h * HD_;
        #pragma unroll
        for (int g = 0; g < 4; g++) {
            float4 v = make_float4(acc_o[i][g*4+0]*inv, acc_o[i][g*4+1]*inv,
                                   acc_o[i][g*4+2]*inv, acc_o[i][g*4+3]*inv);
            *(float4*)(p + txp*4 + 32*g) = v;
        }
    }
}

extern "C" void kernel_launch(void* const* d_in, const int* in_sizes, int n_in,
                              void* d_out, int out_size) {
    (void)in_sizes; (void)n_in; (void)out_size;
    const float* x  = (const float*)d_in[0];
    const float* Wq = (const float*)d_in[1];
    const float* Wk = (const float*)d_in[2];
    const float* Wv = (const float*)d_in[3];
    const float* Wo = (const float*)d_in[4];
    float* out = (float*)d_out;

    float *v, *ao;
    __nv_bfloat16 *xhi, *xlo, *whi, *wlo, *qhi, *qlo, *khi, *klo;
    cudaGetSymbolAddress((void**)&v,   g_v);
    cudaGetSymbolAddress((void**)&ao,  g_ao);
    cudaGetSymbolAddress((void**)&xhi, g_xhi);
    cudaGetSymbolAddress((void**)&xlo, g_xlo);
    cudaGetSymbolAddress((void**)&whi, g_whi);
    cudaGetSymbolAddress((void**)&wlo, g_wlo);
    cudaGetSymbolAddress((void**)&qhi, g_qhi);
    cudaGetSymbolAddress((void**)&qlo, g_qlo);
    cudaGetSymbolAddress((void**)&khi, g_khi);
    cudaGetSymbolAddress((void**)&klo, g_klo);

    const size_t DD = (size_t)D_ * D_;

    cudaFuncSetAttribute(gemm_tc<0>, cudaFuncAttributeMaxDynamicSharedMemorySize, GT_SMEM);
    cudaFuncSetAttribute(gemm_tc<1>, cudaFuncAttributeMaxDynamicSharedMemorySize, GT_SMEM);
    cudaFuncSetAttribute(gemm_tc<2>, cudaFuncAttributeMaxDynamicSharedMemorySize, GT_SMEM);
    cudaFuncSetAttribute(attn_mma, cudaFuncAttributeMaxDynamicSharedMemorySize, A_SMEM);

    dim3 tgrid(D_/128, M_/128);   // (16, 32)

    // launch order arranged so ncu (-s 5 -c 1) captures gemm_tc<1> (launch #6)
    rope_table_kernel<<<(S_*F_ + 255)/256, 256>>>();
    conv_kernel<<<(M_*D_/4 + 255)/256, 256>>>(x,  xhi, xlo, M_*D_/4);
    conv_kernel<<<(D_*D_/4 + 255)/256, 256>>>(Wq, whi + 0*DD, wlo + 0*DD, D_*D_/4);
    conv_kernel<<<(D_*D_/4 + 255)/256, 256>>>(Wk, whi + 1*DD, wlo + 1*DD, D_*D_/4);
    conv_kernel<<<(D_*D_/4 + 255)/256, 256>>>(Wv, whi + 2*DD, wlo + 2*DD, D_*D_/4);
    gemm_tc<1><<<tgrid, 256, GT_SMEM>>>(xhi, xlo, whi + 0*DD, wlo + 0*DD, nullptr, qhi, qlo);
    conv_kernel<<<(D_*D_/4 + 255)/256, 256>>>(Wo, whi + 3*DD, wlo + 3*DD, D_*D_/4);
    gemm_tc<1><<<tgrid, 256, GT_SMEM>>>(xhi, xlo, whi + 1*DD, wlo + 1*DD, nullptr, khi, klo);
    gemm_tc<2><<<tgrid, 256, GT_SMEM>>>(xhi, xlo, whi + 2*DD, wlo + 2*DD, v, nullptr, nullptr);

    attn_mma<<<dim3(S_/128, B_*H_), 256, A_SMEM>>>();

    conv_kernel<<<(M_*D_/4 + 255)/256, 256>>>(ao, xhi, xlo, M_*D_/4);
    gemm_tc<0><<<tgrid, 256, GT_SMEM>>>(xhi, xlo, whi + 3*DD, wlo + 3*DD, out, nullptr, nullptr);
}

// round 7
// speedup vs baseline: 2.0149x; 1.0743x over previous
#include <cuda_runtime.h>
#include <cuda_bf16.h>
#include <math.h>
#include <stdint.h>

#define B_  2
#define S_  2048
#define D_  2048
#define H_  16
#define HD_ 128
#define M_  (B_*S_)      // 4096
#define F_  (HD_/2)      // 64

// ---------------- scratch (alloc-free rule: __device__ globals) ----------------
__device__ float g_v [B_*H_*S_*HD_];   // [b,h,s,hd] fp32
__device__ float g_ao[M_*D_];          // attention output, [b*s, d]
__device__ float g_cos[S_*F_];
__device__ float g_sin[S_*F_];

__device__ __nv_bfloat16 g_qhi[B_*H_*S_*HD_];
__device__ __nv_bfloat16 g_qlo[B_*H_*S_*HD_];
__device__ __nv_bfloat16 g_khi[B_*H_*S_*HD_];
__device__ __nv_bfloat16 g_klo[B_*H_*S_*HD_];

__device__ __nv_bfloat16 g_xhi[M_*D_];
__device__ __nv_bfloat16 g_xlo[M_*D_];
__device__ __nv_bfloat16 g_whi[4*D_*D_];
__device__ __nv_bfloat16 g_wlo[4*D_*D_];

// ---------------- PTX helpers (plain sm_100 target: no tcgen05) ----------------
__device__ __forceinline__ uint32_t smem_u32(const void* p) {
    uint32_t a;
    asm("{ .reg .u64 t; cvta.to.shared.u64 t, %1; cvt.u32.u64 %0, t; }" : "=r"(a) : "l"(p));
    return a;
}
__device__ __forceinline__ void cp16(uint32_t s, const void* g) {
    asm volatile("cp.async.cg.shared.global [%0], [%1], 16;" :: "r"(s), "l"(g));
}
#define CP_COMMIT() asm volatile("cp.async.commit_group;")

__device__ __forceinline__ void ldsm4(uint32_t* r, uint32_t addr) {
    asm volatile("ldmatrix.sync.aligned.m8n8.x4.shared.b16 {%0,%1,%2,%3}, [%4];"
        : "=r"(r[0]), "=r"(r[1]), "=r"(r[2]), "=r"(r[3]) : "r"(addr));
}
__device__ __forceinline__ void mma16816(float* d, const uint32_t* a, uint32_t b0, uint32_t b1) {
    asm volatile(
        "mma.sync.aligned.m16n8k16.row.col.f32.bf16.bf16.f32 "
        "{%0,%1,%2,%3}, {%4,%5,%6,%7}, {%8,%9}, {%0,%1,%2,%3};"
        : "+f"(d[0]), "+f"(d[1]), "+f"(d[2]), "+f"(d[3])
        : "r"(a[0]), "r"(a[1]), "r"(a[2]), "r"(a[3]), "r"(b0), "r"(b1));
}

// ---------------- RoPE table ----------------
__global__ void rope_table_kernel() {
    int idx = blockIdx.x * blockDim.x + threadIdx.x;
    if (idx >= S_ * F_) return;
    int s = idx >> 6;
    int i = idx & 63;
    double invf = pow(10000.0, -(double)i / 64.0);
    double f = (double)s * invf;
    double sn, cs;
    sincos(f, &sn, &cs);
    g_cos[idx] = (float)cs;
    g_sin[idx] = (float)sn;
}

// ---------------- fp32 -> bf16 hi/lo split ----------------
__global__ void conv_kernel(const float* __restrict__ in,
                            __nv_bfloat16* __restrict__ hi,
                            __nv_bfloat16* __restrict__ lo, int n4) {
    int i = blockIdx.x * blockDim.x + threadIdx.x;
    if (i >= n4) return;
    float4 v = ((const float4*)in)[i];
    float xs[4] = {v.x, v.y, v.z, v.w};
    __nv_bfloat16 h[4], l[4];
    #pragma unroll
    for (int j = 0; j < 4; j++) {
        h[j] = __float2bfloat16(xs[j]);
        l[j] = __float2bfloat16(xs[j] - __bfloat162float(h[j]));
    }
    __nv_bfloat162* hp = (__nv_bfloat162*)hi;
    __nv_bfloat162* lp = (__nv_bfloat162*)lo;
    hp[2*i]   = __halves2bfloat162(h[0], h[1]);
    hp[2*i+1] = __halves2bfloat162(h[2], h[3]);
    lp[2*i]   = __halves2bfloat162(l[0], l[1]);
    lp[2*i+1] = __halves2bfloat162(l[2], l[3]);
}

// ---------------- mma.sync bf16 GEMM: C[m,n] = sum_k A[m,k]*B[n,k] ----------------
// MODE 0: out fp32 row-major [M,2048]
// MODE 1: RoPE, out bf16 hi/lo [B,H,S,HD]  (outhi/outlo)
// MODE 2: out fp32 [B,H,S,HD]
// 2-stage double buffer, 2 CTAs/SM.
#define KC 32
#define ROWB 80
#define TILE_B (128*ROWB)
#define STAGE_B (4*TILE_B)
#define GT_SMEM (2*STAGE_B)          // 81920

template <int MODE>
__global__ __launch_bounds__(256, 2) void gemm_tc(
    const __nv_bfloat16* __restrict__ Ahi, const __nv_bfloat16* __restrict__ Alo,
    const __nv_bfloat16* __restrict__ Bhi, const __nv_bfloat16* __restrict__ Blo,
    float* __restrict__ outp,
    __nv_bfloat16* __restrict__ outhi, __nv_bfloat16* __restrict__ outlo)
{
    extern __shared__ char smc[];
    const uint32_t sb = smem_u32(smc);
    const int tid = threadIdx.x;
    const int lane = tid & 31;
    const int wid = tid >> 5;
    const int wm = (wid >> 2) * 64;
    const int wn = (wid & 3) * 32;
    const int m0 = blockIdx.y * 128;
    const int n0 = blockIdx.x * 128;

    auto load_stage = [&](int stg, int k0) {
        uint32_t base = sb + stg * STAGE_B;
        #pragma unroll
        for (int t = 0; t < 2; t++) {
            int idx = t * 256 + tid;
            int row = idx >> 2, seg = idx & 3;
            uint32_t so = row * ROWB + seg * 16;
            size_t goA = (size_t)(m0 + row) * D_ + k0 + seg * 8;
            size_t goB = (size_t)(n0 + row) * D_ + k0 + seg * 8;
            cp16(base + 0*TILE_B + so, Ahi + goA);
            cp16(base + 1*TILE_B + so, Alo + goA);
            cp16(base + 2*TILE_B + so, Bhi + goB);
            cp16(base + 3*TILE_B + so, Blo + goB);
        }
        CP_COMMIT();
    };

    float acc[4][4][4];
    #pragma unroll
    for (int mi = 0; mi < 4; mi++)
        #pragma unroll
        for (int ni = 0; ni < 4; ni++)
            #pragma unroll
            for (int e = 0; e < 4; e++) acc[mi][ni][e] = 0.f;

    load_stage(0, 0);

    const int NCH = 2048 / KC;
    const int lrow = lane & 15;
    const int lk   = (lane >> 4) * 8;

    for (int c = 0; c < NCH; c++) {
        asm volatile("cp.async.wait_group 0;" ::: "memory");
        __syncthreads();
        // prefetch next stage; overlaps with compute below
        if (c + 1 < NCH) load_stage((c + 1) & 1, (c + 1) * KC);

        const uint32_t st = sb + (c & 1) * STAGE_B;
        const uint32_t aAh = st, aAl = st + TILE_B, aBh = st + 2*TILE_B, aBl = st + 3*TILE_B;

        #pragma unroll
        for (int kk = 0; kk < 2; kk++) {
            const int kb = (kk * 16 + lk) * 2;
            uint32_t ah[4][4], al[4][4];
            #pragma unroll
            for (int mi = 0; mi < 4; mi++) {
                uint32_t off = (wm + mi*16 + lrow) * ROWB + kb;
                ldsm4(ah[mi], aAh + off);
                ldsm4(al[mi], aAl + off);
            }
            uint32_t bh[2][4], bl[2][4];
            #pragma unroll
            for (int nj = 0; nj < 2; nj++) {
                uint32_t off = (wn + nj*16 + lrow) * ROWB + kb;
                ldsm4(bh[nj], aBh + off);
                ldsm4(bl[nj], aBl + off);
            }
            #pragma unroll
            for (int mi = 0; mi < 4; mi++)
                #pragma unroll
                for (int ni = 0; ni < 4; ni++) {
                    const int nj = ni >> 1, ns = ni & 1;
                    mma16816(acc[mi][ni], ah[mi], bh[nj][ns], bh[nj][ns+2]);
                    mma16816(acc[mi][ni], ah[mi], bl[nj][ns], bl[nj][ns+2]);
                    mma16816(acc[mi][ni], al[mi], bh[nj][ns], bh[nj][ns+2]);
                }
        }
    }

    const int rr = lane >> 2;
    const int cp = (lane & 3) * 2;
    #pragma unroll
    for (int mi = 0; mi < 4; mi++) {
        #pragma unroll
        for (int half = 0; half < 2; half++) {
            int m = m0 + wm + mi*16 + rr + half*8;
            int s = m & (S_ - 1);
            #pragma unroll
            for (int ni = 0; ni < 4; ni++) {
                float e = acc[mi][ni][half*2 + 0];
                float o = acc[mi][ni][half*2 + 1];
                int n = n0 + wn + ni*8 + cp;
                if (MODE == 1) {
                    int pair = (n & (HD_ - 1)) >> 1;
                    float cc = g_cos[s * F_ + pair], ss = g_sin[s * F_ + pair];
                    float xe = e, xo = o;
                    e = xe * cc - xo * ss;
                    o = xo * cc + xe * ss;
                    int br = m >> 11, h = n >> 7, hd = n & (HD_ - 1);
                    size_t ei = (((size_t)(br * H_ + h)) * S_ + s) * HD_ + hd;
                    __nv_bfloat16 eh = __float2bfloat16(e);
                    __nv_bfloat16 oh = __float2bfloat16(o);
                    __nv_bfloat16 el = __float2bfloat16(e - __bfloat162float(eh));
                    __nv_bfloat16 ol = __float2bfloat16(o - __bfloat162float(oh));
                    ((__nv_bfloat162*)outhi)[ei >> 1] = __halves2bfloat162(eh, oh);
                    ((__nv_bfloat162*)outlo)[ei >> 1] = __halves2bfloat162(el, ol);
                } else if (MODE == 0) {
                    *(float2*)(outp + (size_t)m * D_ + n) = make_float2(e, o);
                } else {
                    int br = m >> 11, h = n >> 7, hd = n & (HD_ - 1);
                    *(float2*)(outp + (((size_t)(br * H_ + h)) * S_ + s) * HD_ + hd) =
                        make_float2(e, o);
                }
            }
        }
    }
}

// ---------------- flash attention: HMMA QK^T (3-term) + fp32 PV ----------------
// CTA: 128 q-rows (8 warps x m16), K-tile 64, 256 threads.
// K double-buffered (prefetch next tile); V prefetched under QK+softmax.
#define A_SQH 0                     // Q hi: 128 x 272B
#define A_SQL 34816                 // Q lo
#define A_SKH(b) (69632  + (b)*17408)   // K hi x2: 64 x 272B
#define A_SKL(b) (104448 + (b)*17408)   // K lo x2
#define A_SV  139264                // V fp32: 64 x 528B
#define A_SP  173056                // P fp32: 128 x 69 floats
#define A_SC  208384                // corr: 128 floats
#define A_SL  208896                // l:    128 floats
#define A_SMEM 209408

__global__ __launch_bounds__(256, 1) void attn_mma()
{
    extern __shared__ char smc[];
    const uint32_t sb = smem_u32(smc);
    float* Ps   = (float*)(smc + A_SP);
    float* CorS = (float*)(smc + A_SC);
    float* LSm  = (float*)(smc + A_SL);

    const int tid = threadIdx.x;
    const int lane = tid & 31;
    const int wq = tid >> 5;
    const int qt = (int)gridDim.x - 1 - (int)blockIdx.x;   // heavy CTAs first
    const int bh = blockIdx.y;
    const size_t base = (size_t)bh * S_ * HD_;
    const float qscale = 0.08838834764831845f;  // 1/sqrt(128)

    const int txp = tid & 7;
    const int typ = tid >> 3;

    // ---- preload: Q tiles (group), K[0] (group) ----
    #pragma unroll
    for (int t = 0; t < 8; t++) {
        int idx = t * 256 + tid;
        int row = idx >> 4, ch = idx & 15;
        size_t go = base + (size_t)(qt * 128 + row) * HD_ + ch * 8;
        cp16(sb + A_SQH + row * 272 + ch * 16, g_qhi + go);
        cp16(sb + A_SQL + row * 272 + ch * 16, g_qlo + go);
    }
    CP_COMMIT();
    #pragma unroll
    for (int t = 0; t < 4; t++) {
        int idx = t * 256 + tid;
        int row = idx >> 4, ch = idx & 15;
        size_t go = base + (size_t)row * HD_ + ch * 8;
        cp16(sb + A_SKH(0) + row * 272 + ch * 16, g_khi + go);
        cp16(sb + A_SKL(0) + row * 272 + ch * 16, g_klo + go);
    }
    CP_COMMIT();

    float acc_o[4][16];
    #pragma unroll
    for (int i = 0; i < 4; i++)
        #pragma unroll
        for (int c = 0; c < 16; c++) acc_o[i][c] = 0.f;
    float m_run[2] = {-1e30f, -1e30f};
    float l_run[2] = {0.f, 0.f};

    const int r0 = wq * 16 + (lane >> 2);
    const int nkt = 2 * qt + 2;

    for (int kt = 0; kt < nkt; kt++) {
        const int kbuf = kt & 1;
        // wait: K[kt] (and Q at kt=0) arrived
        asm volatile("cp.async.wait_group 0;" ::: "memory");
        __syncthreads();

        // issue V[kt] (group), then K[kt+1] prefetch (group)
        #pragma unroll
        for (int t = 0; t < 8; t++) {
            int idx = t * 256 + tid;
            int row = idx >> 5, ch = idx & 31;
            cp16(sb + A_SV + row * 528 + ch * 16,
                 g_v + base + (size_t)(kt * 64 + row) * HD_ + ch * 4);
        }
        CP_COMMIT();
        const bool pk = (kt + 1) < nkt;
        if (pk) {
            #pragma unroll
            for (int t = 0; t < 4; t++) {
                int idx = t * 256 + tid;
                int row = idx >> 4, ch = idx & 15;
                size_t go = base + (size_t)((kt + 1) * 64 + row) * HD_ + ch * 8;
                cp16(sb + A_SKH(kbuf ^ 1) + row * 272 + ch * 16, g_khi + go);
                cp16(sb + A_SKL(kbuf ^ 1) + row * 272 + ch * 16, g_klo + go);
            }
            CP_COMMIT();
        }

        // ---- scores: S = Q K^T (3-term hi/lo) ----
        float sacc[8][4];
        #pragma unroll
        for (int ni = 0; ni < 8; ni++)
            #pragma unroll
            for (int e = 0; e < 4; e++) sacc[ni][e] = 0.f;

        const int lrow = lane & 15;
        const int lk = (lane >> 4) * 8;
        #pragma unroll
        for (int kk = 0; kk < 8; kk++) {
            const int kb = (kk * 16 + lk) * 2;
            uint32_t ah[4], al[4];
            ldsm4(ah, sb + A_SQH + (wq * 16 + lrow) * 272 + kb);
            ldsm4(al, sb + A_SQL + (wq * 16 + lrow) * 272 + kb);
            uint32_t bh4[4][4], bl4[4][4];
            #pragma unroll
            for (int nj = 0; nj < 4; nj++) {
                ldsm4(bh4[nj], sb + A_SKH(kbuf) + (nj * 16 + lrow) * 272 + kb);
                ldsm4(bl4[nj], sb + A_SKL(kbuf) + (nj * 16 + lrow) * 272 + kb);
            }
            #pragma unroll
            for (int ni = 0; ni < 8; ni++) {
                const int nj = ni >> 1, ns = ni & 1;
                mma16816(sacc[ni], ah, bh4[nj][ns], bh4[nj][ns+2]);
                mma16816(sacc[ni], ah, bl4[nj][ns], bl4[nj][ns+2]);
                mma16816(sacc[ni], al, bh4[nj][ns], bh4[nj][ns+2]);
            }
        }

        // ---- online softmax (rows r0, r0+8) ----
        #pragma unroll
        for (int h2 = 0; h2 < 2; h2++) {
            const int qg = qt * 128 + r0 + h2 * 8;
            float v[16];
            float mloc = -1e30f;
            #pragma unroll
            for (int ni = 0; ni < 8; ni++)
                #pragma unroll
                for (int e = 0; e < 2; e++) {
                    float s = sacc[ni][h2*2 + e] * qscale;
                    int kg = kt * 64 + ni * 8 + (lane & 3) * 2 + e;
                    if (kg > qg) s = -1e30f;
                    v[ni*2 + e] = s;
                    mloc = fmaxf(mloc, s);
                }
            mloc = fmaxf(mloc, __shfl_xor_sync(0xffffffffu, mloc, 1));
            mloc = fmaxf(mloc, __shfl_xor_sync(0xffffffffu, mloc, 2));
            float mnew = fmaxf(m_run[h2], mloc);
            float corr = __expf(m_run[h2] - mnew);
            float rsum = 0.f;
            float* prow = Ps + (r0 + h2 * 8) * 69 + (lane & 3) * 2;
            #pragma unroll
            for (int ni = 0; ni < 8; ni++) {
                float p0 = __expf(v[ni*2 + 0] - mnew);
                float p1 = __expf(v[ni*2 + 1] - mnew);
                rsum += p0 + p1;
                prow[ni*8 + 0] = p0;
                prow[ni*8 + 1] = p1;
            }
            rsum += __shfl_xor_sync(0xffffffffu, rsum, 1);
            rsum += __shfl_xor_sync(0xffffffffu, rsum, 2);
            l_run[h2] = l_run[h2] * corr + rsum;
            m_run[h2] = mnew;
            if ((lane & 3) == 0) CorS[r0 + h2 * 8] = corr;
        }

        // wait for V[kt] (leave K[kt+1] in flight if issued)
        if (pk) { asm volatile("cp.async.wait_group 1;" ::: "memory"); }
        else    { asm volatile("cp.async.wait_group 0;" ::: "memory"); }
        __syncthreads();

        // ---- PV (fp32): acc_o = acc_o*corr + P V ----
        #pragma unroll
        for (int i = 0; i < 4; i++) {
            float c = CorS[typ * 4 + i];
            #pragma unroll
            for (int g = 0; g < 16; g++) acc_o[i][g] *= c;
        }
        #pragma unroll 4
        for (int k = 0; k < 64; k++) {
            float pv[4];
            #pragma unroll
            for (int i = 0; i < 4; i++) pv[i] = Ps[(typ*4 + i) * 69 + k];
            float4 vv[4];
            #pragma unroll
            for (int g = 0; g < 4; g++)
                vv[g] = *(const float4*)(smc + A_SV + k * 528 + (txp*4 + 32*g) * 4);
            #pragma unroll
            for (int i = 0; i < 4; i++)
                #pragma unroll
                for (int g = 0; g < 4; g++) {
                    acc_o[i][g*4+0] += pv[i] * vv[g].x;
                    acc_o[i][g*4+1] += pv[i] * vv[g].y;
                    acc_o[i][g*4+2] += pv[i] * vv[g].z;
                    acc_o[i][g*4+3] += pv[i] * vv[g].w;
                }
        }
        __syncthreads();
    }

    // ---- finalize ----
    if ((lane & 3) == 0) {
        LSm[r0]     = l_run[0];
        LSm[r0 + 8] = l_run[1];
    }
    __syncthreads();

    const int b = bh >> 4;
    const int h = bh & 15;
    #pragma unroll
    for (int i = 0; i < 4; i++) {
        int sg = qt * 128 + typ * 4 + i;
        float inv = 1.0f / LSm[typ * 4 + i];
        float* p = g_ao + ((size_t)(b * S_ + sg)) * D_ + h * HD_;
        #pragma unroll
        for (int g = 0; g < 4; g++) {
            float4 v = make_float4(acc_o[i][g*4+0]*inv, acc_o[i][g*4+1]*inv,
                                   acc_o[i][g*4+2]*inv, acc_o[i][g*4+3]*inv);
            *(float4*)(p + txp*4 + 32*g) = v;
        }
    }
}

extern "C" void kernel_launch(void* const* d_in, const int* in_sizes, int n_in,
                              void* d_out, int out_size) {
    (void)in_sizes; (void)n_in; (void)out_size;
    const float* x  = (const float*)d_in[0];
    const float* Wq = (const float*)d_in[1];
    const float* Wk = (const float*)d_in[2];
    const float* Wv = (const float*)d_in[3];
    const float* Wo = (const float*)d_in[4];
    float* out = (float*)d_out;

    float *v, *ao;
    __nv_bfloat16 *xhi, *xlo, *whi, *wlo, *qhi, *qlo, *khi, *klo;
    cudaGetSymbolAddress((void**)&v,   g_v);
    cudaGetSymbolAddress((void**)&ao,  g_ao);
    cudaGetSymbolAddress((void**)&xhi, g_xhi);
    cudaGetSymbolAddress((void**)&xlo, g_xlo);
    cudaGetSymbolAddress((void**)&whi, g_whi);
    cudaGetSymbolAddress((void**)&wlo, g_wlo);
    cudaGetSymbolAddress((void**)&qhi, g_qhi);
    cudaGetSymbolAddress((void**)&qlo, g_qlo);
    cudaGetSymbolAddress((void**)&khi, g_khi);
    cudaGetSymbolAddress((void**)&klo, g_klo);

    const size_t DD = (size_t)D_ * D_;

    cudaFuncSetAttribute(gemm_tc<0>, cudaFuncAttributeMaxDynamicSharedMemorySize, GT_SMEM);
    cudaFuncSetAttribute(gemm_tc<1>, cudaFuncAttributeMaxDynamicSharedMemorySize, GT_SMEM);
    cudaFuncSetAttribute(gemm_tc<2>, cudaFuncAttributeMaxDynamicSharedMemorySize, GT_SMEM);
    cudaFuncSetAttribute(attn_mma, cudaFuncAttributeMaxDynamicSharedMemorySize, A_SMEM);

    dim3 tgrid(D_/128, M_/128);   // (16, 32)

    rope_table_kernel<<<(S_*F_ + 255)/256, 256>>>();
    conv_kernel<<<(M_*D_/4 + 255)/256, 256>>>(x,  xhi, xlo, M_*D_/4);
    conv_kernel<<<(D_*D_/4 + 255)/256, 256>>>(Wq, whi + 0*DD, wlo + 0*DD, D_*D_/4);
    conv_kernel<<<(D_*D_/4 + 255)/256, 256>>>(Wk, whi + 1*DD, wlo + 1*DD, D_*D_/4);
    conv_kernel<<<(D_*D_/4 + 255)/256, 256>>>(Wv, whi + 2*DD, wlo + 2*DD, D_*D_/4);
    gemm_tc<1><<<tgrid, 256, GT_SMEM>>>(xhi, xlo, whi + 0*DD, wlo + 0*DD, nullptr, qhi, qlo);
    conv_kernel<<<(D_*D_/4 + 255)/256, 256>>>(Wo, whi + 3*DD, wlo + 3*DD, D_*D_/4);
    gemm_tc<1><<<tgrid, 256, GT_SMEM>>>(xhi, xlo, whi + 1*DD, wlo + 1*DD, nullptr, khi, klo);
    gemm_tc<2><<<tgrid, 256, GT_SMEM>>>(xhi, xlo, whi + 2*DD, wlo + 2*DD, v, nullptr, nullptr);

    attn_mma<<<dim3(S_/128, B_*H_), 256, A_SMEM>>>();

    conv_kernel<<<(M_*D_/4 + 255)/256, 256>>>(ao, xhi, xlo, M_*D_/4);
    gemm_tc<0><<<tgrid, 256, GT_SMEM>>>(xhi, xlo, whi + 3*DD, wlo + 3*DD, out, nullptr, nullptr);
}

// round 8
// speedup vs baseline: 2.1387x; 1.0614x over previous
#include <cuda_runtime.h>
#include <cuda_bf16.h>
#include <math.h>
#include <stdint.h>

#define B_  2
#define S_  2048
#define D_  2048
#define H_  16
#define HD_ 128
#define M_  (B_*S_)      // 4096
#define F_  (HD_/2)      // 64

// ---------------- scratch (alloc-free rule: __device__ globals) ----------------
__device__ float g_ao[M_*D_];          // attention output, [b*s, d]
__device__ float g_cos[S_*F_];
__device__ float g_sin[S_*F_];

__device__ __nv_bfloat16 g_qhi[B_*H_*S_*HD_];
__device__ __nv_bfloat16 g_qlo[B_*H_*S_*HD_];
__device__ __nv_bfloat16 g_khi[B_*H_*S_*HD_];
__device__ __nv_bfloat16 g_klo[B_*H_*S_*HD_];
__device__ __nv_bfloat16 g_vhi[B_*H_*S_*HD_];
__device__ __nv_bfloat16 g_vlo[B_*H_*S_*HD_];

__device__ __nv_bfloat16 g_xhi[M_*D_];
__device__ __nv_bfloat16 g_xlo[M_*D_];
__device__ __nv_bfloat16 g_whi[4*D_*D_];
__device__ __nv_bfloat16 g_wlo[4*D_*D_];

// ---------------- PTX helpers (plain sm_100 target: no tcgen05) ----------------
__device__ __forceinline__ uint32_t smem_u32(const void* p) {
    uint32_t a;
    asm("{ .reg .u64 t; cvta.to.shared.u64 t, %1; cvt.u32.u64 %0, t; }" : "=r"(a) : "l"(p));
    return a;
}
__device__ __forceinline__ void cp16(uint32_t s, const void* g) {
    asm volatile("cp.async.cg.shared.global [%0], [%1], 16;" :: "r"(s), "l"(g));
}
#define CP_COMMIT() asm volatile("cp.async.commit_group;")

__device__ __forceinline__ void ldsm4(uint32_t* r, uint32_t addr) {
    asm volatile("ldmatrix.sync.aligned.m8n8.x4.shared.b16 {%0,%1,%2,%3}, [%4];"
        : "=r"(r[0]), "=r"(r[1]), "=r"(r[2]), "=r"(r[3]) : "r"(addr));
}
__device__ __forceinline__ void ldsm4t(uint32_t* r, uint32_t addr) {
    asm volatile("ldmatrix.sync.aligned.m8n8.x4.trans.shared.b16 {%0,%1,%2,%3}, [%4];"
        : "=r"(r[0]), "=r"(r[1]), "=r"(r[2]), "=r"(r[3]) : "r"(addr));
}
__device__ __forceinline__ void mma16816(float* d, const uint32_t* a, uint32_t b0, uint32_t b1) {
    asm volatile(
        "mma.sync.aligned.m16n8k16.row.col.f32.bf16.bf16.f32 "
        "{%0,%1,%2,%3}, {%4,%5,%6,%7}, {%8,%9}, {%0,%1,%2,%3};"
        : "+f"(d[0]), "+f"(d[1]), "+f"(d[2]), "+f"(d[3])
        : "r"(a[0]), "r"(a[1]), "r"(a[2]), "r"(a[3]), "r"(b0), "r"(b1));
}
__device__ __forceinline__ uint32_t pack_bf16x2(float a, float b) {
    __nv_bfloat162 t = __halves2bfloat162(__float2bfloat16(a), __float2bfloat16(b));
    return *reinterpret_cast<uint32_t*>(&t);
}

// ---------------- RoPE table ----------------
__global__ void rope_table_kernel() {
    int idx = blockIdx.x * blockDim.x + threadIdx.x;
    if (idx >= S_ * F_) return;
    int s = idx >> 6;
    int i = idx & 63;
    double invf = pow(10000.0, -(double)i / 64.0);
    double f = (double)s * invf;
    double sn, cs;
    sincos(f, &sn, &cs);
    g_cos[idx] = (float)cs;
    g_sin[idx] = (float)sn;
}

// ---------------- fp32 -> bf16 hi/lo split ----------------
__global__ void conv_kernel(const float* __restrict__ in,
                            __nv_bfloat16* __restrict__ hi,
                            __nv_bfloat16* __restrict__ lo, int n4) {
    int i = blockIdx.x * blockDim.x + threadIdx.x;
    if (i >= n4) return;
    float4 v = ((const float4*)in)[i];
    float xs[4] = {v.x, v.y, v.z, v.w};
    __nv_bfloat16 h[4], l[4];
    #pragma unroll
    for (int j = 0; j < 4; j++) {
        h[j] = __float2bfloat16(xs[j]);
        l[j] = __float2bfloat16(xs[j] - __bfloat162float(h[j]));
    }
    __nv_bfloat162* hp = (__nv_bfloat162*)hi;
    __nv_bfloat162* lp = (__nv_bfloat162*)lo;
    hp[2*i]   = __halves2bfloat162(h[0], h[1]);
    hp[2*i+1] = __halves2bfloat162(h[2], h[3]);
    lp[2*i]   = __halves2bfloat162(l[0], l[1]);
    lp[2*i+1] = __halves2bfloat162(l[2], l[3]);
}

// ---------------- mma.sync bf16 GEMM: C[m,n] = sum_k A[m,k]*B[n,k] ----------------
// MODE 0: out fp32 row-major [M,2048]
// MODE 1: RoPE, out bf16 hi/lo [B,H,S,HD]
// MODE 3: no RoPE, out bf16 hi/lo [B,H,S,HD]
#define KC 32
#define ROWB 80
#define TILE_B (128*ROWB)
#define STAGE_B (4*TILE_B)
#define GT_SMEM (2*STAGE_B)          // 81920

template <int MODE>
__global__ __launch_bounds__(256, 2) void gemm_tc(
    const __nv_bfloat16* __restrict__ Ahi, const __nv_bfloat16* __restrict__ Alo,
    const __nv_bfloat16* __restrict__ Bhi, const __nv_bfloat16* __restrict__ Blo,
    float* __restrict__ outp,
    __nv_bfloat16* __restrict__ outhi, __nv_bfloat16* __restrict__ outlo,
    int ybase)
{
    extern __shared__ char smc[];
    const uint32_t sb = smem_u32(smc);
    const int tid = threadIdx.x;
    const int lane = tid & 31;
    const int wid = tid >> 5;
    const int wm = (wid >> 2) * 64;
    const int wn = (wid & 3) * 32;
    const int m0 = (blockIdx.y + ybase) * 128;
    const int n0 = blockIdx.x * 128;

    auto load_stage = [&](int stg, int k0) {
        uint32_t base = sb + stg * STAGE_B;
        #pragma unroll
        for (int t = 0; t < 2; t++) {
            int idx = t * 256 + tid;
            int row = idx >> 2, seg = idx & 3;
            uint32_t so = row * ROWB + seg * 16;
            size_t goA = (size_t)(m0 + row) * D_ + k0 + seg * 8;
            size_t goB = (size_t)(n0 + row) * D_ + k0 + seg * 8;
            cp16(base + 0*TILE_B + so, Ahi + goA);
            cp16(base + 1*TILE_B + so, Alo + goA);
            cp16(base + 2*TILE_B + so, Bhi + goB);
            cp16(base + 3*TILE_B + so, Blo + goB);
        }
        CP_COMMIT();
    };

    float acc[4][4][4];
    #pragma unroll
    for (int mi = 0; mi < 4; mi++)
        #pragma unroll
        for (int ni = 0; ni < 4; ni++)
            #pragma unroll
            for (int e = 0; e < 4; e++) acc[mi][ni][e] = 0.f;

    load_stage(0, 0);

    const int NCH = 2048 / KC;
    const int lrow = lane & 15;
    const int lk   = (lane >> 4) * 8;

    for (int c = 0; c < NCH; c++) {
        asm volatile("cp.async.wait_group 0;" ::: "memory");
        __syncthreads();
        if (c + 1 < NCH) load_stage((c + 1) & 1, (c + 1) * KC);

        const uint32_t st = sb + (c & 1) * STAGE_B;
        const uint32_t aAh = st, aAl = st + TILE_B, aBh = st + 2*TILE_B, aBl = st + 3*TILE_B;

        #pragma unroll
        for (int kk = 0; kk < 2; kk++) {
            const int kb = (kk * 16 + lk) * 2;
            uint32_t ah[4][4], al[4][4];
            #pragma unroll
            for (int mi = 0; mi < 4; mi++) {
                uint32_t off = (wm + mi*16 + lrow) * ROWB + kb;
                ldsm4(ah[mi], aAh + off);
                ldsm4(al[mi], aAl + off);
            }
            uint32_t bh[2][4], bl[2][4];
            #pragma unroll
            for (int nj = 0; nj < 2; nj++) {
                uint32_t off = (wn + nj*16 + lrow) * ROWB + kb;
                ldsm4(bh[nj], aBh + off);
                ldsm4(bl[nj], aBl + off);
            }
            #pragma unroll
            for (int mi = 0; mi < 4; mi++)
                #pragma unroll
                for (int ni = 0; ni < 4; ni++) {
                    const int nj = ni >> 1, ns = ni & 1;
                    mma16816(acc[mi][ni], ah[mi], bh[nj][ns], bh[nj][ns+2]);
                    mma16816(acc[mi][ni], ah[mi], bl[nj][ns], bl[nj][ns+2]);
                    mma16816(acc[mi][ni], al[mi], bh[nj][ns], bh[nj][ns+2]);
                }
        }
    }

    const int rr = lane >> 2;
    const int cp = (lane & 3) * 2;
    #pragma unroll
    for (int mi = 0; mi < 4; mi++) {
        #pragma unroll
        for (int half = 0; half < 2; half++) {
            int m = m0 + wm + mi*16 + rr + half*8;
            int s = m & (S_ - 1);
            #pragma unroll
            for (int ni = 0; ni < 4; ni++) {
                float e = acc[mi][ni][half*2 + 0];
                float o = acc[mi][ni][half*2 + 1];
                int n = n0 + wn + ni*8 + cp;
                if (MODE == 1 || MODE == 3) {
                    if (MODE == 1) {
                        int pair = (n & (HD_ - 1)) >> 1;
                        float cc = g_cos[s * F_ + pair], ss = g_sin[s * F_ + pair];
                        float xe = e, xo = o;
                        e = xe * cc - xo * ss;
                        o = xo * cc + xe * ss;
                    }
                    int br = m >> 11, h = n >> 7, hd = n & (HD_ - 1);
                    size_t ei = (((size_t)(br * H_ + h)) * S_ + s) * HD_ + hd;
                    __nv_bfloat16 eh = __float2bfloat16(e);
                    __nv_bfloat16 oh = __float2bfloat16(o);
                    __nv_bfloat16 el = __float2bfloat16(e - __bfloat162float(eh));
                    __nv_bfloat16 ol = __float2bfloat16(o - __bfloat162float(oh));
                    ((__nv_bfloat162*)outhi)[ei >> 1] = __halves2bfloat162(eh, oh);
                    ((__nv_bfloat162*)outlo)[ei >> 1] = __halves2bfloat162(el, ol);
                } else {
                    *(float2*)(outp + (size_t)m * D_ + n) = make_float2(e, o);
                }
            }
        }
    }
}

// ---------------- flash attention: HMMA QK^T + HMMA PV (P in registers) ----------------
// CTA: 128 q-rows (8 warps x m16), K-tile 64, 256 threads.
#define AT_SQH 0                        // Q hi: 128 x 272B
#define AT_SQL 34816                    // Q lo
#define AT_SKH(b) (69632  + (b)*17408)  // K hi x2: 64 x 272B
#define AT_SKL(b) (104448 + (b)*17408)  // K lo x2
#define AT_SVH 139264                   // V hi: 64 x 272B
#define AT_SVL 156672                   // V lo
#define A_SMEM 174080

__global__ __launch_bounds__(256, 1) void attn_mma()
{
    extern __shared__ char smc[];
    const uint32_t sb = smem_u32(smc);

    const int tid = threadIdx.x;
    const int lane = tid & 31;
    const int wq = tid >> 5;
    const int qt = (int)gridDim.x - 1 - (int)blockIdx.x;   // heavy CTAs first
    const int bh = blockIdx.y;
    const size_t base = (size_t)bh * S_ * HD_;
    const float qscale = 0.08838834764831845f;  // 1/sqrt(128)

    // ---- preload Q (group), K[0] (group) ----
    #pragma unroll
    for (int t = 0; t < 8; t++) {
        int idx = t * 256 + tid;
        int row = idx >> 4, ch = idx & 15;
        size_t go = base + (size_t)(qt * 128 + row) * HD_ + ch * 8;
        cp16(sb + AT_SQH + row * 272 + ch * 16, g_qhi + go);
        cp16(sb + AT_SQL + row * 272 + ch * 16, g_qlo + go);
    }
    CP_COMMIT();
    #pragma unroll
    for (int t = 0; t < 4; t++) {
        int idx = t * 256 + tid;
        int row = idx >> 4, ch = idx & 15;
        size_t go = base + (size_t)row * HD_ + ch * 8;
        cp16(sb + AT_SKH(0) + row * 272 + ch * 16, g_khi + go);
        cp16(sb + AT_SKL(0) + row * 272 + ch * 16, g_klo + go);
    }
    CP_COMMIT();

    // acc[t8][e]: 16 n8-tiles over hd (warp rows wq*16..+16)
    float acc[16][4];
    #pragma unroll
    for (int t8 = 0; t8 < 16; t8++)
        #pragma unroll
        for (int e = 0; e < 4; e++) acc[t8][e] = 0.f;
    float m_run[2] = {-1e30f, -1e30f};
    float l_run[2] = {0.f, 0.f};

    const int r0 = wq * 16 + (lane >> 2);
    const int nkt = 2 * qt + 2;
    const int lrow = lane & 15;
    const int lk = (lane >> 4) * 8;

    for (int kt = 0; kt < nkt; kt++) {
        const int kbuf = kt & 1;
        asm volatile("cp.async.wait_group 0;" ::: "memory");
        __syncthreads();

        // issue V[kt] (group), then prefetch K[kt+1] (group)
        #pragma unroll
        for (int t = 0; t < 4; t++) {
            int idx = t * 256 + tid;
            int row = idx >> 4, ch = idx & 15;
            size_t go = base + (size_t)(kt * 64 + row) * HD_ + ch * 8;
            cp16(sb + AT_SVH + row * 272 + ch * 16, g_vhi + go);
            cp16(sb + AT_SVL + row * 272 + ch * 16, g_vlo + go);
        }
        CP_COMMIT();
        const bool pk = (kt + 1) < nkt;
        if (pk) {
            #pragma unroll
            for (int t = 0; t < 4; t++) {
                int idx = t * 256 + tid;
                int row = idx >> 4, ch = idx & 15;
                size_t go = base + (size_t)((kt + 1) * 64 + row) * HD_ + ch * 8;
                cp16(sb + AT_SKH(kbuf ^ 1) + row * 272 + ch * 16, g_khi + go);
                cp16(sb + AT_SKL(kbuf ^ 1) + row * 272 + ch * 16, g_klo + go);
            }
            CP_COMMIT();
        }

        // ---- QK^T (3-term) ----
        float sacc[8][4];
        #pragma unroll
        for (int ni = 0; ni < 8; ni++)
            #pragma unroll
            for (int e = 0; e < 4; e++) sacc[ni][e] = 0.f;

        #pragma unroll
        for (int kk = 0; kk < 8; kk++) {
            const int kb = (kk * 16 + lk) * 2;
            uint32_t ah[4], al[4];
            ldsm4(ah, sb + AT_SQH + (wq * 16 + lrow) * 272 + kb);
            ldsm4(al, sb + AT_SQL + (wq * 16 + lrow) * 272 + kb);
            uint32_t bh4[4][4], bl4[4][4];
            #pragma unroll
            for (int nj = 0; nj < 4; nj++) {
                ldsm4(bh4[nj], sb + AT_SKH(kbuf) + (nj * 16 + lrow) * 272 + kb);
                ldsm4(bl4[nj], sb + AT_SKL(kbuf) + (nj * 16 + lrow) * 272 + kb);
            }
            #pragma unroll
            for (int ni = 0; ni < 8; ni++) {
                const int nj = ni >> 1, ns = ni & 1;
                mma16816(sacc[ni], ah, bh4[nj][ns], bh4[nj][ns+2]);
                mma16816(sacc[ni], ah, bl4[nj][ns], bl4[nj][ns+2]);
                mma16816(sacc[ni], al, bh4[nj][ns], bh4[nj][ns+2]);
            }
        }

        // ---- softmax; pack P into bf16 hi/lo A-fragments (registers) ----
        uint32_t phi[8][2], plo[8][2];   // [ni][h2]
        #pragma unroll
        for (int h2 = 0; h2 < 2; h2++) {
            const int qg = qt * 128 + r0 + h2 * 8;
            float v[16];
            float mloc = -1e30f;
            #pragma unroll
            for (int ni = 0; ni < 8; ni++)
                #pragma unroll
                for (int e = 0; e < 2; e++) {
                    float s = sacc[ni][h2*2 + e] * qscale;
                    int kg = kt * 64 + ni * 8 + (lane & 3) * 2 + e;
                    if (kg > qg) s = -1e30f;
                    v[ni*2 + e] = s;
                    mloc = fmaxf(mloc, s);
                }
            mloc = fmaxf(mloc, __shfl_xor_sync(0xffffffffu, mloc, 1));
            mloc = fmaxf(mloc, __shfl_xor_sync(0xffffffffu, mloc, 2));
            float mnew = fmaxf(m_run[h2], mloc);
            float corr = __expf(m_run[h2] - mnew);
            float rsum = 0.f;
            #pragma unroll
            for (int ni = 0; ni < 8; ni++) {
                float p0 = __expf(v[ni*2 + 0] - mnew);
                float p1 = __expf(v[ni*2 + 1] - mnew);
                rsum += p0 + p1;
                __nv_bfloat16 h0 = __float2bfloat16(p0);
                __nv_bfloat16 h1 = __float2bfloat16(p1);
                float l0 = p0 - __bfloat162float(h0);
                float l1 = p1 - __bfloat162float(h1);
                __nv_bfloat162 ph = __halves2bfloat162(h0, h1);
                phi[ni][h2] = *reinterpret_cast<uint32_t*>(&ph);
                plo[ni][h2] = pack_bf16x2(l0, l1);
            }
            rsum += __shfl_xor_sync(0xffffffffu, rsum, 1);
            rsum += __shfl_xor_sync(0xffffffffu, rsum, 2);
            l_run[h2] = l_run[h2] * corr + rsum;
            m_run[h2] = mnew;
            // rescale accumulator rows for this h2 (c0,c1 <-> h2=0; c2,c3 <-> h2=1)
            #pragma unroll
            for (int t8 = 0; t8 < 16; t8++) {
                acc[t8][h2*2 + 0] *= corr;
                acc[t8][h2*2 + 1] *= corr;
            }
        }

        // wait for V[kt] (leave K[kt+1] in flight)
        if (pk) { asm volatile("cp.async.wait_group 1;" ::: "memory"); }
        else    { asm volatile("cp.async.wait_group 0;" ::: "memory"); }
        __syncthreads();

        // ---- PV (3-term HMMA): A = P fragments from registers, B = V via ldsm.trans ----
        #pragma unroll
        for (int kk = 0; kk < 4; kk++) {
            uint32_t aH[4] = { phi[2*kk][0], phi[2*kk][1], phi[2*kk+1][0], phi[2*kk+1][1] };
            uint32_t aL[4] = { plo[2*kk][0], plo[2*kk][1], plo[2*kk+1][0], plo[2*kk+1][1] };
            // trans-ldsm address: row = kk*16 + (lane&15), colb = (ng*16 + (lane>>4)*8)*2
            #pragma unroll
            for (int ng = 0; ng < 8; ng++) {
                uint32_t off = (kk * 16 + lrow) * 272 + (ng * 16 + lk) * 2;
                uint32_t vh[4], vl[4];
                ldsm4t(vh, sb + AT_SVH + off);
                ldsm4t(vl, sb + AT_SVL + off);
                const int ta = 2*ng, tb = 2*ng + 1;
                mma16816(acc[ta], aH, vh[0], vh[1]);
                mma16816(acc[ta], aL, vh[0], vh[1]);
                mma16816(acc[ta], aH, vl[0], vl[1]);
                mma16816(acc[tb], aH, vh[2], vh[3]);
                mma16816(acc[tb], aL, vh[2], vh[3]);
                mma16816(acc[tb], aH, vl[2], vl[3]);
            }
        }
        __syncthreads();
    }

    // ---- finalize: normalize and store ----
    const int b = bh >> 4;
    const int h = bh & 15;
    #pragma unroll
    for (int h2 = 0; h2 < 2; h2++) {
        float inv = 1.0f / l_run[h2];
        int sg = qt * 128 + r0 + h2 * 8;
        float* p = g_ao + ((size_t)(b * S_ + sg)) * D_ + h * HD_;
        #pragma unroll
        for (int t8 = 0; t8 < 16; t8++) {
            int col = t8 * 8 + (lane & 3) * 2;
            *(float2*)(p + col) = make_float2(acc[t8][h2*2 + 0] * inv,
                                              acc[t8][h2*2 + 1] * inv);
        }
    }
}

extern "C" void kernel_launch(void* const* d_in, const int* in_sizes, int n_in,
                              void* d_out, int out_size) {
    (void)in_sizes; (void)n_in; (void)out_size;
    const float* x  = (const float*)d_in[0];
    const float* Wq = (const float*)d_in[1];
    const float* Wk = (const float*)d_in[2];
    const float* Wv = (const float*)d_in[3];
    const float* Wo = (const float*)d_in[4];
    float* out = (float*)d_out;

    float *ao;
    __nv_bfloat16 *xhi, *xlo, *whi, *wlo, *qhi, *qlo, *khi, *klo, *vhi, *vlo;
    cudaGetSymbolAddress((void**)&ao,  g_ao);
    cudaGetSymbolAddress((void**)&xhi, g_xhi);
    cudaGetSymbolAddress((void**)&xlo, g_xlo);
    cudaGetSymbolAddress((void**)&whi, g_whi);
    cudaGetSymbolAddress((void**)&wlo, g_wlo);
    cudaGetSymbolAddress((void**)&qhi, g_qhi);
    cudaGetSymbolAddress((void**)&qlo, g_qlo);
    cudaGetSymbolAddress((void**)&khi, g_khi);
    cudaGetSymbolAddress((void**)&klo, g_klo);
    cudaGetSymbolAddress((void**)&vhi, g_vhi);
    cudaGetSymbolAddress((void**)&vlo, g_vlo);

    const size_t DD = (size_t)D_ * D_;

    cudaFuncSetAttribute(gemm_tc<0>, cudaFuncAttributeMaxDynamicSharedMemorySize, GT_SMEM);
    cudaFuncSetAttribute(gemm_tc<1>, cudaFuncAttributeMaxDynamicSharedMemorySize, GT_SMEM);
    cudaFuncSetAttribute(gemm_tc<3>, cudaFuncAttributeMaxDynamicSharedMemorySize, GT_SMEM);
    cudaFuncSetAttribute(attn_mma, cudaFuncAttributeMaxDynamicSharedMemorySize, A_SMEM);

    dim3 tgrid(D_/128, M_/128);   // (16, 32)

    // launch order: Q-GEMM split across slots 4-6 so ncu (-s 5 -c 1) captures a gemm
    rope_table_kernel<<<(S_*F_ + 255)/256, 256>>>();                                   // 1
    conv_kernel<<<(M_*D_/4 + 255)/256, 256>>>(x,  xhi, xlo, M_*D_/4);                  // 2
    conv_kernel<<<(D_*D_/4 + 255)/256, 256>>>(Wq, whi + 0*DD, wlo + 0*DD, D_*D_/4);    // 3
    gemm_tc<1><<<dim3(16,11), 256, GT_SMEM>>>(xhi, xlo, whi, wlo, nullptr, qhi, qlo, 0);   // 4
    gemm_tc<1><<<dim3(16,11), 256, GT_SMEM>>>(xhi, xlo, whi, wlo, nullptr, qhi, qlo, 11);  // 5
    gemm_tc<1><<<dim3(16,10), 256, GT_SMEM>>>(xhi, xlo, whi, wlo, nullptr, qhi, qlo, 22);  // 6
    conv_kernel<<<(D_*D_/4 + 255)/256, 256>>>(Wk, whi + 1*DD, wlo + 1*DD, D_*D_/4);    // 7
    gemm_tc<1><<<tgrid, 256, GT_SMEM>>>(xhi, xlo, whi + 1*DD, wlo + 1*DD, nullptr, khi, klo, 0);
    conv_kernel<<<(D_*D_/4 + 255)/256, 256>>>(Wv, whi + 2*DD, wlo + 2*DD, D_*D_/4);
    gemm_tc<3><<<tgrid, 256, GT_SMEM>>>(xhi, xlo, whi + 2*DD, wlo + 2*DD, nullptr, vhi, vlo, 0);
    conv_kernel<<<(D_*D_/4 + 255)/256, 256>>>(Wo, whi + 3*DD, wlo + 3*DD, D_*D_/4);

    attn_mma<<<dim3(S_/128, B_*H_), 256, A_SMEM>>>();

    conv_kernel<<<(M_*D_/4 + 255)/256, 256>>>(ao, xhi, xlo, M_*D_/4);
    gemm_tc<0><<<tgrid, 256, GT_SMEM>>>(xhi, xlo, whi + 3*DD, wlo + 3*DD, out, nullptr, nullptr, 0);
}

// round 9
// speedup vs baseline: 2.4036x; 1.1239x over previous
#include <cuda_runtime.h>
#include <cuda_bf16.h>
#include <math.h>
#include <stdint.h>

#define B_  2
#define S_  2048
#define D_  2048
#define H_  16
#define HD_ 128
#define M_  (B_*S_)      // 4096
#define F_  (HD_/2)      // 64

// ---------------- scratch (alloc-free rule: __device__ globals) ----------------
__device__ float g_cos[S_*F_];
__device__ float g_sin[S_*F_];

__device__ __nv_bfloat16 g_qhi[B_*H_*S_*HD_];
__device__ __nv_bfloat16 g_qlo[B_*H_*S_*HD_];
__device__ __nv_bfloat16 g_khi[B_*H_*S_*HD_];
__device__ __nv_bfloat16 g_klo[B_*H_*S_*HD_];
__device__ __nv_bfloat16 g_vhi[B_*H_*S_*HD_];
__device__ __nv_bfloat16 g_vlo[B_*H_*S_*HD_];

__device__ __nv_bfloat16 g_xhi[M_*D_];   // x split; reused as attn-out split
__device__ __nv_bfloat16 g_xlo[M_*D_];
__device__ __nv_bfloat16 g_whi[4*D_*D_];
__device__ __nv_bfloat16 g_wlo[4*D_*D_];

// ---------------- PTX helpers (plain sm_100 target: no tcgen05) ----------------
__device__ __forceinline__ uint32_t smem_u32(const void* p) {
    uint32_t a;
    asm("{ .reg .u64 t; cvta.to.shared.u64 t, %1; cvt.u32.u64 %0, t; }" : "=r"(a) : "l"(p));
    return a;
}
__device__ __forceinline__ void cp16(uint32_t s, const void* g) {
    asm volatile("cp.async.cg.shared.global [%0], [%1], 16;" :: "r"(s), "l"(g));
}
#define CP_COMMIT() asm volatile("cp.async.commit_group;")

__device__ __forceinline__ void ldsm4(uint32_t* r, uint32_t addr) {
    asm volatile("ldmatrix.sync.aligned.m8n8.x4.shared.b16 {%0,%1,%2,%3}, [%4];"
        : "=r"(r[0]), "=r"(r[1]), "=r"(r[2]), "=r"(r[3]) : "r"(addr));
}
__device__ __forceinline__ void ldsm4t(uint32_t* r, uint32_t addr) {
    asm volatile("ldmatrix.sync.aligned.m8n8.x4.trans.shared.b16 {%0,%1,%2,%3}, [%4];"
        : "=r"(r[0]), "=r"(r[1]), "=r"(r[2]), "=r"(r[3]) : "r"(addr));
}
__device__ __forceinline__ void mma16816(float* d, const uint32_t* a, uint32_t b0, uint32_t b1) {
    asm volatile(
        "mma.sync.aligned.m16n8k16.row.col.f32.bf16.bf16.f32 "
        "{%0,%1,%2,%3}, {%4,%5,%6,%7}, {%8,%9}, {%0,%1,%2,%3};"
        : "+f"(d[0]), "+f"(d[1]), "+f"(d[2]), "+f"(d[3])
        : "r"(a[0]), "r"(a[1]), "r"(a[2]), "r"(a[3]), "r"(b0), "r"(b1));
}
__device__ __forceinline__ uint32_t pack_bf16x2(float a, float b) {
    __nv_bfloat162 t = __halves2bfloat162(__float2bfloat16(a), __float2bfloat16(b));
    return *reinterpret_cast<uint32_t*>(&t);
}

// ---------------- RoPE table ----------------
__global__ void rope_table_kernel() {
    int idx = blockIdx.x * blockDim.x + threadIdx.x;
    if (idx >= S_ * F_) return;
    int s = idx >> 6;
    int i = idx & 63;
    double invf = pow(10000.0, -(double)i / 64.0);
    double f = (double)s * invf;
    double sn, cs;
    sincos(f, &sn, &cs);
    g_cos[idx] = (float)cs;
    g_sin[idx] = (float)sn;
}

// ---------------- fp32 -> bf16 hi/lo split ----------------
__global__ void conv_kernel(const float* __restrict__ in,
                            __nv_bfloat16* __restrict__ hi,
                            __nv_bfloat16* __restrict__ lo, int n4) {
    int i = blockIdx.x * blockDim.x + threadIdx.x;
    if (i >= n4) return;
    float4 v = ((const float4*)in)[i];
    float xs[4] = {v.x, v.y, v.z, v.w};
    __nv_bfloat16 h[4], l[4];
    #pragma unroll
    for (int j = 0; j < 4; j++) {
        h[j] = __float2bfloat16(xs[j]);
        l[j] = __float2bfloat16(xs[j] - __bfloat162float(h[j]));
    }
    __nv_bfloat162* hp = (__nv_bfloat162*)hi;
    __nv_bfloat162* lp = (__nv_bfloat162*)lo;
    hp[2*i]   = __halves2bfloat162(h[0], h[1]);
    hp[2*i+1] = __halves2bfloat162(h[2], h[3]);
    lp[2*i]   = __halves2bfloat162(l[0], l[1]);
    lp[2*i+1] = __halves2bfloat162(l[2], l[3]);
}

// ---------------- mma.sync bf16 GEMM: C[m,n] = sum_k A[m,k]*B[n,k] ----------------
// MODE 0: out fp32 row-major [M,2048]
// MODE 1: RoPE, out bf16 hi/lo [B,H,S,HD]
// MODE 3: no RoPE, out bf16 hi/lo [B,H,S,HD]
#define KC 32
#define ROWB 80
#define TILE_B (128*ROWB)
#define STAGE_B (4*TILE_B)
#define GT_SMEM (2*STAGE_B)          // 81920

template <int MODE>
__global__ __launch_bounds__(256, 2) void gemm_tc(
    const __nv_bfloat16* __restrict__ Ahi, const __nv_bfloat16* __restrict__ Alo,
    const __nv_bfloat16* __restrict__ Bhi, const __nv_bfloat16* __restrict__ Blo,
    float* __restrict__ outp,
    __nv_bfloat16* __restrict__ outhi, __nv_bfloat16* __restrict__ outlo)
{
    extern __shared__ char smc[];
    const uint32_t sb = smem_u32(smc);
    const int tid = threadIdx.x;
    const int lane = tid & 31;
    const int wid = tid >> 5;
    const int wm = (wid >> 2) * 64;
    const int wn = (wid & 3) * 32;
    const int m0 = blockIdx.y * 128;
    const int n0 = blockIdx.x * 128;

    auto load_stage = [&](int stg, int k0) {
        uint32_t base = sb + stg * STAGE_B;
        #pragma unroll
        for (int t = 0; t < 2; t++) {
            int idx = t * 256 + tid;
            int row = idx >> 2, seg = idx & 3;
            uint32_t so = row * ROWB + seg * 16;
            size_t goA = (size_t)(m0 + row) * D_ + k0 + seg * 8;
            size_t goB = (size_t)(n0 + row) * D_ + k0 + seg * 8;
            cp16(base + 0*TILE_B + so, Ahi + goA);
            cp16(base + 1*TILE_B + so, Alo + goA);
            cp16(base + 2*TILE_B + so, Bhi + goB);
            cp16(base + 3*TILE_B + so, Blo + goB);
        }
        CP_COMMIT();
    };

    float acc[4][4][4];
    #pragma unroll
    for (int mi = 0; mi < 4; mi++)
        #pragma unroll
        for (int ni = 0; ni < 4; ni++)
            #pragma unroll
            for (int e = 0; e < 4; e++) acc[mi][ni][e] = 0.f;

    load_stage(0, 0);

    const int NCH = 2048 / KC;
    const int lrow = lane & 15;
    const int lk   = (lane >> 4) * 8;

    for (int c = 0; c < NCH; c++) {
        asm volatile("cp.async.wait_group 0;" ::: "memory");
        __syncthreads();
        if (c + 1 < NCH) load_stage((c + 1) & 1, (c + 1) * KC);

        const uint32_t st = sb + (c & 1) * STAGE_B;
        const uint32_t aAh = st, aAl = st + TILE_B, aBh = st + 2*TILE_B, aBl = st + 3*TILE_B;

        #pragma unroll
        for (int kk = 0; kk < 2; kk++) {
            const int kb = (kk * 16 + lk) * 2;
            uint32_t ah[4][4], al[4][4];
            #pragma unroll
            for (int mi = 0; mi < 4; mi++) {
                uint32_t off = (wm + mi*16 + lrow) * ROWB + kb;
                ldsm4(ah[mi], aAh + off);
                ldsm4(al[mi], aAl + off);
            }
            uint32_t bh[2][4], bl[2][4];
            #pragma unroll
            for (int nj = 0; nj < 2; nj++) {
                uint32_t off = (wn + nj*16 + lrow) * ROWB + kb;
                ldsm4(bh[nj], aBh + off);
                ldsm4(bl[nj], aBl + off);
            }
            // term-major: 16 independent accumulators between reuse of any acc
            #pragma unroll
            for (int t = 0; t < 3; t++)
                #pragma unroll
                for (int mi = 0; mi < 4; mi++)
                    #pragma unroll
                    for (int ni = 0; ni < 4; ni++) {
                        const int nj = ni >> 1, ns = ni & 1;
                        const uint32_t* a = (t == 2) ? al[mi] : ah[mi];
                        const uint32_t* b = (t == 1) ? bl[nj] : bh[nj];
                        mma16816(acc[mi][ni], a, b[ns], b[ns+2]);
                    }
        }
    }

    const int rr = lane >> 2;
    const int cp = (lane & 3) * 2;
    #pragma unroll
    for (int mi = 0; mi < 4; mi++) {
        #pragma unroll
        for (int half = 0; half < 2; half++) {
            int m = m0 + wm + mi*16 + rr + half*8;
            int s = m & (S_ - 1);
            #pragma unroll
            for (int ni = 0; ni < 4; ni++) {
                float e = acc[mi][ni][half*2 + 0];
                float o = acc[mi][ni][half*2 + 1];
                int n = n0 + wn + ni*8 + cp;
                if (MODE == 1 || MODE == 3) {
                    if (MODE == 1) {
                        int pair = (n & (HD_ - 1)) >> 1;
                        float cc = g_cos[s * F_ + pair], ss = g_sin[s * F_ + pair];
                        float xe = e, xo = o;
                        e = xe * cc - xo * ss;
                        o = xo * cc + xe * ss;
                    }
                    int br = m >> 11, h = n >> 7, hd = n & (HD_ - 1);
                    size_t ei = (((size_t)(br * H_ + h)) * S_ + s) * HD_ + hd;
                    __nv_bfloat16 eh = __float2bfloat16(e);
                    __nv_bfloat16 oh = __float2bfloat16(o);
                    __nv_bfloat16 el = __float2bfloat16(e - __bfloat162float(eh));
                    __nv_bfloat16 ol = __float2bfloat16(o - __bfloat162float(oh));
                    ((__nv_bfloat162*)outhi)[ei >> 1] = __halves2bfloat162(eh, oh);
                    ((__nv_bfloat162*)outlo)[ei >> 1] = __halves2bfloat162(el, ol);
                } else {
                    *(float2*)(outp + (size_t)m * D_ + n) = make_float2(e, o);
                }
            }
        }
    }
}

// ---------------- flash attention: HMMA QK^T + HMMA PV (P in registers) ----------------
// CTA: 128 q-rows (8 warps x m16), K-tile 64, 256 threads.
// Epilogue writes bf16 hi/lo split directly (feeds final GEMM).
#define AT_SQH 0                        // Q hi: 128 x 272B
#define AT_SQL 34816                    // Q lo
#define AT_SKH(b) (69632  + (b)*17408)  // K hi x2: 64 x 272B
#define AT_SKL(b) (104448 + (b)*17408)  // K lo x2
#define AT_SVH 139264                   // V hi: 64 x 272B
#define AT_SVL 156672                   // V lo
#define A_SMEM 174080

__global__ __launch_bounds__(256, 1) void attn_mma(
    __nv_bfloat16* __restrict__ outhi, __nv_bfloat16* __restrict__ outlo)
{
    extern __shared__ char smc[];
    const uint32_t sb = smem_u32(smc);

    const int tid = threadIdx.x;
    const int lane = tid & 31;
    const int wq = tid >> 5;
    const int qt = (int)gridDim.x - 1 - (int)blockIdx.x;   // heavy CTAs first
    const int bh = blockIdx.y;
    const size_t base = (size_t)bh * S_ * HD_;
    const float qscale = 0.08838834764831845f;  // 1/sqrt(128)

    // ---- preload Q (group), K[0] (group) ----
    #pragma unroll
    for (int t = 0; t < 8; t++) {
        int idx = t * 256 + tid;
        int row = idx >> 4, ch = idx & 15;
        size_t go = base + (size_t)(qt * 128 + row) * HD_ + ch * 8;
        cp16(sb + AT_SQH + row * 272 + ch * 16, g_qhi + go);
        cp16(sb + AT_SQL + row * 272 + ch * 16, g_qlo + go);
    }
    CP_COMMIT();
    #pragma unroll
    for (int t = 0; t < 4; t++) {
        int idx = t * 256 + tid;
        int row = idx >> 4, ch = idx & 15;
        size_t go = base + (size_t)row * HD_ + ch * 8;
        cp16(sb + AT_SKH(0) + row * 272 + ch * 16, g_khi + go);
        cp16(sb + AT_SKL(0) + row * 272 + ch * 16, g_klo + go);
    }
    CP_COMMIT();

    float acc[16][4];
    #pragma unroll
    for (int t8 = 0; t8 < 16; t8++)
        #pragma unroll
        for (int e = 0; e < 4; e++) acc[t8][e] = 0.f;
    float m_run[2] = {-1e30f, -1e30f};
    float l_run[2] = {0.f, 0.f};

    const int r0 = wq * 16 + (lane >> 2);
    const int nkt = 2 * qt + 2;
    const int lrow = lane & 15;
    const int lk = (lane >> 4) * 8;

    for (int kt = 0; kt < nkt; kt++) {
        const int kbuf = kt & 1;
        asm volatile("cp.async.wait_group 0;" ::: "memory");
        __syncthreads();

        // issue V[kt] (group), then prefetch K[kt+1] (group)
        #pragma unroll
        for (int t = 0; t < 4; t++) {
            int idx = t * 256 + tid;
            int row = idx >> 4, ch = idx & 15;
            size_t go = base + (size_t)(kt * 64 + row) * HD_ + ch * 8;
            cp16(sb + AT_SVH + row * 272 + ch * 16, g_vhi + go);
            cp16(sb + AT_SVL + row * 272 + ch * 16, g_vlo + go);
        }
        CP_COMMIT();
        const bool pk = (kt + 1) < nkt;
        if (pk) {
            #pragma unroll
            for (int t = 0; t < 4; t++) {
                int idx = t * 256 + tid;
                int row = idx >> 4, ch = idx & 15;
                size_t go = base + (size_t)((kt + 1) * 64 + row) * HD_ + ch * 8;
                cp16(sb + AT_SKH(kbuf ^ 1) + row * 272 + ch * 16, g_khi + go);
                cp16(sb + AT_SKL(kbuf ^ 1) + row * 272 + ch * 16, g_klo + go);
            }
            CP_COMMIT();
        }

        // ---- QK^T (3-term, term-major) ----
        float sacc[8][4];
        #pragma unroll
        for (int ni = 0; ni < 8; ni++)
            #pragma unroll
            for (int e = 0; e < 4; e++) sacc[ni][e] = 0.f;

        #pragma unroll
        for (int kk = 0; kk < 8; kk++) {
            const int kb = (kk * 16 + lk) * 2;
            uint32_t ah[4], al[4];
            ldsm4(ah, sb + AT_SQH + (wq * 16 + lrow) * 272 + kb);
            ldsm4(al, sb + AT_SQL + (wq * 16 + lrow) * 272 + kb);
            uint32_t bh4[4][4], bl4[4][4];
            #pragma unroll
            for (int nj = 0; nj < 4; nj++) {
                ldsm4(bh4[nj], sb + AT_SKH(kbuf) + (nj * 16 + lrow) * 272 + kb);
                ldsm4(bl4[nj], sb + AT_SKL(kbuf) + (nj * 16 + lrow) * 272 + kb);
            }
            #pragma unroll
            for (int t = 0; t < 3; t++)
                #pragma unroll
                for (int ni = 0; ni < 8; ni++) {
                    const int nj = ni >> 1, ns = ni & 1;
                    const uint32_t* a = (t == 2) ? al : ah;
                    const uint32_t* b = (t == 1) ? bl4[nj] : bh4[nj];
                    mma16816(sacc[ni], a, b[ns], b[ns+2]);
                }
        }

        // ---- softmax; pack P into bf16 hi/lo A-fragments (registers) ----
        uint32_t phi[8][2], plo[8][2];
        #pragma unroll
        for (int h2 = 0; h2 < 2; h2++) {
            const int qg = qt * 128 + r0 + h2 * 8;
            float v[16];
            float mloc = -1e30f;
            #pragma unroll
            for (int ni = 0; ni < 8; ni++)
                #pragma unroll
                for (int e = 0; e < 2; e++) {
                    float s = sacc[ni][h2*2 + e] * qscale;
                    int kg = kt * 64 + ni * 8 + (lane & 3) * 2 + e;
                    if (kg > qg) s = -1e30f;
                    v[ni*2 + e] = s;
                    mloc = fmaxf(mloc, s);
                }
            mloc = fmaxf(mloc, __shfl_xor_sync(0xffffffffu, mloc, 1));
            mloc = fmaxf(mloc, __shfl_xor_sync(0xffffffffu, mloc, 2));
            float mnew = fmaxf(m_run[h2], mloc);
            float corr = __expf(m_run[h2] - mnew);
            float rsum = 0.f;
            #pragma unroll
            for (int ni = 0; ni < 8; ni++) {
                float p0 = __expf(v[ni*2 + 0] - mnew);
                float p1 = __expf(v[ni*2 + 1] - mnew);
                rsum += p0 + p1;
                __nv_bfloat16 h0 = __float2bfloat16(p0);
                __nv_bfloat16 h1 = __float2bfloat16(p1);
                float l0 = p0 - __bfloat162float(h0);
                float l1 = p1 - __bfloat162float(h1);
                __nv_bfloat162 ph = __halves2bfloat162(h0, h1);
                phi[ni][h2] = *reinterpret_cast<uint32_t*>(&ph);
                plo[ni][h2] = pack_bf16x2(l0, l1);
            }
            rsum += __shfl_xor_sync(0xffffffffu, rsum, 1);
            rsum += __shfl_xor_sync(0xffffffffu, rsum, 2);
            l_run[h2] = l_run[h2] * corr + rsum;
            m_run[h2] = mnew;
            #pragma unroll
            for (int t8 = 0; t8 < 16; t8++) {
                acc[t8][h2*2 + 0] *= corr;
                acc[t8][h2*2 + 1] *= corr;
            }
        }

        if (pk) { asm volatile("cp.async.wait_group 1;" ::: "memory"); }
        else    { asm volatile("cp.async.wait_group 0;" ::: "memory"); }
        __syncthreads();

        // ---- PV (3-term HMMA), ta/tb interleaved per term ----
        #pragma unroll
        for (int kk = 0; kk < 4; kk++) {
            uint32_t aH[4] = { phi[2*kk][0], phi[2*kk][1], phi[2*kk+1][0], phi[2*kk+1][1] };
            uint32_t aL[4] = { plo[2*kk][0], plo[2*kk][1], plo[2*kk+1][0], plo[2*kk+1][1] };
            #pragma unroll
            for (int ng = 0; ng < 8; ng++) {
                uint32_t off = (kk * 16 + lrow) * 272 + (ng * 16 + lk) * 2;
                uint32_t vh[4], vl[4];
                ldsm4t(vh, sb + AT_SVH + off);
                ldsm4t(vl, sb + AT_SVL + off);
                const int ta = 2*ng, tb = 2*ng + 1;
                mma16816(acc[ta], aH, vh[0], vh[1]);
                mma16816(acc[tb], aH, vh[2], vh[3]);
                mma16816(acc[ta], aL, vh[0], vh[1]);
                mma16816(acc[tb], aL, vh[2], vh[3]);
                mma16816(acc[ta], aH, vl[0], vl[1]);
                mma16816(acc[tb], aH, vl[2], vl[3]);
            }
        }
        __syncthreads();
    }

    // ---- finalize: normalize, split hi/lo, store to [b*s, h*HD+d] ----
    const int b = bh >> 4;
    const int h = bh & 15;
    #pragma unroll
    for (int h2 = 0; h2 < 2; h2++) {
        float inv = 1.0f / l_run[h2];
        int sg = qt * 128 + r0 + h2 * 8;
        size_t rowbase = ((size_t)(b * S_ + sg)) * D_ + h * HD_;
        #pragma unroll
        for (int t8 = 0; t8 < 16; t8++) {
            int col = t8 * 8 + (lane & 3) * 2;
            float e = acc[t8][h2*2 + 0] * inv;
            float o = acc[t8][h2*2 + 1] * inv;
            size_t ei = rowbase + col;
            __nv_bfloat16 eh = __float2bfloat16(e);
            __nv_bfloat16 oh = __float2bfloat16(o);
            __nv_bfloat16 el = __float2bfloat16(e - __bfloat162float(eh));
            __nv_bfloat16 ol = __float2bfloat16(o - __bfloat162float(oh));
            ((__nv_bfloat162*)outhi)[ei >> 1] = __halves2bfloat162(eh, oh);
            ((__nv_bfloat162*)outlo)[ei >> 1] = __halves2bfloat162(el, ol);
        }
    }
}

extern "C" void kernel_launch(void* const* d_in, const int* in_sizes, int n_in,
                              void* d_out, int out_size) {
    (void)in_sizes; (void)n_in; (void)out_size;
    const float* x  = (const float*)d_in[0];
    const float* Wq = (const float*)d_in[1];
    const float* Wk = (const float*)d_in[2];
    const float* Wv = (const float*)d_in[3];
    const float* Wo = (const float*)d_in[4];
    float* out = (float*)d_out;

    __nv_bfloat16 *xhi, *xlo, *whi, *wlo, *qhi, *qlo, *khi, *klo, *vhi, *vlo;
    cudaGetSymbolAddress((void**)&xhi, g_xhi);
    cudaGetSymbolAddress((void**)&xlo, g_xlo);
    cudaGetSymbolAddress((void**)&whi, g_whi);
    cudaGetSymbolAddress((void**)&wlo, g_wlo);
    cudaGetSymbolAddress((void**)&qhi, g_qhi);
    cudaGetSymbolAddress((void**)&qlo, g_qlo);
    cudaGetSymbolAddress((void**)&khi, g_khi);
    cudaGetSymbolAddress((void**)&klo, g_klo);
    cudaGetSymbolAddress((void**)&vhi, g_vhi);
    cudaGetSymbolAddress((void**)&vlo, g_vlo);

    const size_t DD = (size_t)D_ * D_;

    cudaFuncSetAttribute(gemm_tc<0>, cudaFuncAttributeMaxDynamicSharedMemorySize, GT_SMEM);
    cudaFuncSetAttribute(gemm_tc<1>, cudaFuncAttributeMaxDynamicSharedMemorySize, GT_SMEM);
    cudaFuncSetAttribute(gemm_tc<3>, cudaFuncAttributeMaxDynamicSharedMemorySize, GT_SMEM);
    cudaFuncSetAttribute(attn_mma, cudaFuncAttributeMaxDynamicSharedMemorySize, A_SMEM);

    dim3 tgrid(D_/128, M_/128);   // (16, 32)

    // launch order: slot 5 = full Q GEMM (harness offset 1 -> ncu global #6 hits it)
    rope_table_kernel<<<(S_*F_ + 255)/256, 256>>>();                                   // 1
    conv_kernel<<<(M_*D_/4 + 255)/256, 256>>>(x,  xhi, xlo, M_*D_/4);                  // 2
    conv_kernel<<<(D_*D_/4 + 255)/256, 256>>>(Wq, whi + 0*DD, wlo + 0*DD, D_*D_/4);    // 3
    conv_kernel<<<(D_*D_/4 + 255)/256, 256>>>(Wk, whi + 1*DD, wlo + 1*DD, D_*D_/4);    // 4
    gemm_tc<1><<<tgrid, 256, GT_SMEM>>>(xhi, xlo, whi + 0*DD, wlo + 0*DD, nullptr, qhi, qlo); // 5
    conv_kernel<<<(D_*D_/4 + 255)/256, 256>>>(Wv, whi + 2*DD, wlo + 2*DD, D_*D_/4);    // 6
    gemm_tc<1><<<tgrid, 256, GT_SMEM>>>(xhi, xlo, whi + 1*DD, wlo + 1*DD, nullptr, khi, klo);
    conv_kernel<<<(D_*D_/4 + 255)/256, 256>>>(Wo, whi + 3*DD, wlo + 3*DD, D_*D_/4);
    gemm_tc<3><<<tgrid, 256, GT_SMEM>>>(xhi, xlo, whi + 2*DD, wlo + 2*DD, nullptr, vhi, vlo);

    attn_mma<<<dim3(S_/128, B_*H_), 256, A_SMEM>>>(xhi, xlo);

    gemm_tc<0><<<tgrid, 256, GT_SMEM>>>(xhi, xlo, whi + 3*DD, wlo + 3*DD, out, nullptr, nullptr);
}

// round 11
// speedup vs baseline: 2.5376x; 1.0557x over previous
#include <cuda_runtime.h>
#include <cuda_bf16.h>
#include <math.h>
#include <stdint.h>

#define B_  2
#define S_  2048
#define D_  2048
#define H_  16
#define HD_ 128
#define M_  (B_*S_)      // 4096
#define F_  (HD_/2)      // 64

// ---------------- scratch (alloc-free rule: __device__ globals) ----------------
__device__ float g_cos[S_*F_];
__device__ float g_sin[S_*F_];

__device__ __nv_bfloat16 g_qhi[B_*H_*S_*HD_];
__device__ __nv_bfloat16 g_qlo[B_*H_*S_*HD_];
__device__ __nv_bfloat16 g_khi[B_*H_*S_*HD_];
__device__ __nv_bfloat16 g_klo[B_*H_*S_*HD_];
__device__ __nv_bfloat16 g_vhi[B_*H_*S_*HD_];
__device__ __nv_bfloat16 g_vlo[B_*H_*S_*HD_];

__device__ __nv_bfloat16 g_xhi[M_*D_];   // x split; reused as attn-out split
__device__ __nv_bfloat16 g_xlo[M_*D_];
__device__ __nv_bfloat16 g_whi[4*D_*D_];
__device__ __nv_bfloat16 g_wlo[4*D_*D_];

// ---------------- PTX helpers (plain sm_100 target: no tcgen05) ----------------
__device__ __forceinline__ uint32_t smem_u32(const void* p) {
    uint32_t a;
    asm("{ .reg .u64 t; cvta.to.shared.u64 t, %1; cvt.u32.u64 %0, t; }" : "=r"(a) : "l"(p));
    return a;
}
__device__ __forceinline__ void cp16(uint32_t s, const void* g) {
    asm volatile("cp.async.cg.shared.global [%0], [%1], 16;" :: "r"(s), "l"(g));
}
#define CP_COMMIT() asm volatile("cp.async.commit_group;")

__device__ __forceinline__ void ldsm4(uint32_t* r, uint32_t addr) {
    asm volatile("ldmatrix.sync.aligned.m8n8.x4.shared.b16 {%0,%1,%2,%3}, [%4];"
        : "=r"(r[0]), "=r"(r[1]), "=r"(r[2]), "=r"(r[3]) : "r"(addr));
}
__device__ __forceinline__ void ldsm4t(uint32_t* r, uint32_t addr) {
    asm volatile("ldmatrix.sync.aligned.m8n8.x4.trans.shared.b16 {%0,%1,%2,%3}, [%4];"
        : "=r"(r[0]), "=r"(r[1]), "=r"(r[2]), "=r"(r[3]) : "r"(addr));
}
__device__ __forceinline__ void mma16816(float* d, const uint32_t* a, uint32_t b0, uint32_t b1) {
    asm volatile(
        "mma.sync.aligned.m16n8k16.row.col.f32.bf16.bf16.f32 "
        "{%0,%1,%2,%3}, {%4,%5,%6,%7}, {%8,%9}, {%0,%1,%2,%3};"
        : "+f"(d[0]), "+f"(d[1]), "+f"(d[2]), "+f"(d[3])
        : "r"(a[0]), "r"(a[1]), "r"(a[2]), "r"(a[3]), "r"(b0), "r"(b1));
}
__device__ __forceinline__ uint32_t pack_bf16x2(float a, float b) {
    __nv_bfloat162 t = __halves2bfloat162(__float2bfloat16(a), __float2bfloat16(b));
    return *reinterpret_cast<uint32_t*>(&t);
}

// ---------------- RoPE table ----------------
__global__ void rope_table_kernel() {
    int idx = blockIdx.x * blockDim.x + threadIdx.x;
    if (idx >= S_ * F_) return;
    int s = idx >> 6;
    int i = idx & 63;
    double invf = pow(10000.0, -(double)i / 64.0);
    double f = (double)s * invf;
    double sn, cs;
    sincos(f, &sn, &cs);
    g_cos[idx] = (float)cs;
    g_sin[idx] = (float)sn;
}

// ---------------- fused fp32 -> bf16 hi/lo splits: x (2 segs) + 4 weights ----------------
// grid (4096, 6): y=0,1 -> x halves; y=2..5 -> Wq,Wk,Wv,Wo
__global__ void conv_fused(const float* __restrict__ x,
                           const float* __restrict__ Wq, const float* __restrict__ Wk,
                           const float* __restrict__ Wv, const float* __restrict__ Wo,
                           __nv_bfloat16* __restrict__ xhi, __nv_bfloat16* __restrict__ xlo,
                           __nv_bfloat16* __restrict__ whi, __nv_bfloat16* __restrict__ wlo)
{
    const int y = blockIdx.y;
    const int i = blockIdx.x * blockDim.x + threadIdx.x;   // [0, 1M) float4s
    const float* in;
    __nv_bfloat16 *hi, *lo;
    size_t off4;                                            // float4 offset into out
    const size_t SEG = (size_t)D_ * D_ / 4;                 // 1M float4s
    if (y < 2) {
        in = x + (size_t)y * SEG * 4;
        hi = xhi; lo = xlo;
        off4 = (size_t)y * SEG + i;
    } else {
        const float* ws[4] = {Wq, Wk, Wv, Wo};
        in = ws[y - 2];
        hi = whi; lo = wlo;
        off4 = (size_t)(y - 2) * SEG + i;
    }
    float4 v = ((const float4*)in)[i];
    float xs[4] = {v.x, v.y, v.z, v.w};
    __nv_bfloat16 h[4], l[4];
    #pragma unroll
    for (int j = 0; j < 4; j++) {
        h[j] = __float2bfloat16(xs[j]);
        l[j] = __float2bfloat16(xs[j] - __bfloat162float(h[j]));
    }
    __nv_bfloat162* hp = (__nv_bfloat162*)hi;
    __nv_bfloat162* lp = (__nv_bfloat162*)lo;
    hp[2*off4]   = __halves2bfloat162(h[0], h[1]);
    hp[2*off4+1] = __halves2bfloat162(h[2], h[3]);
    lp[2*off4]   = __halves2bfloat162(l[0], l[1]);
    lp[2*off4+1] = __halves2bfloat162(l[2], l[3]);
}

// ---------------- mma.sync bf16 GEMM machinery ----------------
#define KC 32
#define ROWB 80
#define TILE_B (128*ROWB)
#define STAGE_B (4*TILE_B)
#define GT_SMEM (2*STAGE_B)          // 81920

struct GemmCore {
    uint32_t sb;
    int tid, lane, wid, wm, wn, m0, n0;
    const __nv_bfloat16 *Ahi, *Alo, *Bhi, *Blo;

    __device__ __forceinline__ void load_stage(int stg, int k0) {
        uint32_t base = sb + stg * STAGE_B;
        #pragma unroll
        for (int t = 0; t < 2; t++) {
            int idx = t * 256 + tid;
            int row = idx >> 2, seg = idx & 3;
            uint32_t so = row * ROWB + seg * 16;
            size_t goA = (size_t)(m0 + row) * D_ + k0 + seg * 8;
            size_t goB = (size_t)(n0 + row) * D_ + k0 + seg * 8;
            cp16(base + 0*TILE_B + so, Ahi + goA);
            cp16(base + 1*TILE_B + so, Alo + goA);
            cp16(base + 2*TILE_B + so, Bhi + goB);
            cp16(base + 3*TILE_B + so, Blo + goB);
        }
        CP_COMMIT();
    }

    __device__ __forceinline__ void run(float acc[4][4][4]) {
        #pragma unroll
        for (int mi = 0; mi < 4; mi++)
            #pragma unroll
            for (int ni = 0; ni < 4; ni++)
                #pragma unroll
                for (int e = 0; e < 4; e++) acc[mi][ni][e] = 0.f;

        load_stage(0, 0);
        const int NCH = 2048 / KC;
        const int lrow = lane & 15;
        const int lk   = (lane >> 4) * 8;

        for (int c = 0; c < NCH; c++) {
            asm volatile("cp.async.wait_group 0;" ::: "memory");
            __syncthreads();
            if (c + 1 < NCH) load_stage((c + 1) & 1, (c + 1) * KC);

            const uint32_t st = sb + (c & 1) * STAGE_B;
            const uint32_t aAh = st, aAl = st + TILE_B, aBh = st + 2*TILE_B, aBl = st + 3*TILE_B;

            #pragma unroll
            for (int kk = 0; kk < 2; kk++) {
                const int kb = (kk * 16 + lk) * 2;
                uint32_t ah[4][4], al[4][4];
                #pragma unroll
                for (int mi = 0; mi < 4; mi++) {
                    uint32_t off = (wm + mi*16 + lrow) * ROWB + kb;
                    ldsm4(ah[mi], aAh + off);
                    ldsm4(al[mi], aAl + off);
                }
                uint32_t bh[2][4], bl[2][4];
                #pragma unroll
                for (int nj = 0; nj < 2; nj++) {
                    uint32_t off = (wn + nj*16 + lrow) * ROWB + kb;
                    ldsm4(bh[nj], aBh + off);
                    ldsm4(bl[nj], aBl + off);
                }
                // term-major: 16 independent accumulators between reuse
                #pragma unroll
                for (int t = 0; t < 3; t++)
                    #pragma unroll
                    for (int mi = 0; mi < 4; mi++)
                        #pragma unroll
                        for (int ni = 0; ni < 4; ni++) {
                            const int nj = ni >> 1, ns = ni & 1;
                            const uint32_t* a = (t == 2) ? al[mi] : ah[mi];
                            const uint32_t* b = (t == 1) ? bl[nj] : bh[nj];
                            mma16816(acc[mi][ni], a, b[ns], b[ns+2]);
                        }
            }
        }
    }
};

// ---- fused QKV projection: grid (16, 32, 3); z = 0:Q(RoPE) 1:K(RoPE) 2:V ----
__global__ __launch_bounds__(256, 2) void gemm_qkv(
    const __nv_bfloat16* __restrict__ xhi, const __nv_bfloat16* __restrict__ xlo,
    const __nv_bfloat16* __restrict__ whi, const __nv_bfloat16* __restrict__ wlo,
    __nv_bfloat16* __restrict__ qhi, __nv_bfloat16* __restrict__ qlo,
    __nv_bfloat16* __restrict__ khi, __nv_bfloat16* __restrict__ klo,
    __nv_bfloat16* __restrict__ vhi, __nv_bfloat16* __restrict__ vlo)
{
    extern __shared__ char smc[];
    const int z = blockIdx.z;
    const size_t DD = (size_t)D_ * D_;

    GemmCore gc;
    gc.sb = smem_u32(smc);
    gc.tid = threadIdx.x;
    gc.lane = gc.tid & 31;
    gc.wid = gc.tid >> 5;
    gc.wm = (gc.wid >> 2) * 64;
    gc.wn = (gc.wid & 3) * 32;
    gc.m0 = blockIdx.y * 128;
    gc.n0 = blockIdx.x * 128;
    gc.Ahi = xhi; gc.Alo = xlo;
    gc.Bhi = whi + z * DD; gc.Blo = wlo + z * DD;

    float acc[4][4][4];
    gc.run(acc);

    __nv_bfloat16* outhi = (z == 0) ? qhi : (z == 1) ? khi : vhi;
    __nv_bfloat16* outlo = (z == 0) ? qlo : (z == 1) ? klo : vlo;
    const bool rope = (z < 2);

    const int rr = gc.lane >> 2;
    const int cp = (gc.lane & 3) * 2;
    #pragma unroll
    for (int mi = 0; mi < 4; mi++) {
        #pragma unroll
        for (int half = 0; half < 2; half++) {
            int m = gc.m0 + gc.wm + mi*16 + rr + half*8;
            int s = m & (S_ - 1);
            #pragma unroll
            for (int ni = 0; ni < 4; ni++) {
                float e = acc[mi][ni][half*2 + 0];
                float o = acc[mi][ni][half*2 + 1];
                int n = gc.n0 + gc.wn + ni*8 + cp;
                if (rope) {
                    int pair = (n & (HD_ - 1)) >> 1;
                    float cc = g_cos[s * F_ + pair], ss = g_sin[s * F_ + pair];
                    float xe = e, xo = o;
                    e = xe * cc - xo * ss;
                    o = xo * cc + xe * ss;
                }
                int br = m >> 11, h = n >> 7, hd = n & (HD_ - 1);
                size_t ei = (((size_t)(br * H_ + h)) * S_ + s) * HD_ + hd;
                __nv_bfloat16 eh = __float2bfloat16(e);
                __nv_bfloat16 oh = __float2bfloat16(o);
                __nv_bfloat16 el = __float2bfloat16(e - __bfloat162float(eh));
                __nv_bfloat16 ol = __float2bfloat16(o - __bfloat162float(oh));
                ((__nv_bfloat162*)outhi)[ei >> 1] = __halves2bfloat162(eh, oh);
                ((__nv_bfloat162*)outlo)[ei >> 1] = __halves2bfloat162(el, ol);
            }
        }
    }
}

// ---- output projection: fp32 row-major [M, 2048] ----
__global__ __launch_bounds__(256, 2) void gemm_out(
    const __nv_bfloat16* __restrict__ Ahi, const __nv_bfloat16* __restrict__ Alo,
    const __nv_bfloat16* __restrict__ Bhi, const __nv_bfloat16* __restrict__ Blo,
    float* __restrict__ outp)
{
    extern __shared__ char smc[];
    GemmCore gc;
    gc.sb = smem_u32(smc);
    gc.tid = threadIdx.x;
    gc.lane = gc.tid & 31;
    gc.wid = gc.tid >> 5;
    gc.wm = (gc.wid >> 2) * 64;
    gc.wn = (gc.wid & 3) * 32;
    gc.m0 = blockIdx.y * 128;
    gc.n0 = blockIdx.x * 128;
    gc.Ahi = Ahi; gc.Alo = Alo; gc.Bhi = Bhi; gc.Blo = Blo;

    float acc[4][4][4];
    gc.run(acc);

    const int rr = gc.lane >> 2;
    const int cp = (gc.lane & 3) * 2;
    #pragma unroll
    for (int mi = 0; mi < 4; mi++)
        #pragma unroll
        for (int half = 0; half < 2; half++) {
            int m = gc.m0 + gc.wm + mi*16 + rr + half*8;
            #pragma unroll
            for (int ni = 0; ni < 4; ni++) {
                int n = gc.n0 + gc.wn + ni*8 + cp;
                *(float2*)(outp + (size_t)m * D_ + n) =
                    make_float2(acc[mi][ni][half*2 + 0], acc[mi][ni][half*2 + 1]);
            }
        }
}

// ---------------- flash attention: HMMA QK^T + HMMA PV (P in registers) ----------------
#define AT_SQH 0                        // Q hi: 128 x 272B
#define AT_SQL 34816                    // Q lo
#define AT_SKH(b) (69632  + (b)*17408)  // K hi x2: 64 x 272B
#define AT_SKL(b) (104448 + (b)*17408)  // K lo x2
#define AT_SVH 139264                   // V hi: 64 x 272B
#define AT_SVL 156672                   // V lo
#define A_SMEM 174080

__global__ __launch_bounds__(256, 1) void attn_mma(
    __nv_bfloat16* __restrict__ outhi, __nv_bfloat16* __restrict__ outlo)
{
    extern __shared__ char smc[];
    const uint32_t sb = smem_u32(smc);

    const int tid = threadIdx.x;
    const int lane = tid & 31;
    const int wq = tid >> 5;
    const int qt = (int)gridDim.x - 1 - (int)blockIdx.x;   // heavy CTAs first
    const int bh = blockIdx.y;
    const size_t base = (size_t)bh * S_ * HD_;
    const float qscale = 0.08838834764831845f;  // 1/sqrt(128)

    #pragma unroll
    for (int t = 0; t < 8; t++) {
        int idx = t * 256 + tid;
        int row = idx >> 4, ch = idx & 15;
        size_t go = base + (size_t)(qt * 128 + row) * HD_ + ch * 8;
        cp16(sb + AT_SQH + row * 272 + ch * 16, g_qhi + go);
        cp16(sb + AT_SQL + row * 272 + ch * 16, g_qlo + go);
    }
    CP_COMMIT();
    #pragma unroll
    for (int t = 0; t < 4; t++) {
        int idx = t * 256 + tid;
        int row = idx >> 4, ch = idx & 15;
        size_t go = base + (size_t)row * HD_ + ch * 8;
        cp16(sb + AT_SKH(0) + row * 272 + ch * 16, g_khi + go);
        cp16(sb + AT_SKL(0) + row * 272 + ch * 16, g_klo + go);
    }
    CP_COMMIT();

    float acc[16][4];
    #pragma unroll
    for (int t8 = 0; t8 < 16; t8++)
        #pragma unroll
        for (int e = 0; e < 4; e++) acc[t8][e] = 0.f;
    float m_run[2] = {-1e30f, -1e30f};
    float l_run[2] = {0.f, 0.f};

    const int r0 = wq * 16 + (lane >> 2);
    const int nkt = 2 * qt + 2;
    const int lrow = lane & 15;
    const int lk = (lane >> 4) * 8;

    for (int kt = 0; kt < nkt; kt++) {
        const int kbuf = kt & 1;
        asm volatile("cp.async.wait_group 0;" ::: "memory");
        __syncthreads();

        #pragma unroll
        for (int t = 0; t < 4; t++) {
            int idx = t * 256 + tid;
            int row = idx >> 4, ch = idx & 15;
            size_t go = base + (size_t)(kt * 64 + row) * HD_ + ch * 8;
            cp16(sb + AT_SVH + row * 272 + ch * 16, g_vhi + go);
            cp16(sb + AT_SVL + row * 272 + ch * 16, g_vlo + go);
        }
        CP_COMMIT();
        const bool pk = (kt + 1) < nkt;
        if (pk) {
            #pragma unroll
            for (int t = 0; t < 4; t++) {
                int idx = t * 256 + tid;
                int row = idx >> 4, ch = idx & 15;
                size_t go = base + (size_t)((kt + 1) * 64 + row) * HD_ + ch * 8;
                cp16(sb + AT_SKH(kbuf ^ 1) + row * 272 + ch * 16, g_khi + go);
                cp16(sb + AT_SKL(kbuf ^ 1) + row * 272 + ch * 16, g_klo + go);
            }
            CP_COMMIT();
        }

        // ---- QK^T (3-term, term-major) ----
        float sacc[8][4];
        #pragma unroll
        for (int ni = 0; ni < 8; ni++)
            #pragma unroll
            for (int e = 0; e < 4; e++) sacc[ni][e] = 0.f;

        #pragma unroll
        for (int kk = 0; kk < 8; kk++) {
            const int kb = (kk * 16 + lk) * 2;
            uint32_t ah[4], al[4];
            ldsm4(ah, sb + AT_SQH + (wq * 16 + lrow) * 272 + kb);
            ldsm4(al, sb + AT_SQL + (wq * 16 + lrow) * 272 + kb);
            uint32_t bh4[4][4], bl4[4][4];
            #pragma unroll
            for (int nj = 0; nj < 4; nj++) {
                ldsm4(bh4[nj], sb + AT_SKH(kbuf) + (nj * 16 + lrow) * 272 + kb);
                ldsm4(bl4[nj], sb + AT_SKL(kbuf) + (nj * 16 + lrow) * 272 + kb);
            }
            #pragma unroll
            for (int t = 0; t < 3; t++)
                #pragma unroll
                for (int ni = 0; ni < 8; ni++) {
                    const int nj = ni >> 1, ns = ni & 1;
                    const uint32_t* a = (t == 2) ? al : ah;
                    const uint32_t* b = (t == 1) ? bl4[nj] : bh4[nj];
                    mma16816(sacc[ni], a, b[ns], b[ns+2]);
                }
        }

        // ---- softmax; pack P into bf16 hi/lo A-fragments (registers) ----
        uint32_t phi[8][2], plo[8][2];
        #pragma unroll
        for (int h2 = 0; h2 < 2; h2++) {
            const int qg = qt * 128 + r0 + h2 * 8;
            float v[16];
            float mloc = -1e30f;
            #pragma unroll
            for (int ni = 0; ni < 8; ni++)
                #pragma unroll
                for (int e = 0; e < 2; e++) {
                    float s = sacc[ni][h2*2 + e] * qscale;
                    int kg = kt * 64 + ni * 8 + (lane & 3) * 2 + e;
                    if (kg > qg) s = -1e30f;
                    v[ni*2 + e] = s;
                    mloc = fmaxf(mloc, s);
                }
            mloc = fmaxf(mloc, __shfl_xor_sync(0xffffffffu, mloc, 1));
            mloc = fmaxf(mloc, __shfl_xor_sync(0xffffffffu, mloc, 2));
            float mnew = fmaxf(m_run[h2], mloc);
            float corr = __expf(m_run[h2] - mnew);
            float rsum = 0.f;
            #pragma unroll
            for (int ni = 0; ni < 8; ni++) {
                float p0 = __expf(v[ni*2 + 0] - mnew);
                float p1 = __expf(v[ni*2 + 1] - mnew);
                rsum += p0 + p1;
                __nv_bfloat16 h0 = __float2bfloat16(p0);
                __nv_bfloat16 h1 = __float2bfloat16(p1);
                float l0 = p0 - __bfloat162float(h0);
                float l1 = p1 - __bfloat162float(h1);
                __nv_bfloat162 ph = __halves2bfloat162(h0, h1);
                phi[ni][h2] = *reinterpret_cast<uint32_t*>(&ph);
                plo[ni][h2] = pack_bf16x2(l0, l1);
            }
            rsum += __shfl_xor_sync(0xffffffffu, rsum, 1);
            rsum += __shfl_xor_sync(0xffffffffu, rsum, 2);
            l_run[h2] = l_run[h2] * corr + rsum;
            m_run[h2] = mnew;
            #pragma unroll
            for (int t8 = 0; t8 < 16; t8++) {
                acc[t8][h2*2 + 0] *= corr;
                acc[t8][h2*2 + 1] *= corr;
            }
        }

        if (pk) { asm volatile("cp.async.wait_group 1;" ::: "memory"); }
        else    { asm volatile("cp.async.wait_group 0;" ::: "memory"); }
        __syncthreads();

        // ---- PV (3-term HMMA), two n16-groups interleaved: reuse distance 4 ----
        #pragma unroll
        for (int kk = 0; kk < 4; kk++) {
            uint32_t aH[4] = { phi[2*kk][0], phi[2*kk][1], phi[2*kk+1][0], phi[2*kk+1][1] };
            uint32_t aL[4] = { plo[2*kk][0], plo[2*kk][1], plo[2*kk+1][0], plo[2*kk+1][1] };
            #pragma unroll
            for (int np = 0; np < 4; np++) {
                const int ng0 = 2*np, ng1 = 2*np + 1;
                uint32_t off0 = (kk * 16 + lrow) * 272 + (ng0 * 16 + lk) * 2;
                uint32_t off1 = (kk * 16 + lrow) * 272 + (ng1 * 16 + lk) * 2;
                uint32_t vh0[4], vl0[4], vh1[4], vl1[4];
                ldsm4t(vh0, sb + AT_SVH + off0);
                ldsm4t(vh1, sb + AT_SVH + off1);
                ldsm4t(vl0, sb + AT_SVL + off0);
                ldsm4t(vl1, sb + AT_SVL + off1);
                const int a0 = 2*ng0, b0v = 2*ng0 + 1, a1 = 2*ng1, b1v = 2*ng1 + 1;
                mma16816(acc[a0],  aH, vh0[0], vh0[1]);
                mma16816(acc[b0v], aH, vh0[2], vh0[3]);
                mma16816(acc[a1],  aH, vh1[0], vh1[1]);
                mma16816(acc[b1v], aH, vh1[2], vh1[3]);
                mma16816(acc[a0],  aL, vh0[0], vh0[1]);
                mma16816(acc[b0v], aL, vh0[2], vh0[3]);
                mma16816(acc[a1],  aL, vh1[0], vh1[1]);
                mma16816(acc[b1v], aL, vh1[2], vh1[3]);
                mma16816(acc[a0],  aH, vl0[0], vl0[1]);
                mma16816(acc[b0v], aH, vl0[2], vl0[3]);
                mma16816(acc[a1],  aH, vl1[0], vl1[1]);
                mma16816(acc[b1v], aH, vl1[2], vl1[3]);
            }
        }
        __syncthreads();
    }

    // ---- finalize: normalize, split hi/lo, store to [b*s, h*HD+d] ----
    const int b = bh >> 4;
    const int h = bh & 15;
    #pragma unroll
    for (int h2 = 0; h2 < 2; h2++) {
        float inv = 1.0f / l_run[h2];
        int sg = qt * 128 + r0 + h2 * 8;
        size_t rowbase = ((size_t)(b * S_ + sg)) * D_ + h * HD_;
        #pragma unroll
        for (int t8 = 0; t8 < 16; t8++) {
            int col = t8 * 8 + (lane & 3) * 2;
            float e = acc[t8][h2*2 + 0] * inv;
            float o = acc[t8][h2*2 + 1] * inv;
            size_t ei = rowbase + col;
            __nv_bfloat16 eh = __float2bfloat16(e);
            __nv_bfloat16 oh = __float2bfloat16(o);
            __nv_bfloat16 el = __float2bfloat16(e - __bfloat162float(eh));
            __nv_bfloat16 ol = __float2bfloat16(o - __bfloat162float(oh));
            ((__nv_bfloat162*)outhi)[ei >> 1] = __halves2bfloat162(eh, oh);
            ((__nv_bfloat162*)outlo)[ei >> 1] = __halves2bfloat162(el, ol);
        }
    }
}

extern "C" void kernel_launch(void* const* d_in, const int* in_sizes, int n_in,
                              void* d_out, int out_size) {
    (void)in_sizes; (void)n_in; (void)out_size;
    const float* x  = (const float*)d_in[0];
    const float* Wq = (const float*)d_in[1];
    const float* Wk = (const float*)d_in[2];
    const float* Wv = (const float*)d_in[3];
    const float* Wo = (const float*)d_in[4];
    float* out = (float*)d_out;

    __nv_bfloat16 *xhi, *xlo, *whi, *wlo, *qhi, *qlo, *khi, *klo, *vhi, *vlo;
    cudaGetSymbolAddress((void**)&xhi, g_xhi);
    cudaGetSymbolAddress((void**)&xlo, g_xlo);
    cudaGetSymbolAddress((void**)&whi, g_whi);
    cudaGetSymbolAddress((void**)&wlo, g_wlo);
    cudaGetSymbolAddress((void**)&qhi, g_qhi);
    cudaGetSymbolAddress((void**)&qlo, g_qlo);
    cudaGetSymbolAddress((void**)&khi, g_khi);
    cudaGetSymbolAddress((void**)&klo, g_klo);
    cudaGetSymbolAddress((void**)&vhi, g_vhi);
    cudaGetSymbolAddress((void**)&vlo, g_vlo);

    const size_t DD = (size_t)D_ * D_;

    cudaFuncSetAttribute(gemm_qkv, cudaFuncAttributeMaxDynamicSharedMemorySize, GT_SMEM);
    cudaFuncSetAttribute(gemm_out, cudaFuncAttributeMaxDynamicSharedMemorySize, GT_SMEM);
    cudaFuncSetAttribute(attn_mma, cudaFuncAttributeMaxDynamicSharedMemorySize, A_SMEM);

    rope_table_kernel<<<(S_*F_ + 255)/256, 256>>>();
    conv_fused<<<dim3(4096, 6), 256>>>(x, Wq, Wk, Wv, Wo, xhi, xlo, whi, wlo);
    gemm_qkv<<<dim3(16, 32, 3), 256, GT_SMEM>>>(xhi, xlo, whi, wlo,
                                                qhi, qlo, khi, klo, vhi, vlo);
    attn_mma<<<dim3(S_/128, B_*H_), 256, A_SMEM>>>(xhi, xlo);
    gemm_out<<<dim3(16, 32), 256, GT_SMEM>>>(xhi, xlo, whi + 3*DD, wlo + 3*DD, out);
}

// round 12
// speedup vs baseline: 2.8124x; 1.1083x over previous
#include <cuda_runtime.h>
#include <cuda_bf16.h>
#include <math.h>
#include <stdint.h>

#define B_  2
#define S_  2048
#define D_  2048
#define H_  16
#define HD_ 128
#define M_  (B_*S_)      // 4096
#define F_  (HD_/2)      // 64

// ---------------- scratch (alloc-free rule: __device__ globals) ----------------
__device__ float g_cos[S_*F_];
__device__ float g_sin[S_*F_];

__device__ __nv_bfloat16 g_qhi[B_*H_*S_*HD_];
__device__ __nv_bfloat16 g_qlo[B_*H_*S_*HD_];
__device__ __nv_bfloat16 g_khi[B_*H_*S_*HD_];
__device__ __nv_bfloat16 g_klo[B_*H_*S_*HD_];
__device__ __nv_bfloat16 g_vhi[B_*H_*S_*HD_];
__device__ __nv_bfloat16 g_vlo[B_*H_*S_*HD_];

__device__ __nv_bfloat16 g_xhi[M_*D_];   // x split; reused as attn-out split
__device__ __nv_bfloat16 g_xlo[M_*D_];
__device__ __nv_bfloat16 g_whi[4*D_*D_];
__device__ __nv_bfloat16 g_wlo[4*D_*D_];

// ---------------- PTX helpers (plain sm_100 target: no tcgen05) ----------------
__device__ __forceinline__ uint32_t smem_u32(const void* p) {
    uint32_t a;
    asm("{ .reg .u64 t; cvta.to.shared.u64 t, %1; cvt.u32.u64 %0, t; }" : "=r"(a) : "l"(p));
    return a;
}
__device__ __forceinline__ void cp16(uint32_t s, const void* g) {
    asm volatile("cp.async.cg.shared.global [%0], [%1], 16;" :: "r"(s), "l"(g));
}
#define CP_COMMIT() asm volatile("cp.async.commit_group;")

__device__ __forceinline__ void ldsm4(uint32_t* r, uint32_t addr) {
    asm volatile("ldmatrix.sync.aligned.m8n8.x4.shared.b16 {%0,%1,%2,%3}, [%4];"
        : "=r"(r[0]), "=r"(r[1]), "=r"(r[2]), "=r"(r[3]) : "r"(addr));
}
__device__ __forceinline__ void ldsm4t(uint32_t* r, uint32_t addr) {
    asm volatile("ldmatrix.sync.aligned.m8n8.x4.trans.shared.b16 {%0,%1,%2,%3}, [%4];"
        : "=r"(r[0]), "=r"(r[1]), "=r"(r[2]), "=r"(r[3]) : "r"(addr));
}
__device__ __forceinline__ void mma16816(float* d, const uint32_t* a, uint32_t b0, uint32_t b1) {
    asm volatile(
        "mma.sync.aligned.m16n8k16.row.col.f32.bf16.bf16.f32 "
        "{%0,%1,%2,%3}, {%4,%5,%6,%7}, {%8,%9}, {%0,%1,%2,%3};"
        : "+f"(d[0]), "+f"(d[1]), "+f"(d[2]), "+f"(d[3])
        : "r"(a[0]), "r"(a[1]), "r"(a[2]), "r"(a[3]), "r"(b0), "r"(b1));
}
__device__ __forceinline__ uint32_t pack_bf16x2(float a, float b) {
    __nv_bfloat162 t = __halves2bfloat162(__float2bfloat16(a), __float2bfloat16(b));
    return *reinterpret_cast<uint32_t*>(&t);
}
// SW64-style bank swizzle for 64B rows; preserves 16B granularity
__device__ __forceinline__ uint32_t swz64(uint32_t x) { return x ^ ((x >> 3) & 0x30); }

// ---------------- RoPE table ----------------
__global__ void rope_table_kernel() {
    int idx = blockIdx.x * blockDim.x + threadIdx.x;
    if (idx >= S_ * F_) return;
    int s = idx >> 6;
    int i = idx & 63;
    double invf = pow(10000.0, -(double)i / 64.0);
    double f = (double)s * invf;
    double sn, cs;
    sincos(f, &sn, &cs);
    g_cos[idx] = (float)cs;
    g_sin[idx] = (float)sn;
}

// ---------------- fused fp32 -> bf16 hi/lo splits: x (2 segs) + 4 weights ----------------
__global__ void conv_fused(const float* __restrict__ x,
                           const float* __restrict__ Wq, const float* __restrict__ Wk,
                           const float* __restrict__ Wv, const float* __restrict__ Wo,
                           __nv_bfloat16* __restrict__ xhi, __nv_bfloat16* __restrict__ xlo,
                           __nv_bfloat16* __restrict__ whi, __nv_bfloat16* __restrict__ wlo)
{
    const int y = blockIdx.y;
    const int i = blockIdx.x * blockDim.x + threadIdx.x;
    const float* in;
    __nv_bfloat16 *hi, *lo;
    size_t off4;
    const size_t SEG = (size_t)D_ * D_ / 4;
    if (y < 2) {
        in = x + (size_t)y * SEG * 4;
        hi = xhi; lo = xlo;
        off4 = (size_t)y * SEG + i;
    } else {
        const float* ws[4] = {Wq, Wk, Wv, Wo};
        in = ws[y - 2];
        hi = whi; lo = wlo;
        off4 = (size_t)(y - 2) * SEG + i;
    }
    float4 v = ((const float4*)in)[i];
    float xs[4] = {v.x, v.y, v.z, v.w};
    __nv_bfloat16 h[4], l[4];
    #pragma unroll
    for (int j = 0; j < 4; j++) {
        h[j] = __float2bfloat16(xs[j]);
        l[j] = __float2bfloat16(xs[j] - __bfloat162float(h[j]));
    }
    __nv_bfloat162* hp = (__nv_bfloat162*)hi;
    __nv_bfloat162* lp = (__nv_bfloat162*)lo;
    hp[2*off4]   = __halves2bfloat162(h[0], h[1]);
    hp[2*off4+1] = __halves2bfloat162(h[2], h[3]);
    lp[2*off4]   = __halves2bfloat162(l[0], l[1]);
    lp[2*off4+1] = __halves2bfloat162(l[2], l[3]);
}

// ---------------- mma.sync bf16 GEMM machinery ----------------
// 64B rows + XOR swizzle, 3-stage cp.async pipeline (wait_group 1), 2 CTAs/SM.
#define KC 32
#define TILE_B (128*64)              // 8192
#define STAGE_B (4*TILE_B)           // 32768
#define GT_SMEM (3*STAGE_B)          // 98304

struct GemmCore {
    uint32_t sb;
    int tid, lane, wid, wm, wn, m0, n0;
    const __nv_bfloat16 *Ahi, *Alo, *Bhi, *Blo;

    __device__ __forceinline__ void load_stage(int stg, int k0) {
        if (k0 < 2048) {
            uint32_t base = sb + stg * STAGE_B;
            #pragma unroll
            for (int t = 0; t < 2; t++) {
                int idx = t * 256 + tid;
                int row = idx >> 2, seg = idx & 3;
                uint32_t so = swz64(row * 64 + seg * 16);
                size_t goA = (size_t)(m0 + row) * D_ + k0 + seg * 8;
                size_t goB = (size_t)(n0 + row) * D_ + k0 + seg * 8;
                cp16(base + 0*TILE_B + so, Ahi + goA);
                cp16(base + 1*TILE_B + so, Alo + goA);
                cp16(base + 2*TILE_B + so, Bhi + goB);
                cp16(base + 3*TILE_B + so, Blo + goB);
            }
        }
        CP_COMMIT();   // empty commit past the tail keeps group counting uniform
    }

    __device__ __forceinline__ void run(float acc[4][4][4]) {
        #pragma unroll
        for (int mi = 0; mi < 4; mi++)
            #pragma unroll
            for (int ni = 0; ni < 4; ni++)
                #pragma unroll
                for (int e = 0; e < 4; e++) acc[mi][ni][e] = 0.f;

        load_stage(0, 0);
        load_stage(1, KC);
        const int NCH = 2048 / KC;
        const int lrow = lane & 15;
        const int lk   = (lane >> 4) * 8;

        int stg = 0;
        for (int c = 0; c < NCH; c++) {
            asm volatile("cp.async.wait_group 1;" ::: "memory");
            __syncthreads();
            int nst = stg + 2; if (nst >= 3) nst -= 3;
            load_stage(nst, (c + 2) * KC);

            const uint32_t st = sb + stg * STAGE_B;
            const uint32_t aAh = st, aAl = st + TILE_B, aBh = st + 2*TILE_B, aBl = st + 3*TILE_B;

            #pragma unroll
            for (int kk = 0; kk < 2; kk++) {
                const int kb = (kk * 16 + lk) * 2;
                uint32_t ah[4][4], al[4][4];
                #pragma unroll
                for (int mi = 0; mi < 4; mi++) {
                    uint32_t off = swz64((wm + mi*16 + lrow) * 64 + kb);
                    ldsm4(ah[mi], aAh + off);
                    ldsm4(al[mi], aAl + off);
                }
                uint32_t bh[2][4], bl[2][4];
                #pragma unroll
                for (int nj = 0; nj < 2; nj++) {
                    uint32_t off = swz64((wn + nj*16 + lrow) * 64 + kb);
                    ldsm4(bh[nj], aBh + off);
                    ldsm4(bl[nj], aBl + off);
                }
                // term-major: 16 independent accumulators between reuse
                #pragma unroll
                for (int t = 0; t < 3; t++)
                    #pragma unroll
                    for (int mi = 0; mi < 4; mi++)
                        #pragma unroll
                        for (int ni = 0; ni < 4; ni++) {
                            const int nj = ni >> 1, ns = ni & 1;
                            const uint32_t* a = (t == 2) ? al[mi] : ah[mi];
                            const uint32_t* b = (t == 1) ? bl[nj] : bh[nj];
                            mma16816(acc[mi][ni], a, b[ns], b[ns+2]);
                        }
            }
            if (++stg >= 3) stg = 0;
        }
    }
};

// ---- fused QKV projection: grid (16, 32, 3); z = 0:Q(RoPE) 1:K(RoPE) 2:V ----
__global__ __launch_bounds__(256, 2) void gemm_qkv(
    const __nv_bfloat16* __restrict__ xhi, const __nv_bfloat16* __restrict__ xlo,
    const __nv_bfloat16* __restrict__ whi, const __nv_bfloat16* __restrict__ wlo,
    __nv_bfloat16* __restrict__ qhi, __nv_bfloat16* __restrict__ qlo,
    __nv_bfloat16* __restrict__ khi, __nv_bfloat16* __restrict__ klo,
    __nv_bfloat16* __restrict__ vhi, __nv_bfloat16* __restrict__ vlo)
{
    extern __shared__ char smc[];
    const int z = blockIdx.z;
    const size_t DD = (size_t)D_ * D_;

    GemmCore gc;
    gc.sb = smem_u32(smc);
    gc.tid = threadIdx.x;
    gc.lane = gc.tid & 31;
    gc.wid = gc.tid >> 5;
    gc.wm = (gc.wid >> 2) * 64;
    gc.wn = (gc.wid & 3) * 32;
    gc.m0 = blockIdx.y * 128;
    gc.n0 = blockIdx.x * 128;
    gc.Ahi = xhi; gc.Alo = xlo;
    gc.Bhi = whi + z * DD; gc.Blo = wlo + z * DD;

    float acc[4][4][4];
    gc.run(acc);

    __nv_bfloat16* outhi = (z == 0) ? qhi : (z == 1) ? khi : vhi;
    __nv_bfloat16* outlo = (z == 0) ? qlo : (z == 1) ? klo : vlo;
    const bool rope = (z < 2);

    const int rr = gc.lane >> 2;
    const int cp = (gc.lane & 3) * 2;
    #pragma unroll
    for (int mi = 0; mi < 4; mi++) {
        #pragma unroll
        for (int half = 0; half < 2; half++) {
            int m = gc.m0 + gc.wm + mi*16 + rr + half*8;
            int s = m & (S_ - 1);
            #pragma unroll
            for (int ni = 0; ni < 4; ni++) {
                float e = acc[mi][ni][half*2 + 0];
                float o = acc[mi][ni][half*2 + 1];
                int n = gc.n0 + gc.wn + ni*8 + cp;
                if (rope) {
                    int pair = (n & (HD_ - 1)) >> 1;
                    float cc = g_cos[s * F_ + pair], ss = g_sin[s * F_ + pair];
                    float xe = e, xo = o;
                    e = xe * cc - xo * ss;
                    o = xo * cc + xe * ss;
                }
                int br = m >> 11, h = n >> 7, hd = n & (HD_ - 1);
                size_t ei = (((size_t)(br * H_ + h)) * S_ + s) * HD_ + hd;
                __nv_bfloat16 eh = __float2bfloat16(e);
                __nv_bfloat16 oh = __float2bfloat16(o);
                __nv_bfloat16 el = __float2bfloat16(e - __bfloat162float(eh));
                __nv_bfloat16 ol = __float2bfloat16(o - __bfloat162float(oh));
                ((__nv_bfloat162*)outhi)[ei >> 1] = __halves2bfloat162(eh, oh);
                ((__nv_bfloat162*)outlo)[ei >> 1] = __halves2bfloat162(el, ol);
            }
        }
    }
}

// ---- output projection: fp32 row-major [M, 2048] ----
__global__ __launch_bounds__(256, 2) void gemm_out(
    const __nv_bfloat16* __restrict__ Ahi, const __nv_bfloat16* __restrict__ Alo,
    const __nv_bfloat16* __restrict__ Bhi, const __nv_bfloat16* __restrict__ Blo,
    float* __restrict__ outp)
{
    extern __shared__ char smc[];
    GemmCore gc;
    gc.sb = smem_u32(smc);
    gc.tid = threadIdx.x;
    gc.lane = gc.tid & 31;
    gc.wid = gc.tid >> 5;
    gc.wm = (gc.wid >> 2) * 64;
    gc.wn = (gc.wid & 3) * 32;
    gc.m0 = blockIdx.y * 128;
    gc.n0 = blockIdx.x * 128;
    gc.Ahi = Ahi; gc.Alo = Alo; gc.Bhi = Bhi; gc.Blo = Blo;

    float acc[4][4][4];
    gc.run(acc);

    const int rr = gc.lane >> 2;
    const int cp = (gc.lane & 3) * 2;
    #pragma unroll
    for (int mi = 0; mi < 4; mi++)
        #pragma unroll
        for (int half = 0; half < 2; half++) {
            int m = gc.m0 + gc.wm + mi*16 + rr + half*8;
            #pragma unroll
            for (int ni = 0; ni < 4; ni++) {
                int n = gc.n0 + gc.wn + ni*8 + cp;
                *(float2*)(outp + (size_t)m * D_ + n) =
                    make_float2(acc[mi][ni][half*2 + 0], acc[mi][ni][half*2 + 1]);
            }
        }
}

// ---------------- flash attention: HMMA QK^T + HMMA PV (P in registers) ----------------
#define AT_SQH 0                        // Q hi: 128 x 272B
#define AT_SQL 34816                    // Q lo
#define AT_SKH(b) (69632  + (b)*17408)  // K hi x2: 64 x 272B
#define AT_SKL(b) (104448 + (b)*17408)  // K lo x2
#define AT_SVH 139264                   // V hi: 64 x 272B
#define AT_SVL 156672                   // V lo
#define A_SMEM 174080

__global__ __launch_bounds__(256, 1) void attn_mma(
    __nv_bfloat16* __restrict__ outhi, __nv_bfloat16* __restrict__ outlo)
{
    extern __shared__ char smc[];
    const uint32_t sb = smem_u32(smc);

    const int tid = threadIdx.x;
    const int lane = tid & 31;
    const int wq = tid >> 5;
    const int qt = (int)gridDim.x - 1 - (int)blockIdx.x;   // heavy CTAs first
    const int bh = blockIdx.y;
    const size_t base = (size_t)bh * S_ * HD_;
    const float qscale = 0.08838834764831845f;  // 1/sqrt(128)

    #pragma unroll
    for (int t = 0; t < 8; t++) {
        int idx = t * 256 + tid;
        int row = idx >> 4, ch = idx & 15;
        size_t go = base + (size_t)(qt * 128 + row) * HD_ + ch * 8;
        cp16(sb + AT_SQH + row * 272 + ch * 16, g_qhi + go);
        cp16(sb + AT_SQL + row * 272 + ch * 16, g_qlo + go);
    }
    CP_COMMIT();
    #pragma unroll
    for (int t = 0; t < 4; t++) {
        int idx = t * 256 + tid;
        int row = idx >> 4, ch = idx & 15;
        size_t go = base + (size_t)row * HD_ + ch * 8;
        cp16(sb + AT_SKH(0) + row * 272 + ch * 16, g_khi + go);
        cp16(sb + AT_SKL(0) + row * 272 + ch * 16, g_klo + go);
    }
    CP_COMMIT();

    float acc[16][4];
    #pragma unroll
    for (int t8 = 0; t8 < 16; t8++)
        #pragma unroll
        for (int e = 0; e < 4; e++) acc[t8][e] = 0.f;
    float m_run[2] = {-1e30f, -1e30f};
    float l_run[2] = {0.f, 0.f};

    const int r0 = wq * 16 + (lane >> 2);
    const int nkt = 2 * qt + 2;
    const int lrow = lane & 15;
    const int lk = (lane >> 4) * 8;

    for (int kt = 0; kt < nkt; kt++) {
        const int kbuf = kt & 1;
        asm volatile("cp.async.wait_group 0;" ::: "memory");
        __syncthreads();

        #pragma unroll
        for (int t = 0; t < 4; t++) {
            int idx = t * 256 + tid;
            int row = idx >> 4, ch = idx & 15;
            size_t go = base + (size_t)(kt * 64 + row) * HD_ + ch * 8;
            cp16(sb + AT_SVH + row * 272 + ch * 16, g_vhi + go);
            cp16(sb + AT_SVL + row * 272 + ch * 16, g_vlo + go);
        }
        CP_COMMIT();
        const bool pk = (kt + 1) < nkt;
        if (pk) {
            #pragma unroll
            for (int t = 0; t < 4; t++) {
                int idx = t * 256 + tid;
                int row = idx >> 4, ch = idx & 15;
                size_t go = base + (size_t)((kt + 1) * 64 + row) * HD_ + ch * 8;
                cp16(sb + AT_SKH(kbuf ^ 1) + row * 272 + ch * 16, g_khi + go);
                cp16(sb + AT_SKL(kbuf ^ 1) + row * 272 + ch * 16, g_klo + go);
            }
            CP_COMMIT();
        }

        // ---- QK^T (3-term, term-major) ----
        float sacc[8][4];
        #pragma unroll
        for (int ni = 0; ni < 8; ni++)
            #pragma unroll
            for (int e = 0; e < 4; e++) sacc[ni][e] = 0.f;

        #pragma unroll
        for (int kk = 0; kk < 8; kk++) {
            const int kb = (kk * 16 + lk) * 2;
            uint32_t ah[4], al[4];
            ldsm4(ah, sb + AT_SQH + (wq * 16 + lrow) * 272 + kb);
            ldsm4(al, sb + AT_SQL + (wq * 16 + lrow) * 272 + kb);
            uint32_t bh4[4][4], bl4[4][4];
            #pragma unroll
            for (int nj = 0; nj < 4; nj++) {
                ldsm4(bh4[nj], sb + AT_SKH(kbuf) + (nj * 16 + lrow) * 272 + kb);
                ldsm4(bl4[nj], sb + AT_SKL(kbuf) + (nj * 16 + lrow) * 272 + kb);
            }
            #pragma unroll
            for (int t = 0; t < 3; t++)
                #pragma unroll
                for (int ni = 0; ni < 8; ni++) {
                    const int nj = ni >> 1, ns = ni & 1;
                    const uint32_t* a = (t == 2) ? al : ah;
                    const uint32_t* b = (t == 1) ? bl4[nj] : bh4[nj];
                    mma16816(sacc[ni], a, b[ns], b[ns+2]);
                }
        }

        // ---- softmax; pack P into bf16 hi/lo A-fragments (registers) ----
        uint32_t phi[8][2], plo[8][2];
        #pragma unroll
        for (int h2 = 0; h2 < 2; h2++) {
            const int qg = qt * 128 + r0 + h2 * 8;
            float v[16];
            float mloc = -1e30f;
            #pragma unroll
            for (int ni = 0; ni < 8; ni++)
                #pragma unroll
                for (int e = 0; e < 2; e++) {
                    float s = sacc[ni][h2*2 + e] * qscale;
                    int kg = kt * 64 + ni * 8 + (lane & 3) * 2 + e;
                    if (kg > qg) s = -1e30f;
                    v[ni*2 + e] = s;
                    mloc = fmaxf(mloc, s);
                }
            mloc = fmaxf(mloc, __shfl_xor_sync(0xffffffffu, mloc, 1));
            mloc = fmaxf(mloc, __shfl_xor_sync(0xffffffffu, mloc, 2));
            float mnew = fmaxf(m_run[h2], mloc);
            float corr = __expf(m_run[h2] - mnew);
            float rsum = 0.f;
            #pragma unroll
            for (int ni = 0; ni < 8; ni++) {
                float p0 = __expf(v[ni*2 + 0] - mnew);
                float p1 = __expf(v[ni*2 + 1] - mnew);
                rsum += p0 + p1;
                __nv_bfloat16 h0 = __float2bfloat16(p0);
                __nv_bfloat16 h1 = __float2bfloat16(p1);
                float l0 = p0 - __bfloat162float(h0);
                float l1 = p1 - __bfloat162float(h1);
                __nv_bfloat162 ph = __halves2bfloat162(h0, h1);
                phi[ni][h2] = *reinterpret_cast<uint32_t*>(&ph);
                plo[ni][h2] = pack_bf16x2(l0, l1);
            }
            rsum += __shfl_xor_sync(0xffffffffu, rsum, 1);
            rsum += __shfl_xor_sync(0xffffffffu, rsum, 2);
            l_run[h2] = l_run[h2] * corr + rsum;
            m_run[h2] = mnew;
            #pragma unroll
            for (int t8 = 0; t8 < 16; t8++) {
                acc[t8][h2*2 + 0] *= corr;
                acc[t8][h2*2 + 1] *= corr;
            }
        }

        if (pk) { asm volatile("cp.async.wait_group 1;" ::: "memory"); }
        else    { asm volatile("cp.async.wait_group 0;" ::: "memory"); }
        __syncthreads();

        // ---- PV (3-term HMMA), two n16-groups interleaved: reuse distance 4 ----
        #pragma unroll
        for (int kk = 0; kk < 4; kk++) {
            uint32_t aH[4] = { phi[2*kk][0], phi[2*kk][1], phi[2*kk+1][0], phi[2*kk+1][1] };
            uint32_t aL[4] = { plo[2*kk][0], plo[2*kk][1], plo[2*kk+1][0], plo[2*kk+1][1] };
            #pragma unroll
            for (int np = 0; np < 4; np++) {
                const int ng0 = 2*np, ng1 = 2*np + 1;
                uint32_t off0 = (kk * 16 + lrow) * 272 + (ng0 * 16 + lk) * 2;
                uint32_t off1 = (kk * 16 + lrow) * 272 + (ng1 * 16 + lk) * 2;
                uint32_t vh0[4], vl0[4], vh1[4], vl1[4];
                ldsm4t(vh0, sb + AT_SVH + off0);
                ldsm4t(vh1, sb + AT_SVH + off1);
                ldsm4t(vl0, sb + AT_SVL + off0);
                ldsm4t(vl1, sb + AT_SVL + off1);
                const int a0 = 2*ng0, b0v = 2*ng0 + 1, a1 = 2*ng1, b1v = 2*ng1 + 1;
                mma16816(acc[a0],  aH, vh0[0], vh0[1]);
                mma16816(acc[b0v], aH, vh0[2], vh0[3]);
                mma16816(acc[a1],  aH, vh1[0], vh1[1]);
                mma16816(acc[b1v], aH, vh1[2], vh1[3]);
                mma16816(acc[a0],  aL, vh0[0], vh0[1]);
                mma16816(acc[b0v], aL, vh0[2], vh0[3]);
                mma16816(acc[a1],  aL, vh1[0], vh1[1]);
                mma16816(acc[b1v], aL, vh1[2], vh1[3]);
                mma16816(acc[a0],  aH, vl0[0], vl0[1]);
                mma16816(acc[b0v], aH, vl0[2], vl0[3]);
                mma16816(acc[a1],  aH, vl1[0], vl1[1]);
                mma16816(acc[b1v], aH, vl1[2], vl1[3]);
            }
        }
        __syncthreads();
    }

    // ---- finalize: normalize, split hi/lo, store to [b*s, h*HD+d] ----
    const int b = bh >> 4;
    const int h = bh & 15;
    #pragma unroll
    for (int h2 = 0; h2 < 2; h2++) {
        float inv = 1.0f / l_run[h2];
        int sg = qt * 128 + r0 + h2 * 8;
        size_t rowbase = ((size_t)(b * S_ + sg)) * D_ + h * HD_;
        #pragma unroll
        for (int t8 = 0; t8 < 16; t8++) {
            int col = t8 * 8 + (lane & 3) * 2;
            float e = acc[t8][h2*2 + 0] * inv;
            float o = acc[t8][h2*2 + 1] * inv;
            size_t ei = rowbase + col;
            __nv_bfloat16 eh = __float2bfloat16(e);
            __nv_bfloat16 oh = __float2bfloat16(o);
            __nv_bfloat16 el = __float2bfloat16(e - __bfloat162float(eh));
            __nv_bfloat16 ol = __float2bfloat16(o - __bfloat162float(oh));
            ((__nv_bfloat162*)outhi)[ei >> 1] = __halves2bfloat162(eh, oh);
            ((__nv_bfloat162*)outlo)[ei >> 1] = __halves2bfloat162(el, ol);
        }
    }
}

extern "C" void kernel_launch(void* const* d_in, const int* in_sizes, int n_in,
                              void* d_out, int out_size) {
    (void)in_sizes; (void)n_in; (void)out_size;
    const float* x  = (const float*)d_in[0];
    const float* Wq = (const float*)d_in[1];
    const float* Wk = (const float*)d_in[2];
    const float* Wv = (const float*)d_in[3];
    const float* Wo = (const float*)d_in[4];
    float* out = (float*)d_out;

    __nv_bfloat16 *xhi, *xlo, *whi, *wlo, *qhi, *qlo, *khi, *klo, *vhi, *vlo;
    cudaGetSymbolAddress((void**)&xhi, g_xhi);
    cudaGetSymbolAddress((void**)&xlo, g_xlo);
    cudaGetSymbolAddress((void**)&whi, g_whi);
    cudaGetSymbolAddress((void**)&wlo, g_wlo);
    cudaGetSymbolAddress((void**)&qhi, g_qhi);
    cudaGetSymbolAddress((void**)&qlo, g_qlo);
    cudaGetSymbolAddress((void**)&khi, g_khi);
    cudaGetSymbolAddress((void**)&klo, g_klo);
    cudaGetSymbolAddress((void**)&vhi, g_vhi);
    cudaGetSymbolAddress((void**)&vlo, g_vlo);

    const size_t DD = (size_t)D_ * D_;

    cudaFuncSetAttribute(gemm_qkv, cudaFuncAttributeMaxDynamicSharedMemorySize, GT_SMEM);
    cudaFuncSetAttribute(gemm_out, cudaFuncAttributeMaxDynamicSharedMemorySize, GT_SMEM);
    cudaFuncSetAttribute(attn_mma, cudaFuncAttributeMaxDynamicSharedMemorySize, A_SMEM);

    rope_table_kernel<<<(S_*F_ + 255)/256, 256>>>();
    conv_fused<<<dim3(4096, 6), 256>>>(x, Wq, Wk, Wv, Wo, xhi, xlo, whi, wlo);
    gemm_qkv<<<dim3(16, 32, 3), 256, GT_SMEM>>>(xhi, xlo, whi, wlo,
                                                qhi, qlo, khi, klo, vhi, vlo);
    attn_mma<<<dim3(S_/128, B_*H_), 256, A_SMEM>>>(xhi, xlo);
    gemm_out<<<dim3(16, 32), 256, GT_SMEM>>>(xhi, xlo, whi + 3*DD, wlo + 3*DD, out);
}

// round 13
// speedup vs baseline: 2.9557x; 1.0510x over previous
#include <cuda_runtime.h>
#include <cuda_bf16.h>
#include <math.h>
#include <stdint.h>

#define B_  2
#define S_  2048
#define D_  2048
#define H_  16
#define HD_ 128
#define M_  (B_*S_)      // 4096
#define F_  (HD_/2)      // 64

// ---------------- scratch (alloc-free rule: __device__ globals) ----------------
__device__ float g_cos[S_*F_];
__device__ float g_sin[S_*F_];

__device__ __nv_bfloat16 g_qhi[B_*H_*S_*HD_];
__device__ __nv_bfloat16 g_qlo[B_*H_*S_*HD_];
__device__ __nv_bfloat16 g_khi[B_*H_*S_*HD_];
__device__ __nv_bfloat16 g_klo[B_*H_*S_*HD_];
__device__ __nv_bfloat16 g_vhi[B_*H_*S_*HD_];
__device__ __nv_bfloat16 g_vlo[B_*H_*S_*HD_];

__device__ __nv_bfloat16 g_xhi[M_*D_];   // x split; reused as attn-out split
__device__ __nv_bfloat16 g_xlo[M_*D_];
__device__ __nv_bfloat16 g_whi[4*D_*D_];
__device__ __nv_bfloat16 g_wlo[4*D_*D_];

// ---------------- PTX helpers (plain sm_100 target: no tcgen05) ----------------
__device__ __forceinline__ uint32_t smem_u32(const void* p) {
    uint32_t a;
    asm("{ .reg .u64 t; cvta.to.shared.u64 t, %1; cvt.u32.u64 %0, t; }" : "=r"(a) : "l"(p));
    return a;
}
__device__ __forceinline__ void cp16(uint32_t s, const void* g) {
    asm volatile("cp.async.cg.shared.global [%0], [%1], 16;" :: "r"(s), "l"(g));
}
#define CP_COMMIT() asm volatile("cp.async.commit_group;")

__device__ __forceinline__ void ldsm4(uint32_t* r, uint32_t addr) {
    asm volatile("ldmatrix.sync.aligned.m8n8.x4.shared.b16 {%0,%1,%2,%3}, [%4];"
        : "=r"(r[0]), "=r"(r[1]), "=r"(r[2]), "=r"(r[3]) : "r"(addr));
}
__device__ __forceinline__ void ldsm4t(uint32_t* r, uint32_t addr) {
    asm volatile("ldmatrix.sync.aligned.m8n8.x4.trans.shared.b16 {%0,%1,%2,%3}, [%4];"
        : "=r"(r[0]), "=r"(r[1]), "=r"(r[2]), "=r"(r[3]) : "r"(addr));
}
__device__ __forceinline__ void mma16816(float* d, const uint32_t* a, uint32_t b0, uint32_t b1) {
    asm volatile(
        "mma.sync.aligned.m16n8k16.row.col.f32.bf16.bf16.f32 "
        "{%0,%1,%2,%3}, {%4,%5,%6,%7}, {%8,%9}, {%0,%1,%2,%3};"
        : "+f"(d[0]), "+f"(d[1]), "+f"(d[2]), "+f"(d[3])
        : "r"(a[0]), "r"(a[1]), "r"(a[2]), "r"(a[3]), "r"(b0), "r"(b1));
}
__device__ __forceinline__ uint32_t pack_bf16x2(float a, float b) {
    __nv_bfloat162 t = __halves2bfloat162(__float2bfloat16(a), __float2bfloat16(b));
    return *reinterpret_cast<uint32_t*>(&t);
}
// SW64-style bank swizzle for 64B rows; preserves 16B granularity
__device__ __forceinline__ uint32_t swz64(uint32_t x) { return x ^ ((x >> 3) & 0x30); }
// swizzle for 256B rows: row bits [8:10] -> 16B-column bits [4:6]
__device__ __forceinline__ uint32_t swz256(uint32_t x) { return x ^ ((x >> 4) & 0x70); }

// ---------------- RoPE table ----------------
__global__ void rope_table_kernel() {
    int idx = blockIdx.x * blockDim.x + threadIdx.x;
    if (idx >= S_ * F_) return;
    int s = idx >> 6;
    int i = idx & 63;
    double invf = pow(10000.0, -(double)i / 64.0);
    double f = (double)s * invf;
    double sn, cs;
    sincos(f, &sn, &cs);
    g_cos[idx] = (float)cs;
    g_sin[idx] = (float)sn;
}

// ---------------- fused fp32 -> bf16 hi/lo splits: x (2 segs) + 4 weights ----------------
__global__ void conv_fused(const float* __restrict__ x,
                           const float* __restrict__ Wq, const float* __restrict__ Wk,
                           const float* __restrict__ Wv, const float* __restrict__ Wo,
                           __nv_bfloat16* __restrict__ xhi, __nv_bfloat16* __restrict__ xlo,
                           __nv_bfloat16* __restrict__ whi, __nv_bfloat16* __restrict__ wlo)
{
    const int y = blockIdx.y;
    const int i = blockIdx.x * blockDim.x + threadIdx.x;
    const float* in;
    __nv_bfloat16 *hi, *lo;
    size_t off4;
    const size_t SEG = (size_t)D_ * D_ / 4;
    if (y < 2) {
        in = x + (size_t)y * SEG * 4;
        hi = xhi; lo = xlo;
        off4 = (size_t)y * SEG + i;
    } else {
        const float* ws[4] = {Wq, Wk, Wv, Wo};
        in = ws[y - 2];
        hi = whi; lo = wlo;
        off4 = (size_t)(y - 2) * SEG + i;
    }
    float4 v = ((const float4*)in)[i];
    float xs[4] = {v.x, v.y, v.z, v.w};
    __nv_bfloat16 h[4], l[4];
    #pragma unroll
    for (int j = 0; j < 4; j++) {
        h[j] = __float2bfloat16(xs[j]);
        l[j] = __float2bfloat16(xs[j] - __bfloat162float(h[j]));
    }
    __nv_bfloat162* hp = (__nv_bfloat162*)hi;
    __nv_bfloat162* lp = (__nv_bfloat162*)lo;
    hp[2*off4]   = __halves2bfloat162(h[0], h[1]);
    hp[2*off4+1] = __halves2bfloat162(h[2], h[3]);
    lp[2*off4]   = __halves2bfloat162(l[0], l[1]);
    lp[2*off4+1] = __halves2bfloat162(l[2], l[3]);
}

// ---------------- mma.sync bf16 GEMM machinery (unchanged from round 12) ----------------
#define KC 32
#define TILE_B (128*64)              // 8192
#define STAGE_B (4*TILE_B)           // 32768
#define GT_SMEM (3*STAGE_B)          // 98304

struct GemmCore {
    uint32_t sb;
    int tid, lane, wid, wm, wn, m0, n0;
    const __nv_bfloat16 *Ahi, *Alo, *Bhi, *Blo;

    __device__ __forceinline__ void load_stage(int stg, int k0) {
        if (k0 < 2048) {
            uint32_t base = sb + stg * STAGE_B;
            #pragma unroll
            for (int t = 0; t < 2; t++) {
                int idx = t * 256 + tid;
                int row = idx >> 2, seg = idx & 3;
                uint32_t so = swz64(row * 64 + seg * 16);
                size_t goA = (size_t)(m0 + row) * D_ + k0 + seg * 8;
                size_t goB = (size_t)(n0 + row) * D_ + k0 + seg * 8;
                cp16(base + 0*TILE_B + so, Ahi + goA);
                cp16(base + 1*TILE_B + so, Alo + goA);
                cp16(base + 2*TILE_B + so, Bhi + goB);
                cp16(base + 3*TILE_B + so, Blo + goB);
            }
        }
        CP_COMMIT();   // empty commit past the tail keeps group counting uniform
    }

    __device__ __forceinline__ void run(float acc[4][4][4]) {
        #pragma unroll
        for (int mi = 0; mi < 4; mi++)
            #pragma unroll
            for (int ni = 0; ni < 4; ni++)
                #pragma unroll
                for (int e = 0; e < 4; e++) acc[mi][ni][e] = 0.f;

        load_stage(0, 0);
        load_stage(1, KC);
        const int NCH = 2048 / KC;
        const int lrow = lane & 15;
        const int lk   = (lane >> 4) * 8;

        int stg = 0;
        for (int c = 0; c < NCH; c++) {
            asm volatile("cp.async.wait_group 1;" ::: "memory");
            __syncthreads();
            int nst = stg + 2; if (nst >= 3) nst -= 3;
            load_stage(nst, (c + 2) * KC);

            const uint32_t st = sb + stg * STAGE_B;
            const uint32_t aAh = st, aAl = st + TILE_B, aBh = st + 2*TILE_B, aBl = st + 3*TILE_B;

            #pragma unroll
            for (int kk = 0; kk < 2; kk++) {
                const int kb = (kk * 16 + lk) * 2;
                uint32_t ah[4][4], al[4][4];
                #pragma unroll
                for (int mi = 0; mi < 4; mi++) {
                    uint32_t off = swz64((wm + mi*16 + lrow) * 64 + kb);
                    ldsm4(ah[mi], aAh + off);
                    ldsm4(al[mi], aAl + off);
                }
                uint32_t bh[2][4], bl[2][4];
                #pragma unroll
                for (int nj = 0; nj < 2; nj++) {
                    uint32_t off = swz64((wn + nj*16 + lrow) * 64 + kb);
                    ldsm4(bh[nj], aBh + off);
                    ldsm4(bl[nj], aBl + off);
                }
                // term-major: 16 independent accumulators between reuse
                #pragma unroll
                for (int t = 0; t < 3; t++)
                    #pragma unroll
                    for (int mi = 0; mi < 4; mi++)
                        #pragma unroll
                        for (int ni = 0; ni < 4; ni++) {
                            const int nj = ni >> 1, ns = ni & 1;
                            const uint32_t* a = (t == 2) ? al[mi] : ah[mi];
                            const uint32_t* b = (t == 1) ? bl[nj] : bh[nj];
                            mma16816(acc[mi][ni], a, b[ns], b[ns+2]);
                        }
            }
            if (++stg >= 3) stg = 0;
        }
    }
};

// ---- fused QKV projection: grid (16, 32, 3); z = 0:Q(RoPE) 1:K(RoPE) 2:V ----
__global__ __launch_bounds__(256, 2) void gemm_qkv(
    const __nv_bfloat16* __restrict__ xhi, const __nv_bfloat16* __restrict__ xlo,
    const __nv_bfloat16* __restrict__ whi, const __nv_bfloat16* __restrict__ wlo,
    __nv_bfloat16* __restrict__ qhi, __nv_bfloat16* __restrict__ qlo,
    __nv_bfloat16* __restrict__ khi, __nv_bfloat16* __restrict__ klo,
    __nv_bfloat16* __restrict__ vhi, __nv_bfloat16* __restrict__ vlo)
{
    extern __shared__ char smc[];
    const int z = blockIdx.z;
    const size_t DD = (size_t)D_ * D_;

    GemmCore gc;
    gc.sb = smem_u32(smc);
    gc.tid = threadIdx.x;
    gc.lane = gc.tid & 31;
    gc.wid = gc.tid >> 5;
    gc.wm = (gc.wid >> 2) * 64;
    gc.wn = (gc.wid & 3) * 32;
    gc.m0 = blockIdx.y * 128;
    gc.n0 = blockIdx.x * 128;
    gc.Ahi = xhi; gc.Alo = xlo;
    gc.Bhi = whi + z * DD; gc.Blo = wlo + z * DD;

    float acc[4][4][4];
    gc.run(acc);

    __nv_bfloat16* outhi = (z == 0) ? qhi : (z == 1) ? khi : vhi;
    __nv_bfloat16* outlo = (z == 0) ? qlo : (z == 1) ? klo : vlo;
    const bool rope = (z < 2);

    const int rr = gc.lane >> 2;
    const int cp = (gc.lane & 3) * 2;
    #pragma unroll
    for (int mi = 0; mi < 4; mi++) {
        #pragma unroll
        for (int half = 0; half < 2; half++) {
            int m = gc.m0 + gc.wm + mi*16 + rr + half*8;
            int s = m & (S_ - 1);
            #pragma unroll
            for (int ni = 0; ni < 4; ni++) {
                float e = acc[mi][ni][half*2 + 0];
                float o = acc[mi][ni][half*2 + 1];
                int n = gc.n0 + gc.wn + ni*8 + cp;
                if (rope) {
                    int pair = (n & (HD_ - 1)) >> 1;
                    float cc = g_cos[s * F_ + pair], ss = g_sin[s * F_ + pair];
                    float xe = e, xo = o;
                    e = xe * cc - xo * ss;
                    o = xo * cc + xe * ss;
                }
                int br = m >> 11, h = n >> 7, hd = n & (HD_ - 1);
                size_t ei = (((size_t)(br * H_ + h)) * S_ + s) * HD_ + hd;
                __nv_bfloat16 eh = __float2bfloat16(e);
                __nv_bfloat16 oh = __float2bfloat16(o);
                __nv_bfloat16 el = __float2bfloat16(e - __bfloat162float(eh));
                __nv_bfloat16 ol = __float2bfloat16(o - __bfloat162float(oh));
                ((__nv_bfloat162*)outhi)[ei >> 1] = __halves2bfloat162(eh, oh);
                ((__nv_bfloat162*)outlo)[ei >> 1] = __halves2bfloat162(el, ol);
            }
        }
    }
}

// ---- output projection: fp32 row-major [M, 2048] ----
__global__ __launch_bounds__(256, 2) void gemm_out(
    const __nv_bfloat16* __restrict__ Ahi, const __nv_bfloat16* __restrict__ Alo,
    const __nv_bfloat16* __restrict__ Bhi, const __nv_bfloat16* __restrict__ Blo,
    float* __restrict__ outp)
{
    extern __shared__ char smc[];
    GemmCore gc;
    gc.sb = smem_u32(smc);
    gc.tid = threadIdx.x;
    gc.lane = gc.tid & 31;
    gc.wid = gc.tid >> 5;
    gc.wm = (gc.wid >> 2) * 64;
    gc.wn = (gc.wid & 3) * 32;
    gc.m0 = blockIdx.y * 128;
    gc.n0 = blockIdx.x * 128;
    gc.Ahi = Ahi; gc.Alo = Alo; gc.Bhi = Bhi; gc.Blo = Blo;

    float acc[4][4][4];
    gc.run(acc);

    const int rr = gc.lane >> 2;
    const int cp = (gc.lane & 3) * 2;
    #pragma unroll
    for (int mi = 0; mi < 4; mi++)
        #pragma unroll
        for (int half = 0; half < 2; half++) {
            int m = gc.m0 + gc.wm + mi*16 + rr + half*8;
            #pragma unroll
            for (int ni = 0; ni < 4; ni++) {
                int n = gc.n0 + gc.wn + ni*8 + cp;
                *(float2*)(outp + (size_t)m * D_ + n) =
                    make_float2(acc[mi][ni][half*2 + 0], acc[mi][ni][half*2 + 1]);
            }
        }
}

// ---------------- flash attention v2: 64-q-row CTAs, 128 threads, 2 CTAs/SM ----------------
// smem 96 KB: 256B rows + swz256 (bank-clean ldsm, 16B cp.async).
// Only the kt==qt tile needs causal masking.
#define AT2_QH 0         // Q hi: 64 x 256B
#define AT2_QL 16384     // Q lo
#define AT2_KH 32768     // K hi: 64 x 256B
#define AT2_KL 49152     // K lo
#define AT2_VH 65536     // V hi
#define AT2_VL 81920     // V lo
#define A_SMEM 98304

__global__ __launch_bounds__(128, 2) void attn_mma(
    __nv_bfloat16* __restrict__ outhi, __nv_bfloat16* __restrict__ outlo)
{
    extern __shared__ char smc[];
    const uint32_t sb = smem_u32(smc);

    const int tid = threadIdx.x;
    const int lane = tid & 31;
    const int wq = tid >> 5;                                // 0..3
    const int qt = (int)gridDim.x - 1 - (int)blockIdx.x;    // heavy CTAs first
    const int bh = blockIdx.y;
    const size_t base = (size_t)bh * S_ * HD_;
    const float qscale = 0.08838834764831845f;  // 1/sqrt(128)

    // ---- preload Q ----
    #pragma unroll
    for (int t = 0; t < 8; t++) {
        int idx = t * 128 + tid;
        int row = idx >> 4, ch = idx & 15;
        size_t go = base + (size_t)(qt * 64 + row) * HD_ + ch * 8;
        uint32_t so = swz256(row * 256 + ch * 16);
        cp16(sb + AT2_QH + so, g_qhi + go);
        cp16(sb + AT2_QL + so, g_qlo + go);
    }
    // ---- preload K[0], V[0] ----
    #pragma unroll
    for (int t = 0; t < 8; t++) {
        int idx = t * 128 + tid;
        int row = idx >> 4, ch = idx & 15;
        size_t go = base + (size_t)row * HD_ + ch * 8;
        uint32_t so = swz256(row * 256 + ch * 16);
        cp16(sb + AT2_KH + so, g_khi + go);
        cp16(sb + AT2_KL + so, g_klo + go);
        cp16(sb + AT2_VH + so, g_vhi + go);
        cp16(sb + AT2_VL + so, g_vlo + go);
    }
    CP_COMMIT();
    asm volatile("cp.async.wait_group 0;" ::: "memory");
    __syncthreads();

    float acc[16][4];
    #pragma unroll
    for (int t8 = 0; t8 < 16; t8++)
        #pragma unroll
        for (int e = 0; e < 4; e++) acc[t8][e] = 0.f;
    float m_run[2] = {-1e30f, -1e30f};
    float l_run[2] = {0.f, 0.f};

    const int r0 = wq * 16 + (lane >> 2);
    const int nkt = qt + 1;
    const int lrow = lane & 15;
    const int lk = (lane >> 4) * 8;

    for (int kt = 0; kt < nkt; kt++) {
        // ---- QK^T (3-term, term-major) ----
        float sacc[8][4];
        #pragma unroll
        for (int ni = 0; ni < 8; ni++)
            #pragma unroll
            for (int e = 0; e < 4; e++) sacc[ni][e] = 0.f;

        #pragma unroll
        for (int kk = 0; kk < 8; kk++) {
            const int kb = (kk * 16 + lk) * 2;
            uint32_t ah[4], al[4];
            uint32_t qo = swz256((wq * 16 + lrow) * 256 + kb);
            ldsm4(ah, sb + AT2_QH + qo);
            ldsm4(al, sb + AT2_QL + qo);
            uint32_t bh4[4][4], bl4[4][4];
            #pragma unroll
            for (int nj = 0; nj < 4; nj++) {
                uint32_t ko = swz256((nj * 16 + lrow) * 256 + kb);
                ldsm4(bh4[nj], sb + AT2_KH + ko);
                ldsm4(bl4[nj], sb + AT2_KL + ko);
            }
            #pragma unroll
            for (int t = 0; t < 3; t++)
                #pragma unroll
                for (int ni = 0; ni < 8; ni++) {
                    const int nj = ni >> 1, ns = ni & 1;
                    const uint32_t* a = (t == 2) ? al : ah;
                    const uint32_t* b = (t == 1) ? bl4[nj] : bh4[nj];
                    mma16816(sacc[ni], a, b[ns], b[ns+2]);
                }
        }

        // ---- softmax; pack P into bf16 hi/lo A-fragments (registers) ----
        const bool diag = (kt == qt);   // only last tile crosses the causal boundary
        uint32_t phi[8][2], plo[8][2];
        #pragma unroll
        for (int h2 = 0; h2 < 2; h2++) {
            float v[16];
            float mloc = -1e30f;
            if (diag) {
                const int qg = qt * 64 + r0 + h2 * 8;
                #pragma unroll
                for (int ni = 0; ni < 8; ni++)
                    #pragma unroll
                    for (int e = 0; e < 2; e++) {
                        float s = sacc[ni][h2*2 + e] * qscale;
                        int kg = kt * 64 + ni * 8 + (lane & 3) * 2 + e;
                        if (kg > qg) s = -1e30f;
                        v[ni*2 + e] = s;
                        mloc = fmaxf(mloc, s);
                    }
            } else {
                #pragma unroll
                for (int ni = 0; ni < 8; ni++)
                    #pragma unroll
                    for (int e = 0; e < 2; e++) {
                        float s = sacc[ni][h2*2 + e] * qscale;
                        v[ni*2 + e] = s;
                        mloc = fmaxf(mloc, s);
                    }
            }
            mloc = fmaxf(mloc, __shfl_xor_sync(0xffffffffu, mloc, 1));
            mloc = fmaxf(mloc, __shfl_xor_sync(0xffffffffu, mloc, 2));
            float mnew = fmaxf(m_run[h2], mloc);
            float corr = __expf(m_run[h2] - mnew);
            float rsum = 0.f;
            #pragma unroll
            for (int ni = 0; ni < 8; ni++) {
                float p0 = __expf(v[ni*2 + 0] - mnew);
                float p1 = __expf(v[ni*2 + 1] - mnew);
                rsum += p0 + p1;
                __nv_bfloat16 h0 = __float2bfloat16(p0);
                __nv_bfloat16 h1 = __float2bfloat16(p1);
                float l0 = p0 - __bfloat162float(h0);
                float l1 = p1 - __bfloat162float(h1);
                __nv_bfloat162 ph = __halves2bfloat162(h0, h1);
                phi[ni][h2] = *reinterpret_cast<uint32_t*>(&ph);
                plo[ni][h2] = pack_bf16x2(l0, l1);
            }
            rsum += __shfl_xor_sync(0xffffffffu, rsum, 1);
            rsum += __shfl_xor_sync(0xffffffffu, rsum, 2);
            l_run[h2] = l_run[h2] * corr + rsum;
            m_run[h2] = mnew;
            #pragma unroll
            for (int t8 = 0; t8 < 16; t8++) {
                acc[t8][h2*2 + 0] *= corr;
                acc[t8][h2*2 + 1] *= corr;
            }
        }

        // ---- PV (3-term HMMA), two n16-groups interleaved: reuse distance 4 ----
        #pragma unroll
        for (int kk = 0; kk < 4; kk++) {
            uint32_t aH[4] = { phi[2*kk][0], phi[2*kk][1], phi[2*kk+1][0], phi[2*kk+1][1] };
            uint32_t aL[4] = { plo[2*kk][0], plo[2*kk][1], plo[2*kk+1][0], plo[2*kk+1][1] };
            #pragma unroll
            for (int np = 0; np < 4; np++) {
                const int ng0 = 2*np, ng1 = 2*np + 1;
                uint32_t off0 = swz256((kk * 16 + lrow) * 256 + (ng0 * 16 + lk) * 2);
                uint32_t off1 = swz256((kk * 16 + lrow) * 256 + (ng1 * 16 + lk) * 2);
                uint32_t vh0[4], vl0[4], vh1[4], vl1[4];
                ldsm4t(vh0, sb + AT2_VH + off0);
                ldsm4t(vh1, sb + AT2_VH + off1);
                ldsm4t(vl0, sb + AT2_VL + off0);
                ldsm4t(vl1, sb + AT2_VL + off1);
                const int a0 = 2*ng0, b0v = 2*ng0 + 1, a1 = 2*ng1, b1v = 2*ng1 + 1;
                mma16816(acc[a0],  aH, vh0[0], vh0[1]);
                mma16816(acc[b0v], aH, vh0[2], vh0[3]);
                mma16816(acc[a1],  aH, vh1[0], vh1[1]);
                mma16816(acc[b1v], aH, vh1[2], vh1[3]);
                mma16816(acc[a0],  aL, vh0[0], vh0[1]);
                mma16816(acc[b0v], aL, vh0[2], vh0[3]);
                mma16816(acc[a1],  aL, vh1[0], vh1[1]);
                mma16816(acc[b1v], aL, vh1[2], vh1[3]);
                mma16816(acc[a0],  aH, vl0[0], vl0[1]);
                mma16816(acc[b0v], aH, vl0[2], vl0[3]);
                mma16816(acc[a1],  aH, vl1[0], vl1[1]);
                mma16816(acc[b1v], aH, vl1[2], vl1[3]);
            }
        }

        // ---- load next K/V tile (single-buffered; co-resident CTA hides latency) ----
        if (kt + 1 < nkt) {
            __syncthreads();   // all warps done reading K/V
            #pragma unroll
            for (int t = 0; t < 8; t++) {
                int idx = t * 128 + tid;
                int row = idx >> 4, ch = idx & 15;
                size_t go = base + (size_t)((kt + 1) * 64 + row) * HD_ + ch * 8;
                uint32_t so = swz256(row * 256 + ch * 16);
                cp16(sb + AT2_KH + so, g_khi + go);
                cp16(sb + AT2_KL + so, g_klo + go);
                cp16(sb + AT2_VH + so, g_vhi + go);
                cp16(sb + AT2_VL + so, g_vlo + go);
            }
            CP_COMMIT();
            asm volatile("cp.async.wait_group 0;" ::: "memory");
            __syncthreads();
        }
    }

    // ---- finalize: normalize, split hi/lo, store to [b*s, h*HD+d] ----
    const int b = bh >> 4;
    const int h = bh & 15;
    #pragma unroll
    for (int h2 = 0; h2 < 2; h2++) {
        float inv = 1.0f / l_run[h2];
        int sg = qt * 64 + r0 + h2 * 8;
        size_t rowbase = ((size_t)(b * S_ + sg)) * D_ + h * HD_;
        #pragma unroll
        for (int t8 = 0; t8 < 16; t8++) {
            int col = t8 * 8 + (lane & 3) * 2;
            float e = acc[t8][h2*2 + 0] * inv;
            float o = acc[t8][h2*2 + 1] * inv;
            size_t ei = rowbase + col;
            __nv_bfloat16 eh = __float2bfloat16(e);
            __nv_bfloat16 oh = __float2bfloat16(o);
            __nv_bfloat16 el = __float2bfloat16(e - __bfloat162float(eh));
            __nv_bfloat16 ol = __float2bfloat16(o - __bfloat162float(oh));
            ((__nv_bfloat162*)outhi)[ei >> 1] = __halves2bfloat162(eh, oh);
            ((__nv_bfloat162*)outlo)[ei >> 1] = __halves2bfloat162(el, ol);
        }
    }
}

extern "C" void kernel_launch(void* const* d_in, const int* in_sizes, int n_in,
                              void* d_out, int out_size) {
    (void)in_sizes; (void)n_in; (void)out_size;
    const float* x  = (const float*)d_in[0];
    const float* Wq = (const float*)d_in[1];
    const float* Wk = (const float*)d_in[2];
    const float* Wv = (const float*)d_in[3];
    const float* Wo = (const float*)d_in[4];
    float* out = (float*)d_out;

    __nv_bfloat16 *xhi, *xlo, *whi, *wlo, *qhi, *qlo, *khi, *klo, *vhi, *vlo;
    cudaGetSymbolAddress((void**)&xhi, g_xhi);
    cudaGetSymbolAddress((void**)&xlo, g_xlo);
    cudaGetSymbolAddress((void**)&whi, g_whi);
    cudaGetSymbolAddress((void**)&wlo, g_wlo);
    cudaGetSymbolAddress((void**)&qhi, g_qhi);
    cudaGetSymbolAddress((void**)&qlo, g_qlo);
    cudaGetSymbolAddress((void**)&khi, g_khi);
    cudaGetSymbolAddress((void**)&klo, g_klo);
    cudaGetSymbolAddress((void**)&vhi, g_vhi);
    cudaGetSymbolAddress((void**)&vlo, g_vlo);

    const size_t DD = (size_t)D_ * D_;

    cudaFuncSetAttribute(gemm_qkv, cudaFuncAttributeMaxDynamicSharedMemorySize, GT_SMEM);
    cudaFuncSetAttribute(gemm_out, cudaFuncAttributeMaxDynamicSharedMemorySize, GT_SMEM);
    cudaFuncSetAttribute(attn_mma, cudaFuncAttributeMaxDynamicSharedMemorySize, A_SMEM);

    rope_table_kernel<<<(S_*F_ + 255)/256, 256>>>();
    conv_fused<<<dim3(4096, 6), 256>>>(x, Wq, Wk, Wv, Wo, xhi, xlo, whi, wlo);
    gemm_qkv<<<dim3(16, 32, 3), 256, GT_SMEM>>>(xhi, xlo, whi, wlo,
                                                qhi, qlo, khi, klo, vhi, vlo);
    attn_mma<<<dim3(S_/64, B_*H_), 128, A_SMEM>>>(xhi, xlo);
    gemm_out<<<dim3(16, 32), 256, GT_SMEM>>>(xhi, xlo, whi + 3*DD, wlo + 3*DD, out);
}

// round 14
// speedup vs baseline: 3.0237x; 1.0230x over previous
#include <cuda_runtime.h>
#include <cuda_bf16.h>
#include <math.h>
#include <stdint.h>

#define B_  2
#define S_  2048
#define D_  2048
#define H_  16
#define HD_ 128
#define M_  (B_*S_)      // 4096
#define F_  (HD_/2)      // 64

// ---------------- scratch (alloc-free rule: __device__ globals) ----------------
__device__ float g_cos[S_*F_];
__device__ float g_sin[S_*F_];

__device__ __nv_bfloat16 g_qhi[B_*H_*S_*HD_];
__device__ __nv_bfloat16 g_qlo[B_*H_*S_*HD_];
__device__ __nv_bfloat16 g_khi[B_*H_*S_*HD_];
__device__ __nv_bfloat16 g_klo[B_*H_*S_*HD_];
__device__ __nv_bfloat16 g_vhi[B_*H_*S_*HD_];
__device__ __nv_bfloat16 g_vlo[B_*H_*S_*HD_];

__device__ __nv_bfloat16 g_xhi[M_*D_];   // x split; reused as attn-out split
__device__ __nv_bfloat16 g_xlo[M_*D_];
__device__ __nv_bfloat16 g_whi[4*D_*D_];
__device__ __nv_bfloat16 g_wlo[4*D_*D_];

// ---------------- PTX helpers (plain sm_100 target: no tcgen05) ----------------
__device__ __forceinline__ uint32_t smem_u32(const void* p) {
    uint32_t a;
    asm("{ .reg .u64 t; cvta.to.shared.u64 t, %1; cvt.u32.u64 %0, t; }" : "=r"(a) : "l"(p));
    return a;
}
__device__ __forceinline__ void cp16(uint32_t s, const void* g) {
    asm volatile("cp.async.cg.shared.global [%0], [%1], 16;" :: "r"(s), "l"(g));
}
#define CP_COMMIT() asm volatile("cp.async.commit_group;")

__device__ __forceinline__ void ldsm4(uint32_t* r, uint32_t addr) {
    asm volatile("ldmatrix.sync.aligned.m8n8.x4.shared.b16 {%0,%1,%2,%3}, [%4];"
        : "=r"(r[0]), "=r"(r[1]), "=r"(r[2]), "=r"(r[3]) : "r"(addr));
}
__device__ __forceinline__ void ldsm4t(uint32_t* r, uint32_t addr) {
    asm volatile("ldmatrix.sync.aligned.m8n8.x4.trans.shared.b16 {%0,%1,%2,%3}, [%4];"
        : "=r"(r[0]), "=r"(r[1]), "=r"(r[2]), "=r"(r[3]) : "r"(addr));
}
__device__ __forceinline__ void mma16816(float* d, const uint32_t* a, uint32_t b0, uint32_t b1) {
    asm volatile(
        "mma.sync.aligned.m16n8k16.row.col.f32.bf16.bf16.f32 "
        "{%0,%1,%2,%3}, {%4,%5,%6,%7}, {%8,%9}, {%0,%1,%2,%3};"
        : "+f"(d[0]), "+f"(d[1]), "+f"(d[2]), "+f"(d[3])
        : "r"(a[0]), "r"(a[1]), "r"(a[2]), "r"(a[3]), "r"(b0), "r"(b1));
}
__device__ __forceinline__ uint32_t pack_bf16x2(float a, float b) {
    __nv_bfloat162 t = __halves2bfloat162(__float2bfloat16(a), __float2bfloat16(b));
    return *reinterpret_cast<uint32_t*>(&t);
}
// SW64-style bank swizzle for 64B rows; preserves 16B granularity
__device__ __forceinline__ uint32_t swz64(uint32_t x) { return x ^ ((x >> 3) & 0x30); }
// swizzle for 256B rows: row bits [8:10] -> 16B-column bits [4:6]
__device__ __forceinline__ uint32_t swz256(uint32_t x) { return x ^ ((x >> 4) & 0x70); }

// ---------------- RoPE table ----------------
__global__ void rope_table_kernel() {
    int idx = blockIdx.x * blockDim.x + threadIdx.x;
    if (idx >= S_ * F_) return;
    int s = idx >> 6;
    int i = idx & 63;
    double invf = pow(10000.0, -(double)i / 64.0);
    double f = (double)s * invf;
    double sn, cs;
    sincos(f, &sn, &cs);
    g_cos[idx] = (float)cs;
    g_sin[idx] = (float)sn;
}

// ---------------- fused fp32 -> bf16 hi/lo splits: x (2 segs) + 4 weights ----------------
__global__ void conv_fused(const float* __restrict__ x,
                           const float* __restrict__ Wq, const float* __restrict__ Wk,
                           const float* __restrict__ Wv, const float* __restrict__ Wo,
                           __nv_bfloat16* __restrict__ xhi, __nv_bfloat16* __restrict__ xlo,
                           __nv_bfloat16* __restrict__ whi, __nv_bfloat16* __restrict__ wlo)
{
    const int y = blockIdx.y;
    const int i = blockIdx.x * blockDim.x + threadIdx.x;
    const float* in;
    __nv_bfloat16 *hi, *lo;
    size_t off4;
    const size_t SEG = (size_t)D_ * D_ / 4;
    if (y < 2) {
        in = x + (size_t)y * SEG * 4;
        hi = xhi; lo = xlo;
        off4 = (size_t)y * SEG + i;
    } else {
        const float* ws[4] = {Wq, Wk, Wv, Wo};
        in = ws[y - 2];
        hi = whi; lo = wlo;
        off4 = (size_t)(y - 2) * SEG + i;
    }
    float4 v = ((const float4*)in)[i];
    float xs[4] = {v.x, v.y, v.z, v.w};
    __nv_bfloat16 h[4], l[4];
    #pragma unroll
    for (int j = 0; j < 4; j++) {
        h[j] = __float2bfloat16(xs[j]);
        l[j] = __float2bfloat16(xs[j] - __bfloat162float(h[j]));
    }
    __nv_bfloat162* hp = (__nv_bfloat162*)hi;
    __nv_bfloat162* lp = (__nv_bfloat162*)lo;
    hp[2*off4]   = __halves2bfloat162(h[0], h[1]);
    hp[2*off4+1] = __halves2bfloat162(h[2], h[3]);
    lp[2*off4]   = __halves2bfloat162(l[0], l[1]);
    lp[2*off4+1] = __halves2bfloat162(l[2], l[3]);
}

// ---------------- mma.sync bf16 GEMM machinery ----------------
// CTA 128x128, 4 warps (2x2), warp tile 64x64: A/B smem reads only 2x amplified.
// 64B rows + XOR swizzle, 3-stage cp.async pipeline (wait_group 1), 2 CTAs/SM.
#define KC 32
#define TILE_B (128*64)              // 8192
#define STAGE_B (4*TILE_B)           // 32768
#define GT_SMEM (3*STAGE_B)          // 98304

struct GemmCore {
    uint32_t sb;
    int tid, lane, wid, wm, wn, m0, n0;
    const __nv_bfloat16 *Ahi, *Alo, *Bhi, *Blo;

    __device__ __forceinline__ void init(uint32_t sb_, int bx, int by) {
        sb = sb_;
        tid = threadIdx.x;
        lane = tid & 31;
        wid = tid >> 5;              // 0..3
        wm = (wid >> 1) * 64;
        wn = (wid & 1) * 64;
        m0 = by * 128;
        n0 = bx * 128;
    }

    __device__ __forceinline__ void load_stage(int stg, int k0) {
        if (k0 < 2048) {
            uint32_t base = sb + stg * STAGE_B;
            #pragma unroll
            for (int t = 0; t < 4; t++) {
                int idx = t * 128 + tid;
                int row = idx >> 2, seg = idx & 3;
                uint32_t so = swz64(row * 64 + seg * 16);
                size_t goA = (size_t)(m0 + row) * D_ + k0 + seg * 8;
                size_t goB = (size_t)(n0 + row) * D_ + k0 + seg * 8;
                cp16(base + 0*TILE_B + so, Ahi + goA);
                cp16(base + 1*TILE_B + so, Alo + goA);
                cp16(base + 2*TILE_B + so, Bhi + goB);
                cp16(base + 3*TILE_B + so, Blo + goB);
            }
        }
        CP_COMMIT();   // empty commit past the tail keeps group counting uniform
    }

    // acc[mi][ni][e]: mi 0..3 (m16 rows), ni 0..7 (n8 cols)
    __device__ __forceinline__ void run(float acc[4][8][4]) {
        #pragma unroll
        for (int mi = 0; mi < 4; mi++)
            #pragma unroll
            for (int ni = 0; ni < 8; ni++)
                #pragma unroll
                for (int e = 0; e < 4; e++) acc[mi][ni][e] = 0.f;

        load_stage(0, 0);
        load_stage(1, KC);
        const int NCH = 2048 / KC;
        const int lrow = lane & 15;
        const int lk   = (lane >> 4) * 8;

        int stg = 0;
        for (int c = 0; c < NCH; c++) {
            asm volatile("cp.async.wait_group 1;" ::: "memory");
            __syncthreads();
            int nst = stg + 2; if (nst >= 3) nst -= 3;
            load_stage(nst, (c + 2) * KC);

            const uint32_t st = sb + stg * STAGE_B;
            const uint32_t aAh = st, aAl = st + TILE_B, aBh = st + 2*TILE_B, aBl = st + 3*TILE_B;

            #pragma unroll
            for (int kk = 0; kk < 2; kk++) {
                const int kb = (kk * 16 + lk) * 2;
                uint32_t ah[4][4], al[4][4];
                #pragma unroll
                for (int mi = 0; mi < 4; mi++) {
                    uint32_t off = swz64((wm + mi*16 + lrow) * 64 + kb);
                    ldsm4(ah[mi], aAh + off);
                    ldsm4(al[mi], aAl + off);
                }
                uint32_t bh[4][4], bl[4][4];
                #pragma unroll
                for (int nj = 0; nj < 4; nj++) {
                    uint32_t off = swz64((wn + nj*16 + lrow) * 64 + kb);
                    ldsm4(bh[nj], aBh + off);
                    ldsm4(bl[nj], aBl + off);
                }
                // term-major: 32 independent accumulators between reuse
                #pragma unroll
                for (int t = 0; t < 3; t++)
                    #pragma unroll
                    for (int mi = 0; mi < 4; mi++)
                        #pragma unroll
                        for (int ni = 0; ni < 8; ni++) {
                            const int nj = ni >> 1, ns = ni & 1;
                            const uint32_t* a = (t == 2) ? al[mi] : ah[mi];
                            const uint32_t* b = (t == 1) ? bl[nj] : bh[nj];
                            mma16816(acc[mi][ni], a, b[ns], b[ns+2]);
                        }
            }
            if (++stg >= 3) stg = 0;
        }
    }
};

// ---- fused QKV projection: grid (16, 32, 3); z = 0:Q(RoPE) 1:K(RoPE) 2:V ----
__global__ __launch_bounds__(128, 2) void gemm_qkv(
    const __nv_bfloat16* __restrict__ xhi, const __nv_bfloat16* __restrict__ xlo,
    const __nv_bfloat16* __restrict__ whi, const __nv_bfloat16* __restrict__ wlo,
    __nv_bfloat16* __restrict__ qhi, __nv_bfloat16* __restrict__ qlo,
    __nv_bfloat16* __restrict__ khi, __nv_bfloat16* __restrict__ klo,
    __nv_bfloat16* __restrict__ vhi, __nv_bfloat16* __restrict__ vlo)
{
    extern __shared__ char smc[];
    const int z = blockIdx.z;
    const size_t DD = (size_t)D_ * D_;

    GemmCore gc;
    gc.init(smem_u32(smc), blockIdx.x, blockIdx.y);
    gc.Ahi = xhi; gc.Alo = xlo;
    gc.Bhi = whi + z * DD; gc.Blo = wlo + z * DD;

    float acc[4][8][4];
    gc.run(acc);

    __nv_bfloat16* outhi = (z == 0) ? qhi : (z == 1) ? khi : vhi;
    __nv_bfloat16* outlo = (z == 0) ? qlo : (z == 1) ? klo : vlo;
    const bool rope = (z < 2);

    const int rr = gc.lane >> 2;
    const int cp = (gc.lane & 3) * 2;
    #pragma unroll
    for (int mi = 0; mi < 4; mi++) {
        #pragma unroll
        for (int half = 0; half < 2; half++) {
            int m = gc.m0 + gc.wm + mi*16 + rr + half*8;
            int s = m & (S_ - 1);
            #pragma unroll
            for (int ni = 0; ni < 8; ni++) {
                float e = acc[mi][ni][half*2 + 0];
                float o = acc[mi][ni][half*2 + 1];
                int n = gc.n0 + gc.wn + ni*8 + cp;
                if (rope) {
                    int pair = (n & (HD_ - 1)) >> 1;
                    float cc = g_cos[s * F_ + pair], ss = g_sin[s * F_ + pair];
                    float xe = e, xo = o;
                    e = xe * cc - xo * ss;
                    o = xo * cc + xe * ss;
                }
                int br = m >> 11, h = n >> 7, hd = n & (HD_ - 1);
                size_t ei = (((size_t)(br * H_ + h)) * S_ + s) * HD_ + hd;
                __nv_bfloat16 eh = __float2bfloat16(e);
                __nv_bfloat16 oh = __float2bfloat16(o);
                __nv_bfloat16 el = __float2bfloat16(e - __bfloat162float(eh));
                __nv_bfloat16 ol = __float2bfloat16(o - __bfloat162float(oh));
                ((__nv_bfloat162*)outhi)[ei >> 1] = __halves2bfloat162(eh, oh);
                ((__nv_bfloat162*)outlo)[ei >> 1] = __halves2bfloat162(el, ol);
            }
        }
    }
}

// ---- output projection: fp32 row-major [M, 2048] ----
__global__ __launch_bounds__(128, 2) void gemm_out(
    const __nv_bfloat16* __restrict__ Ahi, const __nv_bfloat16* __restrict__ Alo,
    const __nv_bfloat16* __restrict__ Bhi, const __nv_bfloat16* __restrict__ Blo,
    float* __restrict__ outp)
{
    extern __shared__ char smc[];
    GemmCore gc;
    gc.init(smem_u32(smc), blockIdx.x, blockIdx.y);
    gc.Ahi = Ahi; gc.Alo = Alo; gc.Bhi = Bhi; gc.Blo = Blo;

    float acc[4][8][4];
    gc.run(acc);

    const int rr = gc.lane >> 2;
    const int cp = (gc.lane & 3) * 2;
    #pragma unroll
    for (int mi = 0; mi < 4; mi++)
        #pragma unroll
        for (int half = 0; half < 2; half++) {
            int m = gc.m0 + gc.wm + mi*16 + rr + half*8;
            #pragma unroll
            for (int ni = 0; ni < 8; ni++) {
                int n = gc.n0 + gc.wn + ni*8 + cp;
                *(float2*)(outp + (size_t)m * D_ + n) =
                    make_float2(acc[mi][ni][half*2 + 0], acc[mi][ni][half*2 + 1]);
            }
        }
}

// ---------------- flash attention v2: 64-q-row CTAs, 128 threads, 2 CTAs/SM ----------------
// smem 96 KB: 256B rows + swz256 (bank-clean ldsm, 16B cp.async).
// Only the kt==qt tile needs causal masking.
#define AT2_QH 0         // Q hi: 64 x 256B
#define AT2_QL 16384     // Q lo
#define AT2_KH 32768     // K hi: 64 x 256B
#define AT2_KL 49152     // K lo
#define AT2_VH 65536     // V hi
#define AT2_VL 81920     // V lo
#define A_SMEM 98304

__global__ __launch_bounds__(128, 2) void attn_mma(
    __nv_bfloat16* __restrict__ outhi, __nv_bfloat16* __restrict__ outlo)
{
    extern __shared__ char smc[];
    const uint32_t sb = smem_u32(smc);

    const int tid = threadIdx.x;
    const int lane = tid & 31;
    const int wq = tid >> 5;                                // 0..3
    const int qt = (int)gridDim.x - 1 - (int)blockIdx.x;    // heavy CTAs first
    const int bh = blockIdx.y;
    const size_t base = (size_t)bh * S_ * HD_;
    const float qscale = 0.08838834764831845f;  // 1/sqrt(128)

    // ---- preload Q ----
    #pragma unroll
    for (int t = 0; t < 8; t++) {
        int idx = t * 128 + tid;
        int row = idx >> 4, ch = idx & 15;
        size_t go = base + (size_t)(qt * 64 + row) * HD_ + ch * 8;
        uint32_t so = swz256(row * 256 + ch * 16);
        cp16(sb + AT2_QH + so, g_qhi + go);
        cp16(sb + AT2_QL + so, g_qlo + go);
    }
    // ---- preload K[0], V[0] ----
    #pragma unroll
    for (int t = 0; t < 8; t++) {
        int idx = t * 128 + tid;
        int row = idx >> 4, ch = idx & 15;
        size_t go = base + (size_t)row * HD_ + ch * 8;
        uint32_t so = swz256(row * 256 + ch * 16);
        cp16(sb + AT2_KH + so, g_khi + go);
        cp16(sb + AT2_KL + so, g_klo + go);
        cp16(sb + AT2_VH + so, g_vhi + go);
        cp16(sb + AT2_VL + so, g_vlo + go);
    }
    CP_COMMIT();
    asm volatile("cp.async.wait_group 0;" ::: "memory");
    __syncthreads();

    float acc[16][4];
    #pragma unroll
    for (int t8 = 0; t8 < 16; t8++)
        #pragma unroll
        for (int e = 0; e < 4; e++) acc[t8][e] = 0.f;
    float m_run[2] = {-1e30f, -1e30f};
    float l_run[2] = {0.f, 0.f};

    const int r0 = wq * 16 + (lane >> 2);
    const int nkt = qt + 1;
    const int lrow = lane & 15;
    const int lk = (lane >> 4) * 8;

    for (int kt = 0; kt < nkt; kt++) {
        // ---- QK^T (3-term, term-major) ----
        float sacc[8][4];
        #pragma unroll
        for (int ni = 0; ni < 8; ni++)
            #pragma unroll
            for (int e = 0; e < 4; e++) sacc[ni][e] = 0.f;

        #pragma unroll
        for (int kk = 0; kk < 8; kk++) {
            const int kb = (kk * 16 + lk) * 2;
            uint32_t ah[4], al[4];
            uint32_t qo = swz256((wq * 16 + lrow) * 256 + kb);
            ldsm4(ah, sb + AT2_QH + qo);
            ldsm4(al, sb + AT2_QL + qo);
            uint32_t bh4[4][4], bl4[4][4];
            #pragma unroll
            for (int nj = 0; nj < 4; nj++) {
                uint32_t ko = swz256((nj * 16 + lrow) * 256 + kb);
                ldsm4(bh4[nj], sb + AT2_KH + ko);
                ldsm4(bl4[nj], sb + AT2_KL + ko);
            }
            #pragma unroll
            for (int t = 0; t < 3; t++)
                #pragma unroll
                for (int ni = 0; ni < 8; ni++) {
                    const int nj = ni >> 1, ns = ni & 1;
                    const uint32_t* a = (t == 2) ? al : ah;
                    const uint32_t* b = (t == 1) ? bl4[nj] : bh4[nj];
                    mma16816(sacc[ni], a, b[ns], b[ns+2]);
                }
        }

        // ---- softmax; pack P into bf16 hi/lo A-fragments (registers) ----
        const bool diag = (kt == qt);   // only last tile crosses the causal boundary
        uint32_t phi[8][2], plo[8][2];
        #pragma unroll
        for (int h2 = 0; h2 < 2; h2++) {
            float v[16];
            float mloc = -1e30f;
            if (diag) {
                const int qg = qt * 64 + r0 + h2 * 8;
                #pragma unroll
                for (int ni = 0; ni < 8; ni++)
                    #pragma unroll
                    for (int e = 0; e < 2; e++) {
                        float s = sacc[ni][h2*2 + e] * qscale;
                        int kg = kt * 64 + ni * 8 + (lane & 3) * 2 + e;
                        if (kg > qg) s = -1e30f;
                        v[ni*2 + e] = s;
                        mloc = fmaxf(mloc, s);
                    }
            } else {
                #pragma unroll
                for (int ni = 0; ni < 8; ni++)
                    #pragma unroll
                    for (int e = 0; e < 2; e++) {
                        float s = sacc[ni][h2*2 + e] * qscale;
                        v[ni*2 + e] = s;
                        mloc = fmaxf(mloc, s);
                    }
            }
            mloc = fmaxf(mloc, __shfl_xor_sync(0xffffffffu, mloc, 1));
            mloc = fmaxf(mloc, __shfl_xor_sync(0xffffffffu, mloc, 2));
            float mnew = fmaxf(m_run[h2], mloc);
            float corr = __expf(m_run[h2] - mnew);
            float rsum = 0.f;
            #pragma unroll
            for (int ni = 0; ni < 8; ni++) {
                float p0 = __expf(v[ni*2 + 0] - mnew);
                float p1 = __expf(v[ni*2 + 1] - mnew);
                rsum += p0 + p1;
                __nv_bfloat16 h0 = __float2bfloat16(p0);
                __nv_bfloat16 h1 = __float2bfloat16(p1);
                float l0 = p0 - __bfloat162float(h0);
                float l1 = p1 - __bfloat162float(h1);
                __nv_bfloat162 ph = __halves2bfloat162(h0, h1);
                phi[ni][h2] = *reinterpret_cast<uint32_t*>(&ph);
                plo[ni][h2] = pack_bf16x2(l0, l1);
            }
            rsum += __shfl_xor_sync(0xffffffffu, rsum, 1);
            rsum += __shfl_xor_sync(0xffffffffu, rsum, 2);
            l_run[h2] = l_run[h2] * corr + rsum;
            m_run[h2] = mnew;
            #pragma unroll
            for (int t8 = 0; t8 < 16; t8++) {
                acc[t8][h2*2 + 0] *= corr;
                acc[t8][h2*2 + 1] *= corr;
            }
        }

        // ---- PV (3-term HMMA), two n16-groups interleaved: reuse distance 4 ----
        #pragma unroll
        for (int kk = 0; kk < 4; kk++) {
            uint32_t aH[4] = { phi[2*kk][0], phi[2*kk][1], phi[2*kk+1][0], phi[2*kk+1][1] };
            uint32_t aL[4] = { plo[2*kk][0], plo[2*kk][1], plo[2*kk+1][0], plo[2*kk+1][1] };
            #pragma unroll
            for (int np = 0; np < 4; np++) {
                const int ng0 = 2*np, ng1 = 2*np + 1;
                uint32_t off0 = swz256((kk * 16 + lrow) * 256 + (ng0 * 16 + lk) * 2);
                uint32_t off1 = swz256((kk * 16 + lrow) * 256 + (ng1 * 16 + lk) * 2);
                uint32_t vh0[4], vl0[4], vh1[4], vl1[4];
                ldsm4t(vh0, sb + AT2_VH + off0);
                ldsm4t(vh1, sb + AT2_VH + off1);
                ldsm4t(vl0, sb + AT2_VL + off0);
                ldsm4t(vl1, sb + AT2_VL + off1);
                const int a0 = 2*ng0, b0v = 2*ng0 + 1, a1 = 2*ng1, b1v = 2*ng1 + 1;
                mma16816(acc[a0],  aH, vh0[0], vh0[1]);
                mma16816(acc[b0v], aH, vh0[2], vh0[3]);
                mma16816(acc[a1],  aH, vh1[0], vh1[1]);
                mma16816(acc[b1v], aH, vh1[2], vh1[3]);
                mma16816(acc[a0],  aL, vh0[0], vh0[1]);
                mma16816(acc[b0v], aL, vh0[2], vh0[3]);
                mma16816(acc[a1],  aL, vh1[0], vh1[1]);
                mma16816(acc[b1v], aL, vh1[2], vh1[3]);
                mma16816(acc[a0],  aH, vl0[0], vl0[1]);
                mma16816(acc[b0v], aH, vl0[2], vl0[3]);
                mma16816(acc[a1],  aH, vl1[0], vl1[1]);
                mma16816(acc[b1v], aH, vl1[2], vl1[3]);
            }
        }

        // ---- load next K/V tile (single-buffered; co-resident CTA hides latency) ----
        if (kt + 1 < nkt) {
            __syncthreads();   // all warps done reading K/V
            #pragma unroll
            for (int t = 0; t < 8; t++) {
                int idx = t * 128 + tid;
                int row = idx >> 4, ch = idx & 15;
                size_t go = base + (size_t)((kt + 1) * 64 + row) * HD_ + ch * 8;
                uint32_t so = swz256(row * 256 + ch * 16);
                cp16(sb + AT2_KH + so, g_khi + go);
                cp16(sb + AT2_KL + so, g_klo + go);
                cp16(sb + AT2_VH + so, g_vhi + go);
                cp16(sb + AT2_VL + so, g_vlo + go);
            }
            CP_COMMIT();
            asm volatile("cp.async.wait_group 0;" ::: "memory");
            __syncthreads();
        }
    }

    // ---- finalize: normalize, split hi/lo, store to [b*s, h*HD+d] ----
    const int b = bh >> 4;
    const int h = bh & 15;
    #pragma unroll
    for (int h2 = 0; h2 < 2; h2++) {
        float inv = 1.0f / l_run[h2];
        int sg = qt * 64 + r0 + h2 * 8;
        size_t rowbase = ((size_t)(b * S_ + sg)) * D_ + h * HD_;
        #pragma unroll
        for (int t8 = 0; t8 < 16; t8++) {
            int col = t8 * 8 + (lane & 3) * 2;
            float e = acc[t8][h2*2 + 0] * inv;
            float o = acc[t8][h2*2 + 1] * inv;
            size_t ei = rowbase + col;
            __nv_bfloat16 eh = __float2bfloat16(e);
            __nv_bfloat16 oh = __float2bfloat16(o);
            __nv_bfloat16 el = __float2bfloat16(e - __bfloat162float(eh));
            __nv_bfloat16 ol = __float2bfloat16(o - __bfloat162float(oh));
            ((__nv_bfloat162*)outhi)[ei >> 1] = __halves2bfloat162(eh, oh);
            ((__nv_bfloat162*)outlo)[ei >> 1] = __halves2bfloat162(el, ol);
        }
    }
}

extern "C" void kernel_launch(void* const* d_in, const int* in_sizes, int n_in,
                              void* d_out, int out_size) {
    (void)in_sizes; (void)n_in; (void)out_size;
    const float* x  = (const float*)d_in[0];
    const float* Wq = (const float*)d_in[1];
    const float* Wk = (const float*)d_in[2];
    const float* Wv = (const float*)d_in[3];
    const float* Wo = (const float*)d_in[4];
    float* out = (float*)d_out;

    __nv_bfloat16 *xhi, *xlo, *whi, *wlo, *qhi, *qlo, *khi, *klo, *vhi, *vlo;
    cudaGetSymbolAddress((void**)&xhi, g_xhi);
    cudaGetSymbolAddress((void**)&xlo, g_xlo);
    cudaGetSymbolAddress((void**)&whi, g_whi);
    cudaGetSymbolAddress((void**)&wlo, g_wlo);
    cudaGetSymbolAddress((void**)&qhi, g_qhi);
    cudaGetSymbolAddress((void**)&qlo, g_qlo);
    cudaGetSymbolAddress((void**)&khi, g_khi);
    cudaGetSymbolAddress((void**)&klo, g_klo);
    cudaGetSymbolAddress((void**)&vhi, g_vhi);
    cudaGetSymbolAddress((void**)&vlo, g_vlo);

    const size_t DD = (size_t)D_ * D_;

    cudaFuncSetAttribute(gemm_qkv, cudaFuncAttributeMaxDynamicSharedMemorySize, GT_SMEM);
    cudaFuncSetAttribute(gemm_out, cudaFuncAttributeMaxDynamicSharedMemorySize, GT_SMEM);
    cudaFuncSetAttribute(attn_mma, cudaFuncAttributeMaxDynamicSharedMemorySize, A_SMEM);

    rope_table_kernel<<<(S_*F_ + 255)/256, 256>>>();
    conv_fused<<<dim3(4096, 6), 256>>>(x, Wq, Wk, Wv, Wo, xhi, xlo, whi, wlo);
    gemm_qkv<<<dim3(16, 32, 3), 128, GT_SMEM>>>(xhi, xlo, whi, wlo,
                                                qhi, qlo, khi, klo, vhi, vlo);
    attn_mma<<<dim3(S_/64, B_*H_), 128, A_SMEM>>>(xhi, xlo);
    gemm_out<<<dim3(16, 32), 128, GT_SMEM>>>(xhi, xlo, whi + 3*DD, wlo + 3*DD, out);
}